// round 1
// baseline (speedup 1.0000x reference)
#include <cuda_runtime.h>
#include <cstdint>
#include <cstddef>

// ---------------- problem constants ----------------
#define BATCH 8
#define HDIM  128
#define WDIM  128
#define HW    16384            // 128*128
#define PTOT  131072           // 8*128*128
#define CDIM  96

// ---------------- scratch (device globals; no allocation) ----------------
__device__ float g_y   [(size_t)PTOT * 96];    // LN output (row-major P x 96)
__device__ float g_qkv [(size_t)PTOT * 288];   // qkv row-major P x 288
__device__ float g_attn[(size_t)PTOT * 96];    // attention output P x 96
__device__ float g_x1  [(size_t)PTOT * 96];    // x + attn branch, P x 96
__device__ float g_h1  [(size_t)PTOT * 384];   // MLP hidden, P x 384

// ---------------- f32x2 packed helpers ----------------
__device__ __forceinline__ unsigned long long ffma2(unsigned long long a,
                                                    unsigned long long b,
                                                    unsigned long long c) {
    unsigned long long d;
    asm("fma.rn.f32x2 %0, %1, %2, %3;" : "=l"(d) : "l"(a), "l"(b), "l"(c));
    return d;
}
__device__ __forceinline__ unsigned long long dup2(float x) {
    unsigned long long r;
    asm("mov.b64 %0, {%1, %1};" : "=l"(r) : "f"(x));
    return r;
}
__device__ __forceinline__ float2 unpk(unsigned long long v) {
    float2 f;
    asm("mov.b64 {%0, %1}, %2;" : "=f"(f.x), "=f"(f.y) : "l"(v));
    return f;
}

// ---------------- LayerNorm 1: planar input -> row-major g_y ----------------
__global__ __launch_bounds__(256)
void ln1_kernel(const float* __restrict__ x, const float* __restrict__ w,
                const float* __restrict__ b) {
    int p = blockIdx.x * 256 + threadIdx.x;      // < PTOT
    int bb = p >> 14;
    int ss = p & 16383;
    const float* xp = x + (size_t)bb * 96 * HW + ss;

    float sum = 0.f, sq = 0.f;
#pragma unroll 16
    for (int c = 0; c < 96; c++) {
        float v = __ldg(xp + (size_t)c * HW);
        sum += v;
        sq = fmaf(v, v, sq);
    }
    float mu = sum * (1.f / 96.f);
    float var = sq * (1.f / 96.f) - mu * mu;
    float rs = rsqrtf(var + 1e-5f);

    float* yp = g_y + (size_t)p * 96;
#pragma unroll
    for (int c0 = 0; c0 < 96; c0 += 4) {
        float4 ww = *(const float4*)(w + c0);
        float4 bb4 = *(const float4*)(b + c0);
        float4 o;
        o.x = (__ldg(xp + (size_t)(c0 + 0) * HW) - mu) * rs * ww.x + bb4.x;
        o.y = (__ldg(xp + (size_t)(c0 + 1) * HW) - mu) * rs * ww.y + bb4.y;
        o.z = (__ldg(xp + (size_t)(c0 + 2) * HW) - mu) * rs * ww.z + bb4.z;
        o.w = (__ldg(xp + (size_t)(c0 + 3) * HW) - mu) * rs * ww.w + bb4.w;
        *(float4*)(yp + c0) = o;
    }
}

// ---------------- LayerNorm 2: g_x1 row-major -> g_y ----------------
__global__ __launch_bounds__(256)
void ln2_kernel(const float* __restrict__ w, const float* __restrict__ b) {
    int p = blockIdx.x * 256 + threadIdx.x;
    const float* xp = g_x1 + (size_t)p * 96;

    float sum = 0.f, sq = 0.f;
#pragma unroll
    for (int c0 = 0; c0 < 96; c0 += 4) {
        float4 t = *(const float4*)(xp + c0);
        sum += t.x + t.y + t.z + t.w;
        sq = fmaf(t.x, t.x, sq); sq = fmaf(t.y, t.y, sq);
        sq = fmaf(t.z, t.z, sq); sq = fmaf(t.w, t.w, sq);
    }
    float mu = sum * (1.f / 96.f);
    float var = sq * (1.f / 96.f) - mu * mu;
    float rs = rsqrtf(var + 1e-5f);

    float* yp = g_y + (size_t)p * 96;
#pragma unroll
    for (int c0 = 0; c0 < 96; c0 += 4) {
        float4 t = *(const float4*)(xp + c0);
        float4 ww = *(const float4*)(w + c0);
        float4 bb4 = *(const float4*)(b + c0);
        float4 o;
        o.x = (t.x - mu) * rs * ww.x + bb4.x;
        o.y = (t.y - mu) * rs * ww.y + bb4.y;
        o.z = (t.z - mu) * rs * ww.z + bb4.z;
        o.w = (t.w - mu) * rs * ww.w + bb4.w;
        *(float4*)(yp + c0) = o;
    }
}

// ---------------- dilated neighborhood attention ----------------
// one thread = (pixel, head). 6 heads: grp = head>>1 (dilation grp+1), sub = head&1.
// qkv row-major (p, 288): q at grp*32+sub*16, k at 96+..., v at 192+...
// zero padding => OOB neighbor: score 0 (still in softmax), v contribution 0.
__global__ __launch_bounds__(256)
void attn_kernel() {
    int idx = blockIdx.x * 256 + threadIdx.x;    // < PTOT*6
    int p = idx / 6;
    int hd = idx - p * 6;
    int bb = p >> 14;
    int ss = p & 16383;
    int h = ss >> 7;
    int w = ss & 127;
    int grp = hd >> 1;
    int dil = grp + 1;
    int cb = grp * 32 + (hd & 1) * 16;

    const float* qp = g_qkv + (size_t)p * 288 + cb;
    float4 q0 = *(const float4*)(qp + 0);
    float4 q1 = *(const float4*)(qp + 4);
    float4 q2 = *(const float4*)(qp + 8);
    float4 q3 = *(const float4*)(qp + 12);

    float sc[9];
#pragma unroll
    for (int i = 0; i < 3; i++) {
#pragma unroll
        for (int j = 0; j < 3; j++) {
            int hh = h + (i - 1) * dil;
            int ww = w + (j - 1) * dil;
            float d = 0.f;
            if ((unsigned)hh < 128u && (unsigned)ww < 128u) {
                int pn = (bb << 14) + (hh << 7) + ww;
                const float* kp = g_qkv + (size_t)pn * 288 + 96 + cb;
                float4 k0 = *(const float4*)(kp + 0);
                float4 k1 = *(const float4*)(kp + 4);
                float4 k2 = *(const float4*)(kp + 8);
                float4 k3 = *(const float4*)(kp + 12);
                d = fmaf(q0.x, k0.x, d); d = fmaf(q0.y, k0.y, d);
                d = fmaf(q0.z, k0.z, d); d = fmaf(q0.w, k0.w, d);
                d = fmaf(q1.x, k1.x, d); d = fmaf(q1.y, k1.y, d);
                d = fmaf(q1.z, k1.z, d); d = fmaf(q1.w, k1.w, d);
                d = fmaf(q2.x, k2.x, d); d = fmaf(q2.y, k2.y, d);
                d = fmaf(q2.z, k2.z, d); d = fmaf(q2.w, k2.w, d);
                d = fmaf(q3.x, k3.x, d); d = fmaf(q3.y, k3.y, d);
                d = fmaf(q3.z, k3.z, d); d = fmaf(q3.w, k3.w, d);
            }
            sc[i * 3 + j] = d * 0.25f;   // SCALE = 16^-0.5
        }
    }

    float mx = sc[0];
#pragma unroll
    for (int k = 1; k < 9; k++) mx = fmaxf(mx, sc[k]);
    float ssum = 0.f;
#pragma unroll
    for (int k = 0; k < 9; k++) { sc[k] = __expf(sc[k] - mx); ssum += sc[k]; }
    float inv = 1.f / ssum;

    float o[16];
#pragma unroll
    for (int d = 0; d < 16; d++) o[d] = 0.f;

#pragma unroll
    for (int i = 0; i < 3; i++) {
#pragma unroll
        for (int j = 0; j < 3; j++) {
            int hh = h + (i - 1) * dil;
            int ww = w + (j - 1) * dil;
            if ((unsigned)hh < 128u && (unsigned)ww < 128u) {
                int pn = (bb << 14) + (hh << 7) + ww;
                const float* vp = g_qkv + (size_t)pn * 288 + 192 + cb;
                float wgt = sc[i * 3 + j] * inv;
                float4 v0 = *(const float4*)(vp + 0);
                float4 v1 = *(const float4*)(vp + 4);
                float4 v2 = *(const float4*)(vp + 8);
                float4 v3 = *(const float4*)(vp + 12);
                o[0]  = fmaf(wgt, v0.x, o[0]);  o[1]  = fmaf(wgt, v0.y, o[1]);
                o[2]  = fmaf(wgt, v0.z, o[2]);  o[3]  = fmaf(wgt, v0.w, o[3]);
                o[4]  = fmaf(wgt, v1.x, o[4]);  o[5]  = fmaf(wgt, v1.y, o[5]);
                o[6]  = fmaf(wgt, v1.z, o[6]);  o[7]  = fmaf(wgt, v1.w, o[7]);
                o[8]  = fmaf(wgt, v2.x, o[8]);  o[9]  = fmaf(wgt, v2.y, o[9]);
                o[10] = fmaf(wgt, v2.z, o[10]); o[11] = fmaf(wgt, v2.w, o[11]);
                o[12] = fmaf(wgt, v3.x, o[12]); o[13] = fmaf(wgt, v3.y, o[13]);
                o[14] = fmaf(wgt, v3.z, o[14]); o[15] = fmaf(wgt, v3.w, o[15]);
            }
        }
    }

    float* op = g_attn + (size_t)p * 96 + cb;
    *(float4*)(op + 0)  = make_float4(o[0], o[1], o[2], o[3]);
    *(float4*)(op + 4)  = make_float4(o[4], o[5], o[6], o[7]);
    *(float4*)(op + 8)  = make_float4(o[8], o[9], o[10], o[11]);
    *(float4*)(op + 12) = make_float4(o[12], o[13], o[14], o[15]);
}

// ---------------- GEMM core: out(P,N) = A(P,K) @ W(N,K)^T + epilogue ----------------
// BM=128, BN=96, BK=32, 256 threads, thread tile 8(M as 4 f32x2 pairs) x 6(N).
// EPI: 0 = plain rowmajor store, 1 = +bias +x(planar residual) store rowmajor,
//      2 = +bias, GELU(exact), store rowmajor, 3 = +bias +res(rowmajor), store planar.
#define GBM 128
#define GBN 96
#define GBK 32

template <int K, int N, int EPI>
__device__ __forceinline__
void gemm_core(const float* __restrict__ A, const float* __restrict__ W,
               const float* __restrict__ bias, const float* __restrict__ res,
               float* __restrict__ out) {
    __shared__ float sA[GBK][GBM + 4];                  // [k][m], padded
    __shared__ unsigned long long sW[GBK][GBN + 4];     // [k][n], weight duplicated

    const int tid = threadIdx.x;
    const int tr = tid >> 4;          // 0..15 -> 8 rows each
    const int tc = tid & 15;          // 0..15 -> 6 cols each
    const int m0 = blockIdx.x * GBM;
    const int n0 = blockIdx.y * GBN;

    unsigned long long acc[4][6];
#pragma unroll
    for (int i = 0; i < 4; i++)
#pragma unroll
        for (int j = 0; j < 6; j++) acc[i][j] = 0ull;

#pragma unroll 1
    for (int kc = 0; kc < K; kc += GBK) {
        // stage A tile: 128x32 = 1024 float4, 4 per thread
#pragma unroll
        for (int ps = 0; ps < 4; ps++) {
            int f = ps * 256 + tid;
            int r = f >> 3;
            int c4 = (f & 7) * 4;
            float4 v = *(const float4*)(A + (size_t)(m0 + r) * K + kc + c4);
            sA[c4 + 0][r] = v.x; sA[c4 + 1][r] = v.y;
            sA[c4 + 2][r] = v.z; sA[c4 + 3][r] = v.w;
        }
        // stage W tile: 96x32 = 768 float4, 3 per thread (duplicate into u64)
#pragma unroll
        for (int ps = 0; ps < 3; ps++) {
            int f = ps * 256 + tid;
            int r = f >> 3;
            int c4 = (f & 7) * 4;
            float4 v = *(const float4*)(W + (size_t)(n0 + r) * K + kc + c4);
            sW[c4 + 0][r] = dup2(v.x); sW[c4 + 1][r] = dup2(v.y);
            sW[c4 + 2][r] = dup2(v.z); sW[c4 + 3][r] = dup2(v.w);
        }
        __syncthreads();

#pragma unroll
        for (int k = 0; k < GBK; k++) {
            const float* ap = &sA[k][tr * 8];
            ulonglong2 a0 = *(const ulonglong2*)(ap);
            ulonglong2 a1 = *(const ulonglong2*)(ap + 4);
            unsigned long long pa[4] = {a0.x, a0.y, a1.x, a1.y};
            unsigned long long wv[6];
#pragma unroll
            for (int n = 0; n < 6; n++) wv[n] = sW[k][tc * 6 + n];
#pragma unroll
            for (int mp = 0; mp < 4; mp++)
#pragma unroll
                for (int n = 0; n < 6; n++)
                    acc[mp][n] = ffma2(pa[mp], wv[n], acc[mp][n]);
        }
        __syncthreads();
    }

    // ---------------- epilogue ----------------
    const int col0 = n0 + tc * 6;
#pragma unroll
    for (int mp = 0; mp < 4; mp++) {
        int m = m0 + tr * 8 + mp * 2;
        float2 fr[6];
#pragma unroll
        for (int n = 0; n < 6; n++) fr[n] = unpk(acc[mp][n]);
#pragma unroll
        for (int half = 0; half < 2; half++) {
            int row = m + half;
            float v[6];
#pragma unroll
            for (int n = 0; n < 6; n++) v[n] = half ? fr[n].y : fr[n].x;

            if (EPI == 0) {
                float* op = out + (size_t)row * N + col0;
                ((float2*)op)[0] = make_float2(v[0], v[1]);
                ((float2*)op)[1] = make_float2(v[2], v[3]);
                ((float2*)op)[2] = make_float2(v[4], v[5]);
            } else if (EPI == 1) {
                int bb = row >> 14, ss = row & 16383;
#pragma unroll
                for (int n = 0; n < 6; n++)
                    v[n] += __ldg(bias + col0 + n)
                          + __ldg(res + (((size_t)bb * 96 + col0 + n) << 14) + ss);
                float* op = out + (size_t)row * N + col0;
                ((float2*)op)[0] = make_float2(v[0], v[1]);
                ((float2*)op)[1] = make_float2(v[2], v[3]);
                ((float2*)op)[2] = make_float2(v[4], v[5]);
            } else if (EPI == 2) {
#pragma unroll
                for (int n = 0; n < 6; n++) {
                    float t = v[n] + __ldg(bias + col0 + n);
                    v[n] = 0.5f * t * (1.f + erff(t * 0.70710678118654752f));
                }
                float* op = out + (size_t)row * N + col0;
                ((float2*)op)[0] = make_float2(v[0], v[1]);
                ((float2*)op)[1] = make_float2(v[2], v[3]);
                ((float2*)op)[2] = make_float2(v[4], v[5]);
            } else {  // EPI == 3: fc2 -> +bias +res(rowmajor) -> planar output
                int bb = row >> 14, ss = row & 16383;
#pragma unroll
                for (int n = 0; n < 6; n++) {
                    float t = v[n] + __ldg(bias + col0 + n)
                            + __ldg(res + (size_t)row * 96 + col0 + n);
                    out[(((size_t)bb * 96 + col0 + n) << 14) + ss] = t;
                }
            }
        }
    }
}

__global__ __launch_bounds__(256, 2)
void gemm_qkv(const float* __restrict__ W) {
    gemm_core<96, 288, 0>(g_y, W, nullptr, nullptr, g_qkv);
}
__global__ __launch_bounds__(256, 2)
void gemm_proj(const float* __restrict__ W, const float* __restrict__ bias,
               const float* __restrict__ x) {
    gemm_core<96, 96, 1>(g_attn, W, bias, x, g_x1);
}
__global__ __launch_bounds__(256, 2)
void gemm_fc1(const float* __restrict__ W, const float* __restrict__ bias) {
    gemm_core<96, 384, 2>(g_y, W, bias, nullptr, g_h1);
}
__global__ __launch_bounds__(256, 2)
void gemm_fc2(const float* __restrict__ W, const float* __restrict__ bias,
              float* __restrict__ out) {
    gemm_core<384, 96, 3>(g_h1, W, bias, g_x1, out);
}

// ---------------- launch ----------------
extern "C" void kernel_launch(void* const* d_in, const int* in_sizes, int n_in,
                              void* d_out, int out_size) {
    (void)in_sizes; (void)n_in; (void)out_size;
    const float* x      = (const float*)d_in[0];
    const float* qkv_w  = (const float*)d_in[1];
    const float* proj_w = (const float*)d_in[2];
    const float* proj_b = (const float*)d_in[3];
    const float* ln1w   = (const float*)d_in[4];
    const float* ln1b   = (const float*)d_in[5];
    const float* ln2w   = (const float*)d_in[6];
    const float* ln2b   = (const float*)d_in[7];
    const float* fc1w   = (const float*)d_in[8];
    const float* fc1b   = (const float*)d_in[9];
    const float* fc2w   = (const float*)d_in[10];
    const float* fc2b   = (const float*)d_in[11];
    float* out = (float*)d_out;

    ln1_kernel<<<PTOT / 256, 256>>>(x, ln1w, ln1b);
    gemm_qkv<<<dim3(PTOT / GBM, 3), 256>>>(qkv_w);
    attn_kernel<<<(PTOT * 6) / 256, 256>>>();
    gemm_proj<<<dim3(PTOT / GBM, 1), 256>>>(proj_w, proj_b, x);
    ln2_kernel<<<PTOT / 256, 256>>>(ln2w, ln2b);
    gemm_fc1<<<dim3(PTOT / GBM, 4), 256>>>(fc1w, fc1b);
    gemm_fc2<<<dim3(PTOT / GBM, 1), 256>>>(fc2w, fc2b, out);
}

// round 3
// speedup vs baseline: 1.9628x; 1.9628x over previous
#include <cuda_runtime.h>
#include <cstdint>
#include <cstddef>

// ---------------- problem constants ----------------
#define HW    16384            // 128*128
#define PTOT  131072           // 8*128*128

// ---------------- scratch (device globals; no allocation) ----------------
__device__ float g_y   [(size_t)PTOT * 96];    // LN output (row-major P x 96)
__device__ float g_qkv [(size_t)PTOT * 288];   // qkv row-major P x 288
__device__ float g_attn[(size_t)PTOT * 96];    // attention output P x 96
__device__ float g_x1  [(size_t)PTOT * 96];    // x + attn branch, P x 96
__device__ float g_h1  [(size_t)PTOT * 384];   // MLP hidden, P x 384
__device__ float g_w   [110592];               // tf32-rounded weights

// ---------------- helpers ----------------
__device__ __forceinline__ uint32_t smem_u32(const void* p) {
    uint32_t a;
    asm("{ .reg .u64 t; cvta.to.shared.u64 t, %1; cvt.u32.u64 %0, t; }"
        : "=r"(a) : "l"(p));
    return a;
}
__device__ __forceinline__ void cpa16(uint32_t dst, const void* src) {
    asm volatile("cp.async.cg.shared.global [%0], [%1], 16;"
                 :: "r"(dst), "l"(src));
}
__device__ __forceinline__ void cp_commit() {
    asm volatile("cp.async.commit_group;" ::: "memory");
}
__device__ __forceinline__ void cp_wait0() {
    asm volatile("cp.async.wait_group 0;" ::: "memory");
}
__device__ __forceinline__ float tf32r(float x) {
    uint32_t u;
    asm("cvt.rna.tf32.f32 %0, %1;" : "=r"(u) : "f"(x));
    return __uint_as_float(u);
}
#define LDSM4(r0, r1, r2, r3, addr) \
    asm volatile("ldmatrix.sync.aligned.m8n8.x4.shared.b16 {%0,%1,%2,%3}, [%4];" \
                 : "=r"(r0), "=r"(r1), "=r"(r2), "=r"(r3) : "r"(addr))
__device__ __forceinline__ uint32_t lds32(uint32_t addr) {
    uint32_t v;
    asm volatile("ld.shared.b32 %0, [%1];" : "=r"(v) : "r"(addr));
    return v;
}
__device__ __forceinline__ void mma8(float* d, const uint32_t* a,
                                     const uint32_t* b) {
    asm volatile(
        "mma.sync.aligned.m16n8k8.row.col.f32.tf32.tf32.f32 "
        "{%0,%1,%2,%3}, {%4,%5,%6,%7}, {%8,%9}, {%0,%1,%2,%3};"
        : "+f"(d[0]), "+f"(d[1]), "+f"(d[2]), "+f"(d[3])
        : "r"(a[0]), "r"(a[1]), "r"(a[2]), "r"(a[3]), "r"(b[0]), "r"(b[1]));
}

// ---------------- weight rounding (tf32 RNA) ----------------
__global__ __launch_bounds__(256)
void round_w(const float* __restrict__ qkv, const float* __restrict__ proj,
             const float* __restrict__ fc1, const float* __restrict__ fc2) {
    int i = blockIdx.x * 256 + threadIdx.x;
    if (i < 27648)        g_w[i] = tf32r(qkv[i]);
    else if (i < 36864)   g_w[i] = tf32r(proj[i - 27648]);
    else if (i < 73728)   g_w[i] = tf32r(fc1[i - 36864]);
    else if (i < 110592)  g_w[i] = tf32r(fc2[i - 73728]);
}

// ---------------- LayerNorm 1: planar input -> row-major g_y (tf32-rounded) ----
__global__ __launch_bounds__(256)
void ln1_kernel(const float* __restrict__ x, const float* __restrict__ w,
                const float* __restrict__ b) {
    int p = blockIdx.x * 256 + threadIdx.x;
    int bb = p >> 14;
    int ss = p & 16383;
    const float* xp = x + (size_t)bb * 96 * HW + ss;

    float sum = 0.f, sq = 0.f;
#pragma unroll 16
    for (int c = 0; c < 96; c++) {
        float v = __ldg(xp + (size_t)c * HW);
        sum += v;
        sq = fmaf(v, v, sq);
    }
    float mu = sum * (1.f / 96.f);
    float var = sq * (1.f / 96.f) - mu * mu;
    float rs = rsqrtf(var + 1e-5f);

    float* yp = g_y + (size_t)p * 96;
#pragma unroll
    for (int c0 = 0; c0 < 96; c0 += 4) {
        float4 ww = *(const float4*)(w + c0);
        float4 bb4 = *(const float4*)(b + c0);
        float4 o;
        o.x = tf32r((__ldg(xp + (size_t)(c0 + 0) * HW) - mu) * rs * ww.x + bb4.x);
        o.y = tf32r((__ldg(xp + (size_t)(c0 + 1) * HW) - mu) * rs * ww.y + bb4.y);
        o.z = tf32r((__ldg(xp + (size_t)(c0 + 2) * HW) - mu) * rs * ww.z + bb4.z);
        o.w = tf32r((__ldg(xp + (size_t)(c0 + 3) * HW) - mu) * rs * ww.w + bb4.w);
        *(float4*)(yp + c0) = o;
    }
}

// ---------------- LayerNorm 2: g_x1 row-major -> g_y (tf32-rounded) ----------
__global__ __launch_bounds__(256)
void ln2_kernel(const float* __restrict__ w, const float* __restrict__ b) {
    int p = blockIdx.x * 256 + threadIdx.x;
    const float* xp = g_x1 + (size_t)p * 96;

    float sum = 0.f, sq = 0.f;
#pragma unroll
    for (int c0 = 0; c0 < 96; c0 += 4) {
        float4 t = *(const float4*)(xp + c0);
        sum += t.x + t.y + t.z + t.w;
        sq = fmaf(t.x, t.x, sq); sq = fmaf(t.y, t.y, sq);
        sq = fmaf(t.z, t.z, sq); sq = fmaf(t.w, t.w, sq);
    }
    float mu = sum * (1.f / 96.f);
    float var = sq * (1.f / 96.f) - mu * mu;
    float rs = rsqrtf(var + 1e-5f);

    float* yp = g_y + (size_t)p * 96;
#pragma unroll
    for (int c0 = 0; c0 < 96; c0 += 4) {
        float4 t = *(const float4*)(xp + c0);
        float4 ww = *(const float4*)(w + c0);
        float4 bb4 = *(const float4*)(b + c0);
        float4 o;
        o.x = tf32r((t.x - mu) * rs * ww.x + bb4.x);
        o.y = tf32r((t.y - mu) * rs * ww.y + bb4.y);
        o.z = tf32r((t.z - mu) * rs * ww.z + bb4.z);
        o.w = tf32r((t.w - mu) * rs * ww.w + bb4.w);
        *(float4*)(yp + c0) = o;
    }
}

// ---------------- dilated neighborhood attention ----------------
__global__ __launch_bounds__(256)
void attn_kernel() {
    int idx = blockIdx.x * 256 + threadIdx.x;    // < PTOT*6
    int p = idx / 6;
    int hd = idx - p * 6;
    int bb = p >> 14;
    int ss = p & 16383;
    int h = ss >> 7;
    int w = ss & 127;
    int grp = hd >> 1;
    int dil = grp + 1;
    int cb = grp * 32 + (hd & 1) * 16;

    const float* qp = g_qkv + (size_t)p * 288 + cb;
    float4 q0 = *(const float4*)(qp + 0);
    float4 q1 = *(const float4*)(qp + 4);
    float4 q2 = *(const float4*)(qp + 8);
    float4 q3 = *(const float4*)(qp + 12);

    float sc[9];
#pragma unroll
    for (int i = 0; i < 3; i++) {
#pragma unroll
        for (int j = 0; j < 3; j++) {
            int hh = h + (i - 1) * dil;
            int ww = w + (j - 1) * dil;
            float d = 0.f;
            if ((unsigned)hh < 128u && (unsigned)ww < 128u) {
                int pn = (bb << 14) + (hh << 7) + ww;
                const float* kp = g_qkv + (size_t)pn * 288 + 96 + cb;
                float4 k0 = *(const float4*)(kp + 0);
                float4 k1 = *(const float4*)(kp + 4);
                float4 k2 = *(const float4*)(kp + 8);
                float4 k3 = *(const float4*)(kp + 12);
                d = fmaf(q0.x, k0.x, d); d = fmaf(q0.y, k0.y, d);
                d = fmaf(q0.z, k0.z, d); d = fmaf(q0.w, k0.w, d);
                d = fmaf(q1.x, k1.x, d); d = fmaf(q1.y, k1.y, d);
                d = fmaf(q1.z, k1.z, d); d = fmaf(q1.w, k1.w, d);
                d = fmaf(q2.x, k2.x, d); d = fmaf(q2.y, k2.y, d);
                d = fmaf(q2.z, k2.z, d); d = fmaf(q2.w, k2.w, d);
                d = fmaf(q3.x, k3.x, d); d = fmaf(q3.y, k3.y, d);
                d = fmaf(q3.z, k3.z, d); d = fmaf(q3.w, k3.w, d);
            }
            sc[i * 3 + j] = d * 0.25f;
        }
    }

    float mx = sc[0];
#pragma unroll
    for (int k = 1; k < 9; k++) mx = fmaxf(mx, sc[k]);
    float ssum = 0.f;
#pragma unroll
    for (int k = 0; k < 9; k++) { sc[k] = __expf(sc[k] - mx); ssum += sc[k]; }
    float inv = 1.f / ssum;

    float o[16];
#pragma unroll
    for (int d = 0; d < 16; d++) o[d] = 0.f;

#pragma unroll
    for (int i = 0; i < 3; i++) {
#pragma unroll
        for (int j = 0; j < 3; j++) {
            int hh = h + (i - 1) * dil;
            int ww = w + (j - 1) * dil;
            if ((unsigned)hh < 128u && (unsigned)ww < 128u) {
                int pn = (bb << 14) + (hh << 7) + ww;
                const float* vp = g_qkv + (size_t)pn * 288 + 192 + cb;
                float wgt = sc[i * 3 + j] * inv;
                float4 v0 = *(const float4*)(vp + 0);
                float4 v1 = *(const float4*)(vp + 4);
                float4 v2 = *(const float4*)(vp + 8);
                float4 v3 = *(const float4*)(vp + 12);
                o[0]  = fmaf(wgt, v0.x, o[0]);  o[1]  = fmaf(wgt, v0.y, o[1]);
                o[2]  = fmaf(wgt, v0.z, o[2]);  o[3]  = fmaf(wgt, v0.w, o[3]);
                o[4]  = fmaf(wgt, v1.x, o[4]);  o[5]  = fmaf(wgt, v1.y, o[5]);
                o[6]  = fmaf(wgt, v1.z, o[6]);  o[7]  = fmaf(wgt, v1.w, o[7]);
                o[8]  = fmaf(wgt, v2.x, o[8]);  o[9]  = fmaf(wgt, v2.y, o[9]);
                o[10] = fmaf(wgt, v2.z, o[10]); o[11] = fmaf(wgt, v2.w, o[11]);
                o[12] = fmaf(wgt, v3.x, o[12]); o[13] = fmaf(wgt, v3.y, o[13]);
                o[14] = fmaf(wgt, v3.z, o[14]); o[15] = fmaf(wgt, v3.w, o[15]);
            }
        }
    }

    float* op = g_attn + (size_t)p * 96 + cb;
#pragma unroll
    for (int d = 0; d < 16; d++) o[d] = tf32r(o[d]);
    *(float4*)(op + 0)  = make_float4(o[0], o[1], o[2], o[3]);
    *(float4*)(op + 4)  = make_float4(o[4], o[5], o[6], o[7]);
    *(float4*)(op + 8)  = make_float4(o[8], o[9], o[10], o[11]);
    *(float4*)(op + 12) = make_float4(o[12], o[13], o[14], o[15]);
}

// ---------------- HMMA tf32 GEMM ----------------
// out(P, NTOT) = A(P, K) @ W(NTOT, K)^T, K-major both, K chunked by 96.
// Block: 128M x 96N, 256 thr (8 warps, 2Mx4N), warp 64Mx24N = 4x3 m16n8k8.
// SMEM rows padded to 100 floats -> conflict-free ldmatrix / B loads.
// EPI: 0 plain rowmajor; 1 +bias +planar-res rowmajor; 2 +bias GELU(tf32r)
//      rowmajor; 3 +bias +rowmajor-res, planar store.
#define SMEM_FLOATS 24832              // max(12800+9600, 2*12416)
#define SMEM_SZ     (SMEM_FLOATS * 4)

template <int K, int NTOT, int EPI>
__global__ __launch_bounds__(256, 2)
void tgemm(const float* __restrict__ A, const float* __restrict__ W,
           const float* __restrict__ bias, const float* __restrict__ res,
           float* __restrict__ out) {
    constexpr int NC = K / 96;
    extern __shared__ __align__(16) float sm[];
    const uint32_t sAa = smem_u32(sm);          // 128 x 100 floats
    const uint32_t sWa = sAa + 51200;           // 96 x 100 floats

    const int tid = threadIdx.x;
    const int lane = tid & 31;
    const int wid = tid >> 5;
    const int wr = wid >> 2;                    // 0..1
    const int wc = wid & 3;                     // 0..3
    const int g = lane >> 2, tig = lane & 3;
    const int m0 = blockIdx.x * 128;
    const int n0 = blockIdx.y * 96;

    float acc[4][3][4];
#pragma unroll
    for (int i = 0; i < 4; i++)
#pragma unroll
        for (int j = 0; j < 3; j++)
#pragma unroll
            for (int q = 0; q < 4; q++) acc[i][j][q] = 0.f;

    // ldmatrix per-lane addresses: lanes 0-7 rows 0-7 @k0, 8-15 rows 8-15 @k0,
    // 16-23 rows 0-7 @k0+4, 24-31 rows 8-15 @k0+4  (a0..a3 of m16n8k8 tf32)
    uint32_t aAddr[4];
    {
        int sel = lane >> 3, lrow = lane & 7;
        int rb = wr * 64 + (sel & 1) * 8 + lrow;
        int kw = (sel >> 1) * 4;
#pragma unroll
        for (int i = 0; i < 4; i++)
            aAddr[i] = sAa + (uint32_t)(((rb + i * 16) * 100 + kw) * 4);
    }
    uint32_t bAddr[3];
#pragma unroll
    for (int j = 0; j < 3; j++)
        bAddr[j] = sWa + (uint32_t)(((wc * 24 + j * 8 + g) * 100 + tig) * 4);

#pragma unroll 1
    for (int c = 0; c < NC; c++) {
        const float* Ab = A + (size_t)m0 * K + c * 96;
#pragma unroll
        for (int it = 0; it < 12; it++) {        // 3072 x 16B
            int u = it * 256 + tid;
            int r = u / 24, cc = u - r * 24;
            cpa16(sAa + (uint32_t)(r * 400 + cc * 16),
                  Ab + (size_t)r * K + cc * 4);
        }
        const float* Wb = W + (size_t)n0 * K + c * 96;
#pragma unroll
        for (int it = 0; it < 9; it++) {         // 2304 x 16B
            int u = it * 256 + tid;
            int r = u / 24, cc = u - r * 24;
            cpa16(sWa + (uint32_t)(r * 400 + cc * 16),
                  Wb + (size_t)r * K + cc * 4);
        }
        cp_commit();
        cp_wait0();
        __syncthreads();

#pragma unroll
        for (int ks = 0; ks < 12; ks++) {
            uint32_t a[4][4], b[3][2];
#pragma unroll
            for (int i = 0; i < 4; i++)
                LDSM4(a[i][0], a[i][1], a[i][2], a[i][3],
                      aAddr[i] + (uint32_t)(ks * 32));
#pragma unroll
            for (int j = 0; j < 3; j++) {
                b[j][0] = lds32(bAddr[j] + (uint32_t)(ks * 32));
                b[j][1] = lds32(bAddr[j] + (uint32_t)(ks * 32 + 16));
            }
#pragma unroll
            for (int i = 0; i < 4; i++)
#pragma unroll
                for (int j = 0; j < 3; j++)
                    mma8(acc[i][j], a[i], b[j]);
        }
        __syncthreads();
    }

    // ---------------- epilogue ----------------
    float* stgD = sm;                            // 128 x 97
    float* stgR = sm + 12416;                    // 128 x 97
#pragma unroll
    for (int i = 0; i < 4; i++)
#pragma unroll
        for (int j = 0; j < 3; j++) {
            int row = wr * 64 + i * 16 + g;
            int col = wc * 24 + j * 8 + 2 * tig;
            stgD[row * 97 + col]       = acc[i][j][0];
            stgD[row * 97 + col + 1]   = acc[i][j][1];
            stgD[(row + 8) * 97 + col]     = acc[i][j][2];
            stgD[(row + 8) * 97 + col + 1] = acc[i][j][3];
        }

    if (EPI == 1) {
        // stage planar residual col-major (coalesced planar reads)
        int bb = m0 >> 14, ss0 = m0 & 16383;
#pragma unroll 4
        for (int u = tid; u < 12288; u += 256) {
            int col = u >> 7, r = u & 127;
            stgR[r * 97 + col] =
                res[(((size_t)bb * 96 + n0 + col) << 14) + ss0 + r];
        }
    } else if (EPI == 3) {
        // stage row-major residual (coalesced)
#pragma unroll 4
        for (int u = tid; u < 12288; u += 256) {
            int r = u / 96, col = u - r * 96;
            stgR[r * 97 + col] = res[(size_t)(m0 + r) * 96 + col];
        }
    }
    __syncthreads();

    if (EPI == 0) {
#pragma unroll 4
        for (int u = tid; u < 12288; u += 256) {
            int r = u / 96, col = u - r * 96;
            out[(size_t)(m0 + r) * NTOT + n0 + col] = stgD[r * 97 + col];
        }
    } else if (EPI == 1) {
#pragma unroll 4
        for (int u = tid; u < 12288; u += 256) {
            int r = u / 96, col = u - r * 96;
            out[(size_t)(m0 + r) * NTOT + n0 + col] =
                stgD[r * 97 + col] + __ldg(bias + n0 + col) + stgR[r * 97 + col];
        }
    } else if (EPI == 2) {
#pragma unroll 2
        for (int u = tid; u < 12288; u += 256) {
            int r = u / 96, col = u - r * 96;
            float t = stgD[r * 97 + col] + __ldg(bias + n0 + col);
            t = 0.5f * t * (1.f + erff(t * 0.70710678118654752f));
            out[(size_t)(m0 + r) * NTOT + n0 + col] = tf32r(t);
        }
    } else {  // EPI == 3: planar store, coalesced
        int bb = m0 >> 14, ss0 = m0 & 16383;
#pragma unroll 4
        for (int u = tid; u < 12288; u += 256) {
            int col = u >> 7, r = u & 127;
            float t = stgD[r * 97 + col] + __ldg(bias + n0 + col)
                    + stgR[r * 97 + col];
            out[(((size_t)bb * 96 + n0 + col) << 14) + ss0 + r] = t;
        }
    }
}

// ---------------- launch ----------------
extern "C" void kernel_launch(void* const* d_in, const int* in_sizes, int n_in,
                              void* d_out, int out_size) {
    (void)in_sizes; (void)n_in; (void)out_size;
    const float* x      = (const float*)d_in[0];
    const float* qkv_w  = (const float*)d_in[1];
    const float* proj_w = (const float*)d_in[2];
    const float* proj_b = (const float*)d_in[3];
    const float* ln1w   = (const float*)d_in[4];
    const float* ln1b   = (const float*)d_in[5];
    const float* ln2w   = (const float*)d_in[6];
    const float* ln2b   = (const float*)d_in[7];
    const float* fc1w   = (const float*)d_in[8];
    const float* fc1b   = (const float*)d_in[9];
    const float* fc2w   = (const float*)d_in[10];
    const float* fc2b   = (const float*)d_in[11];
    float* out = (float*)d_out;

    cudaFuncSetAttribute(tgemm<96, 288, 0>,
                         cudaFuncAttributeMaxDynamicSharedMemorySize, SMEM_SZ);
    cudaFuncSetAttribute(tgemm<96, 96, 1>,
                         cudaFuncAttributeMaxDynamicSharedMemorySize, SMEM_SZ);
    cudaFuncSetAttribute(tgemm<96, 384, 2>,
                         cudaFuncAttributeMaxDynamicSharedMemorySize, SMEM_SZ);
    cudaFuncSetAttribute(tgemm<384, 96, 3>,
                         cudaFuncAttributeMaxDynamicSharedMemorySize, SMEM_SZ);

    float *py, *pqkv, *pattn, *px1, *ph1, *pw;
    cudaGetSymbolAddress((void**)&py, g_y);
    cudaGetSymbolAddress((void**)&pqkv, g_qkv);
    cudaGetSymbolAddress((void**)&pattn, g_attn);
    cudaGetSymbolAddress((void**)&px1, g_x1);
    cudaGetSymbolAddress((void**)&ph1, g_h1);
    cudaGetSymbolAddress((void**)&pw, g_w);

    round_w<<<432, 256>>>(qkv_w, proj_w, fc1w, fc2w);
    ln1_kernel<<<PTOT / 256, 256>>>(x, ln1w, ln1b);
    tgemm<96, 288, 0><<<dim3(PTOT / 128, 3), 256, SMEM_SZ>>>(
        py, pw, nullptr, nullptr, pqkv);
    attn_kernel<<<(PTOT * 6) / 256, 256>>>();
    tgemm<96, 96, 1><<<dim3(PTOT / 128, 1), 256, SMEM_SZ>>>(
        pattn, pw + 27648, proj_b, x, px1);
    ln2_kernel<<<PTOT / 256, 256>>>(ln2w, ln2b);
    tgemm<96, 384, 2><<<dim3(PTOT / 128, 4), 256, SMEM_SZ>>>(
        py, pw + 36864, fc1b, nullptr, ph1);
    tgemm<384, 96, 3><<<dim3(PTOT / 128, 1), 256, SMEM_SZ>>>(
        ph1, pw + 73728, fc2b, px1, out);
}

// round 4
// speedup vs baseline: 2.8366x; 1.4452x over previous
#include <cuda_runtime.h>
#include <cuda_bf16.h>
#include <cstdint>
#include <cstddef>

// ---------------- problem constants ----------------
#define HW    16384            // 128*128
#define PTOT  131072           // 8*128*128 = 1<<17

// ---------------- scratch (device globals; no allocation) ----------------
__device__ __align__(16) __nv_bfloat16 g_y   [(size_t)PTOT * 96];   // LN out, row-major P x 96
__device__ __align__(16) __nv_bfloat16 g_qkv [(size_t)PTOT * 288];  // PLANAR [288][P]
__device__ __align__(16) __nv_bfloat16 g_attn[(size_t)PTOT * 96];   // row-major P x 96
__device__ __align__(16) float         g_x1  [(size_t)PTOT * 96];   // fp32 residual, P x 96
__device__ __align__(16) __nv_bfloat16 g_h1  [(size_t)PTOT * 384];  // MLP hidden, P x 384
__device__ __align__(16) __nv_bfloat16 g_wb  [110592];              // bf16 weights

// ---------------- helpers ----------------
__device__ __forceinline__ uint32_t smem_u32(const void* p) {
    uint32_t a;
    asm("{ .reg .u64 t; cvta.to.shared.u64 t, %1; cvt.u32.u64 %0, t; }"
        : "=r"(a) : "l"(p));
    return a;
}
__device__ __forceinline__ void cpa16(uint32_t dst, const void* src) {
    asm volatile("cp.async.cg.shared.global [%0], [%1], 16;"
                 :: "r"(dst), "l"(src));
}
__device__ __forceinline__ void cp_commit() {
    asm volatile("cp.async.commit_group;" ::: "memory");
}
__device__ __forceinline__ void cp_wait0() {
    asm volatile("cp.async.wait_group 0;" ::: "memory");
}
#define LDSM4(r0, r1, r2, r3, addr) \
    asm volatile("ldmatrix.sync.aligned.m8n8.x4.shared.b16 {%0,%1,%2,%3}, [%4];" \
                 : "=r"(r0), "=r"(r1), "=r"(r2), "=r"(r3) : "r"(addr))
__device__ __forceinline__ uint32_t lds32(uint32_t addr) {
    uint32_t v;
    asm volatile("ld.shared.b32 %0, [%1];" : "=r"(v) : "r"(addr));
    return v;
}
__device__ __forceinline__ void mma16(float* d, const uint32_t* a,
                                      const uint32_t* b) {
    asm volatile(
        "mma.sync.aligned.m16n8k16.row.col.f32.bf16.bf16.f32 "
        "{%0,%1,%2,%3}, {%4,%5,%6,%7}, {%8,%9}, {%0,%1,%2,%3};"
        : "+f"(d[0]), "+f"(d[1]), "+f"(d[2]), "+f"(d[3])
        : "r"(a[0]), "r"(a[1]), "r"(a[2]), "r"(a[3]), "r"(b[0]), "r"(b[1]));
}
__device__ __forceinline__ uint32_t packbf(float a, float b) {
    __nv_bfloat162 p = __floats2bfloat162_rn(a, b);
    return *(uint32_t*)&p;
}

// ---------------- weight conversion fp32 -> bf16 ----------------
__global__ __launch_bounds__(256)
void round_w(const float* __restrict__ qkv, const float* __restrict__ proj,
             const float* __restrict__ fc1, const float* __restrict__ fc2) {
    int i = blockIdx.x * 256 + threadIdx.x;
    float v;
    if (i < 27648)        v = qkv[i];
    else if (i < 36864)   v = proj[i - 27648];
    else if (i < 73728)   v = fc1[i - 36864];
    else                  v = fc2[i - 73728];
    g_wb[i] = __float2bfloat16_rn(v);
}

// ---------------- LayerNorm 1: planar fp32 x -> bf16 row-major g_y ----------
__global__ __launch_bounds__(256)
void ln1_kernel(const float* __restrict__ x, const float* __restrict__ w,
                const float* __restrict__ b, __nv_bfloat16* __restrict__ y) {
    extern __shared__ __align__(16) uint32_t ss[];   // 256 x 51 u32
    int tid = threadIdx.x;
    int p = blockIdx.x * 256 + tid;
    int bb = p >> 14;
    int sp = p & 16383;
    const float* xp = x + (size_t)bb * 96 * HW + sp;

    float sum = 0.f, sq = 0.f;
#pragma unroll 16
    for (int c = 0; c < 96; c++) {
        float v = __ldg(xp + (size_t)c * HW);
        sum += v;
        sq = fmaf(v, v, sq);
    }
    float mu = sum * (1.f / 96.f);
    float var = sq * (1.f / 96.f) - mu * mu;
    float rs = rsqrtf(var + 1e-5f);

#pragma unroll
    for (int c0 = 0; c0 < 96; c0 += 2) {
        float v0 = (__ldg(xp + (size_t)(c0 + 0) * HW) - mu) * rs
                 * __ldg(w + c0 + 0) + __ldg(b + c0 + 0);
        float v1 = (__ldg(xp + (size_t)(c0 + 1) * HW) - mu) * rs
                 * __ldg(w + c0 + 1) + __ldg(b + c0 + 1);
        ss[tid * 51 + (c0 >> 1)] = packbf(v0, v1);
    }
    __syncthreads();
    uint32_t* og = (uint32_t*)(y + (size_t)blockIdx.x * 256 * 96);
#pragma unroll 8
    for (int u = tid; u < 12288; u += 256) {
        int r = u / 48, c2 = u - r * 48;
        og[r * 48 + c2] = ss[r * 51 + c2];
    }
}

// ---------------- LayerNorm 2: fp32 g_x1 row-major -> bf16 g_y --------------
__global__ __launch_bounds__(256)
void ln2_kernel(const float* __restrict__ xin, const float* __restrict__ w,
                const float* __restrict__ b, __nv_bfloat16* __restrict__ y) {
    extern __shared__ __align__(16) uint32_t ss[];   // 256 x 51 u32
    int tid = threadIdx.x;
    int p = blockIdx.x * 256 + tid;
    const float* xp = xin + (size_t)p * 96;

    float sum = 0.f, sq = 0.f;
#pragma unroll
    for (int c0 = 0; c0 < 96; c0 += 4) {
        float4 t = *(const float4*)(xp + c0);
        sum += t.x + t.y + t.z + t.w;
        sq = fmaf(t.x, t.x, sq); sq = fmaf(t.y, t.y, sq);
        sq = fmaf(t.z, t.z, sq); sq = fmaf(t.w, t.w, sq);
    }
    float mu = sum * (1.f / 96.f);
    float var = sq * (1.f / 96.f) - mu * mu;
    float rs = rsqrtf(var + 1e-5f);

#pragma unroll
    for (int c0 = 0; c0 < 96; c0 += 2) {
        float2 t = *(const float2*)(xp + c0);
        float v0 = (t.x - mu) * rs * __ldg(w + c0 + 0) + __ldg(b + c0 + 0);
        float v1 = (t.y - mu) * rs * __ldg(w + c0 + 1) + __ldg(b + c0 + 1);
        ss[tid * 51 + (c0 >> 1)] = packbf(v0, v1);
    }
    __syncthreads();
    uint32_t* og = (uint32_t*)(y + (size_t)blockIdx.x * 256 * 96);
#pragma unroll 8
    for (int u = tid; u < 12288; u += 256) {
        int r = u / 48, c2 = u - r * 48;
        og[r * 48 + c2] = ss[r * 51 + c2];
    }
}

// ---------------- dilated neighborhood attention (SMEM-tiled) ---------------
// CTA: 2 image rows x 128 w, one head. qkv planar bf16 [288][P].
// k/v rows h0-d..h0+1+d staged in SMEM, zero-padded in h and w: OOB neighbors
// contribute exact 0 score / 0 value (matches reference zero-pad unfold).
// SMEM: k [16ch][8r][144w] bf16 (18432 el), v same at +18432. Pads: w offset +8.
__global__ __launch_bounds__(256)
void attn_kernel(const __nv_bfloat16* __restrict__ qkvp,
                 __nv_bfloat16* __restrict__ attn) {
    extern __shared__ __align__(16) __nv_bfloat16 sm[];
    const int tid = threadIdx.x;
    const int b = blockIdx.x >> 6;
    const int h0 = (blockIdx.x & 63) << 1;
    const int hd = blockIdx.y;
    const int grp = hd >> 1;
    const int dil = grp + 1;
    const int cb = grp * 32 + (hd & 1) * 16;
    const int nr = 2 + 2 * dil;

    // zero both tensors (73728 B = 4608 float4)
    {
        float4 z = make_float4(0.f, 0.f, 0.f, 0.f);
        float4* smv = (float4*)sm;
#pragma unroll
        for (int i = 0; i < 18; i++) smv[i * 256 + tid] = z;
    }
    __syncthreads();

    // stage k and v rows
    const int baseh = h0 - dil;
    for (int u = tid; u < (nr << 8); u += 256) {
        int q16 = u & 15, seg = u >> 4;
        int ch = seg / nr, row = seg - ch * nr;
        int hr = baseh + row;
        if ((unsigned)hr < 128u) {
            size_t gofs = ((size_t)b << 14) + (hr << 7);
            const float4* sk = (const float4*)(qkvp
                + (((size_t)(96 + cb + ch)) << 17) + gofs) + q16;
            *((float4*)(sm + ch * 1152 + row * 144 + 8) + q16) = *sk;
            const float4* sv = (const float4*)(qkvp
                + (((size_t)(192 + cb + ch)) << 17) + gofs) + q16;
            *((float4*)(sm + 18432 + ch * 1152 + row * 144 + 8) + q16) = *sv;
        }
    }
    __syncthreads();

    const int r = tid >> 7, w = tid & 127;
    const size_t p = ((size_t)b << 14) + ((size_t)(h0 + r) << 7) + w;

    float q[16];
#pragma unroll
    for (int c = 0; c < 16; c++)
        q[c] = __bfloat162float(qkvp[(((size_t)(cb + c)) << 17) + p]);

    float sc[9];
#pragma unroll
    for (int i = 0; i < 3; i++)
#pragma unroll
        for (int j = 0; j < 3; j++) {
            int base = (r + i * dil) * 144 + (w + 8 + (j - 1) * dil);
            float d = 0.f;
#pragma unroll
            for (int c = 0; c < 16; c++)
                d = fmaf(q[c], __bfloat162float(sm[c * 1152 + base]), d);
            sc[i * 3 + j] = d * 0.25f;      // SCALE = 16^-0.5
        }

    float mx = sc[0];
#pragma unroll
    for (int k = 1; k < 9; k++) mx = fmaxf(mx, sc[k]);
    float ssum = 0.f;
#pragma unroll
    for (int k = 0; k < 9; k++) { sc[k] = __expf(sc[k] - mx); ssum += sc[k]; }
    float inv = 1.f / ssum;

    float o[16];
#pragma unroll
    for (int c = 0; c < 16; c++) o[c] = 0.f;
#pragma unroll
    for (int i = 0; i < 3; i++)
#pragma unroll
        for (int j = 0; j < 3; j++) {
            float wgt = sc[i * 3 + j] * inv;
            int base = 18432 + (r + i * dil) * 144 + (w + 8 + (j - 1) * dil);
#pragma unroll
            for (int c = 0; c < 16; c++)
                o[c] = fmaf(wgt, __bfloat162float(sm[c * 1152 + base]), o[c]);
        }

    // restage (reuse smem) -> coalesced bf16 row-major store
    __syncthreads();
    uint32_t* so = (uint32_t*)sm;
#pragma unroll
    for (int c2 = 0; c2 < 8; c2++)
        so[tid * 17 + c2] = packbf(o[2 * c2], o[2 * c2 + 1]);
    __syncthreads();
    const size_t p0 = ((size_t)b << 14) + ((size_t)h0 << 7);
#pragma unroll
    for (int u = tid; u < 2048; u += 256) {
        int row = u >> 3, wq = u & 7;
        ((uint32_t*)(attn + (p0 + row) * 96 + cb))[wq] = so[row * 17 + wq];
    }
}

// ---------------- bf16 HMMA GEMM ----------------
// out(P, NTOT) = A(P, K) @ W(NTOT, K)^T, bf16 in, fp32 accum, K chunks of 96.
// Block 128M x 96N, 8 warps (2Mx4N), warp 64x24 = 4x3 m16n8k16.
// SMEM rows padded to 104 bf16 (208 B) -> conflict-free ldmatrix / lds32.
// EPI: 0 -> bf16 PLANAR [NTOT][P] (qkv); 1 -> fp32 rowmajor +bias +planar res;
//      2 -> bf16 rowmajor +bias GELU; 3 -> fp32 planar +bias +rowmajor res.
#define SZ_MAIN 49664
#define SZ_RES  99328

template <int K, int NTOT, int EPI>
__global__ __launch_bounds__(256)
void tgemm(const __nv_bfloat16* __restrict__ A,
           const __nv_bfloat16* __restrict__ W,
           const float* __restrict__ bias, const float* __restrict__ res,
           float* __restrict__ outf, __nv_bfloat16* __restrict__ outb) {
    constexpr int NC = K / 96;
    extern __shared__ __align__(16) char dsm[];
    const uint32_t sAa = smem_u32(dsm);            // [128][104] bf16
    const uint32_t sWa = sAa + 26624;              // [96][104] bf16

    const int tid = threadIdx.x;
    const int lane = tid & 31;
    const int wid = tid >> 5;
    const int wr = wid >> 2;                       // 0..1
    const int wc = wid & 3;                        // 0..3
    const int g = lane >> 2, tig = lane & 3;
    const int m0 = blockIdx.x * 128;
    const int n0 = blockIdx.y * 96;

    float acc[4][3][4];
#pragma unroll
    for (int i = 0; i < 4; i++)
#pragma unroll
        for (int j = 0; j < 3; j++)
#pragma unroll
            for (int q = 0; q < 4; q++) acc[i][j][q] = 0.f;

    uint32_t aAddr[4];
#pragma unroll
    for (int i = 0; i < 4; i++)
        aAddr[i] = sAa + (uint32_t)((wr * 64 + i * 16 + (lane & 15)) * 208
                                    + (lane >> 4) * 16);
    uint32_t bAddr[3];
#pragma unroll
    for (int j = 0; j < 3; j++)
        bAddr[j] = sWa + (uint32_t)((wc * 24 + j * 8 + g) * 208 + tig * 4);

#pragma unroll 1
    for (int c = 0; c < NC; c++) {
        const __nv_bfloat16* Ab = A + (size_t)m0 * K + c * 96;
#pragma unroll
        for (int it = 0; it < 6; it++) {           // 1536 x 16B
            int u = it * 256 + tid;
            int rr = u / 12, cc = u - rr * 12;
            cpa16(sAa + (uint32_t)(rr * 208 + cc * 16),
                  Ab + (size_t)rr * K + cc * 8);
        }
        const __nv_bfloat16* Wb = W + (size_t)n0 * K + c * 96;
        for (int u = tid; u < 1152; u += 256) {    // 1152 x 16B
            int rr = u / 12, cc = u - rr * 12;
            cpa16(sWa + (uint32_t)(rr * 208 + cc * 16),
                  Wb + (size_t)rr * K + cc * 8);
        }
        cp_commit();
        cp_wait0();
        __syncthreads();

#pragma unroll
        for (int ks = 0; ks < 6; ks++) {
            uint32_t a[4][4], bb2[3][2];
#pragma unroll
            for (int i = 0; i < 4; i++)
                LDSM4(a[i][0], a[i][1], a[i][2], a[i][3],
                      aAddr[i] + (uint32_t)(ks * 32));
#pragma unroll
            for (int j = 0; j < 3; j++) {
                bb2[j][0] = lds32(bAddr[j] + (uint32_t)(ks * 32));
                bb2[j][1] = lds32(bAddr[j] + (uint32_t)(ks * 32 + 16));
            }
#pragma unroll
            for (int i = 0; i < 4; i++)
#pragma unroll
                for (int j = 0; j < 3; j++)
                    mma16(acc[i][j], a[i], bb2[j]);
        }
        __syncthreads();
    }

    // ---------------- epilogue (stgD overlaps tiles; tiles dead now) --------
    float* stgD = (float*)dsm;                     // 128 x 97 fp32
    float* stgR = (float*)(dsm + 49664);           // 128 x 97 fp32 (EPI 1/3)
#pragma unroll
    for (int i = 0; i < 4; i++)
#pragma unroll
        for (int j = 0; j < 3; j++) {
            int row = wr * 64 + i * 16 + g;
            int col = wc * 24 + j * 8 + 2 * tig;
            stgD[row * 97 + col]           = acc[i][j][0];
            stgD[row * 97 + col + 1]       = acc[i][j][1];
            stgD[(row + 8) * 97 + col]     = acc[i][j][2];
            stgD[(row + 8) * 97 + col + 1] = acc[i][j][3];
        }

    if (EPI == 1) {       // planar fp32 residual, staged coalesced
        int bb = m0 >> 14, ss0 = m0 & 16383;
#pragma unroll 4
        for (int u = tid; u < 12288; u += 256) {
            int col = u >> 7, rr = u & 127;
            stgR[rr * 97 + col] =
                res[(((size_t)bb * 96 + n0 + col) << 14) + ss0 + rr];
        }
    } else if (EPI == 3) { // row-major fp32 residual
#pragma unroll 4
        for (int u = tid; u < 12288; u += 256) {
            int rr = u / 96, col = u - rr * 96;
            stgR[rr * 97 + col] = res[(size_t)(m0 + rr) * 96 + col];
        }
    }
    __syncthreads();

    if (EPI == 0) {        // bf16 planar [NTOT][P]
#pragma unroll 4
        for (int u = tid; u < 6144; u += 256) {
            int col = u >> 6, r2 = (u & 63) << 1;
            uint32_t pk = packbf(stgD[r2 * 97 + col], stgD[(r2 + 1) * 97 + col]);
            *((uint32_t*)(outb + (((size_t)(n0 + col)) << 17) + m0)
              + (u & 63)) = pk;
        }
    } else if (EPI == 1) { // fp32 row-major +bias +res
#pragma unroll 4
        for (int u = tid; u < 12288; u += 256) {
            int rr = u / 96, col = u - rr * 96;
            outf[(size_t)(m0 + rr) * NTOT + n0 + col] =
                stgD[rr * 97 + col] + __ldg(bias + n0 + col)
                + stgR[rr * 97 + col];
        }
    } else if (EPI == 2) { // bf16 row-major, GELU
#pragma unroll 2
        for (int u = tid; u < 6144; u += 256) {
            int rr = u / 48, c2 = (u - rr * 48) * 2;
            float t0 = stgD[rr * 97 + c2] + __ldg(bias + n0 + c2);
            float t1 = stgD[rr * 97 + c2 + 1] + __ldg(bias + n0 + c2 + 1);
            t0 = 0.5f * t0 * (1.f + erff(t0 * 0.70710678118654752f));
            t1 = 0.5f * t1 * (1.f + erff(t1 * 0.70710678118654752f));
            *(uint32_t*)(outb + (size_t)(m0 + rr) * NTOT + n0 + c2) =
                packbf(t0, t1);
        }
    } else {               // EPI == 3: fp32 planar +bias +res
        int bb = m0 >> 14, ss0 = m0 & 16383;
#pragma unroll 4
        for (int u = tid; u < 12288; u += 256) {
            int col = u >> 7, rr = u & 127;
            float t = stgD[rr * 97 + col] + __ldg(bias + n0 + col)
                    + stgR[rr * 97 + col];
            outf[(((size_t)bb * 96 + n0 + col) << 14) + ss0 + rr] = t;
        }
    }
}

// ---------------- launch ----------------
extern "C" void kernel_launch(void* const* d_in, const int* in_sizes, int n_in,
                              void* d_out, int out_size) {
    (void)in_sizes; (void)n_in; (void)out_size;
    const float* x      = (const float*)d_in[0];
    const float* qkv_w  = (const float*)d_in[1];
    const float* proj_w = (const float*)d_in[2];
    const float* proj_b = (const float*)d_in[3];
    const float* ln1w   = (const float*)d_in[4];
    const float* ln1b   = (const float*)d_in[5];
    const float* ln2w   = (const float*)d_in[6];
    const float* ln2b   = (const float*)d_in[7];
    const float* fc1w   = (const float*)d_in[8];
    const float* fc1b   = (const float*)d_in[9];
    const float* fc2w   = (const float*)d_in[10];
    const float* fc2b   = (const float*)d_in[11];
    float* out = (float*)d_out;

    cudaFuncSetAttribute(ln1_kernel,
                         cudaFuncAttributeMaxDynamicSharedMemorySize, 52224);
    cudaFuncSetAttribute(ln2_kernel,
                         cudaFuncAttributeMaxDynamicSharedMemorySize, 52224);
    cudaFuncSetAttribute(attn_kernel,
                         cudaFuncAttributeMaxDynamicSharedMemorySize, 73728);
    cudaFuncSetAttribute(tgemm<96, 288, 0>,
                         cudaFuncAttributeMaxDynamicSharedMemorySize, SZ_MAIN);
    cudaFuncSetAttribute(tgemm<96, 96, 1>,
                         cudaFuncAttributeMaxDynamicSharedMemorySize, SZ_RES);
    cudaFuncSetAttribute(tgemm<96, 384, 2>,
                         cudaFuncAttributeMaxDynamicSharedMemorySize, SZ_MAIN);
    cudaFuncSetAttribute(tgemm<384, 96, 3>,
                         cudaFuncAttributeMaxDynamicSharedMemorySize, SZ_RES);

    __nv_bfloat16 *py, *pqkv, *pattn, *ph1, *pwb;
    float *px1;
    cudaGetSymbolAddress((void**)&py, g_y);
    cudaGetSymbolAddress((void**)&pqkv, g_qkv);
    cudaGetSymbolAddress((void**)&pattn, g_attn);
    cudaGetSymbolAddress((void**)&px1, g_x1);
    cudaGetSymbolAddress((void**)&ph1, g_h1);
    cudaGetSymbolAddress((void**)&pwb, g_wb);

    round_w<<<432, 256>>>(qkv_w, proj_w, fc1w, fc2w);
    ln1_kernel<<<PTOT / 256, 256, 52224>>>(x, ln1w, ln1b, py);
    tgemm<96, 288, 0><<<dim3(PTOT / 128, 3), 256, SZ_MAIN>>>(
        py, pwb, nullptr, nullptr, nullptr, pqkv);
    attn_kernel<<<dim3(512, 6), 256, 73728>>>(pqkv, pattn);
    tgemm<96, 96, 1><<<dim3(PTOT / 128, 1), 256, SZ_RES>>>(
        pattn, pwb + 27648, proj_b, x, px1, nullptr);
    ln2_kernel<<<PTOT / 256, 256, 52224>>>(px1, ln2w, ln2b, py);
    tgemm<96, 384, 2><<<dim3(PTOT / 128, 4), 256, SZ_MAIN>>>(
        py, pwb + 36864, fc1b, nullptr, nullptr, ph1);
    tgemm<384, 96, 3><<<dim3(PTOT / 128, 1), 256, SZ_RES>>>(
        ph1, pwb + 73728, fc2b, px1, out, nullptr);
}

// round 5
// speedup vs baseline: 3.6884x; 1.3003x over previous
#include <cuda_runtime.h>
#include <cuda_bf16.h>
#include <cstdint>
#include <cstddef>

// ---------------- problem constants ----------------
#define HW    16384            // 128*128
#define PTOT  131072           // 8*128*128 = 1<<17

// ---------------- scratch (device globals; no allocation) ----------------
__device__ __align__(16) __nv_bfloat16 g_qkv [(size_t)PTOT * 288];  // PLANAR [288][P]
__device__ __align__(16) __nv_bfloat16 g_attn[(size_t)PTOT * 96];   // row-major P x 96
__device__ __align__(16) float         g_x1  [(size_t)PTOT * 96];   // fp32 residual P x 96
__device__ __align__(16) __nv_bfloat16 g_wb  [110592];              // bf16 weights

// ---------------- helpers ----------------
__device__ __forceinline__ uint32_t smem_u32(const void* p) {
    uint32_t a;
    asm("{ .reg .u64 t; cvta.to.shared.u64 t, %1; cvt.u32.u64 %0, t; }"
        : "=r"(a) : "l"(p));
    return a;
}
__device__ __forceinline__ void cpa16(uint32_t dst, const void* src) {
    asm volatile("cp.async.cg.shared.global [%0], [%1], 16;"
                 :: "r"(dst), "l"(src));
}
__device__ __forceinline__ void cp_commit() {
    asm volatile("cp.async.commit_group;" ::: "memory");
}
__device__ __forceinline__ void cp_wait0() {
    asm volatile("cp.async.wait_group 0;" ::: "memory");
}
#define LDSM4(r0, r1, r2, r3, addr) \
    asm volatile("ldmatrix.sync.aligned.m8n8.x4.shared.b16 {%0,%1,%2,%3}, [%4];" \
                 : "=r"(r0), "=r"(r1), "=r"(r2), "=r"(r3) : "r"(addr))
__device__ __forceinline__ uint32_t lds32(uint32_t addr) {
    uint32_t v;
    asm volatile("ld.shared.b32 %0, [%1];" : "=r"(v) : "r"(addr));
    return v;
}
__device__ __forceinline__ void mma16(float* d, const uint32_t* a,
                                      const uint32_t* b) {
    asm volatile(
        "mma.sync.aligned.m16n8k16.row.col.f32.bf16.bf16.f32 "
        "{%0,%1,%2,%3}, {%4,%5,%6,%7}, {%8,%9}, {%0,%1,%2,%3};"
        : "+f"(d[0]), "+f"(d[1]), "+f"(d[2]), "+f"(d[3])
        : "r"(a[0]), "r"(a[1]), "r"(a[2]), "r"(a[3]), "r"(b[0]), "r"(b[1]));
}
__device__ __forceinline__ uint32_t packbf(float a, float b) {
    __nv_bfloat162 p = __floats2bfloat162_rn(a, b);
    return *(uint32_t*)&p;
}
__device__ __forceinline__ float bflo(uint32_t u) {
    return __uint_as_float(u << 16);
}
__device__ __forceinline__ float bfhi(uint32_t u) {
    return __uint_as_float(u & 0xffff0000u);
}

// ---------------- weight conversion fp32 -> bf16 ----------------
__global__ __launch_bounds__(256)
void round_w(const float* __restrict__ qkv, const float* __restrict__ proj,
             const float* __restrict__ fc1, const float* __restrict__ fc2) {
    int i = blockIdx.x * 256 + threadIdx.x;
    float v;
    if (i < 27648)        v = qkv[i];
    else if (i < 36864)   v = proj[i - 27648];
    else if (i < 73728)   v = fc1[i - 36864];
    else                  v = fc2[i - 73728];
    g_wb[i] = __float2bfloat16_rn(v);
}

// ================= fused LN1 + qkv GEMM =================
// CTA = 128 pixels. LN in regs (pair-split per pixel), bf16 A tile in SMEM,
// loop 3 N-blocks of 96 reusing A. Output: bf16 planar [288][P].
// SMEM: sA [128][104] bf16 (26624) | sW [96][104] bf16 (19968) | sD 96x132 bf16.
#define A_SZ 71936

__global__ __launch_bounds__(256)
void k_ln1_qkv(const float* __restrict__ x, const __nv_bfloat16* __restrict__ wq,
               const float* __restrict__ lnw, const float* __restrict__ lnb,
               __nv_bfloat16* __restrict__ qkv) {
    extern __shared__ __align__(16) char dsm[];
    const uint32_t sAa = smem_u32(dsm);
    const uint32_t sWa = sAa + 26624;
    __nv_bfloat16* sDb = (__nv_bfloat16*)(dsm + 46592);
    uint32_t* sAw = (uint32_t*)dsm;

    const int tid = threadIdx.x;
    const int m0 = blockIdx.x * 128;

    // ---- LN1 from planar x ----
    {
        int px = tid >> 1, half = tid & 1;
        int bb = m0 >> 14, sp = (m0 & 16383) + px;
        const float* xp = x + ((size_t)bb * 96 + half * 48) * HW + sp;
        float v[48];
        float sum = 0.f, sq = 0.f;
#pragma unroll
        for (int i = 0; i < 48; i++) {
            v[i] = __ldg(xp + (size_t)i * HW);
            sum += v[i];
            sq = fmaf(v[i], v[i], sq);
        }
        sum += __shfl_xor_sync(0xffffffffu, sum, 1);
        sq  += __shfl_xor_sync(0xffffffffu, sq, 1);
        float mu = sum * (1.f / 96.f);
        float rs = rsqrtf(sq * (1.f / 96.f) - mu * mu + 1e-5f);
#pragma unroll
        for (int i = 0; i < 24; i++) {
            int c = half * 48 + 2 * i;
            float a0 = (v[2 * i] - mu) * rs * __ldg(lnw + c) + __ldg(lnb + c);
            float a1 = (v[2 * i + 1] - mu) * rs * __ldg(lnw + c + 1)
                     + __ldg(lnb + c + 1);
            sAw[px * 52 + half * 24 + i] = packbf(a0, a1);
        }
    }
    __syncthreads();

    // ---- GEMM over 3 N-blocks ----
    const int lane = tid & 31;
    const int wid = tid >> 5;
    const int wr = wid >> 2, wc = wid & 3;
    const int g = lane >> 2, tig = lane & 3;

    uint32_t aAddr[4];
#pragma unroll
    for (int i = 0; i < 4; i++)
        aAddr[i] = sAa + (uint32_t)((wr * 64 + i * 16 + (lane & 15)) * 208
                                    + (lane >> 4) * 16);
    uint32_t bAddr[3];
#pragma unroll
    for (int j = 0; j < 3; j++)
        bAddr[j] = sWa + (uint32_t)((wc * 24 + j * 8 + g) * 208 + tig * 4);

#pragma unroll 1
    for (int nb = 0; nb < 3; nb++) {
        const __nv_bfloat16* Wb = wq + (size_t)nb * 96 * 96;
        for (int u = tid; u < 1152; u += 256) {
            int rr = u / 12, cc = u - rr * 12;
            cpa16(sWa + (uint32_t)(rr * 208 + cc * 16), Wb + rr * 96 + cc * 8);
        }
        cp_commit(); cp_wait0();
        __syncthreads();

        float acc[4][3][4];
#pragma unroll
        for (int i = 0; i < 4; i++)
#pragma unroll
            for (int j = 0; j < 3; j++)
#pragma unroll
                for (int q = 0; q < 4; q++) acc[i][j][q] = 0.f;

#pragma unroll
        for (int ks = 0; ks < 6; ks++) {
            uint32_t a[4][4], b2[3][2];
#pragma unroll
            for (int i = 0; i < 4; i++)
                LDSM4(a[i][0], a[i][1], a[i][2], a[i][3],
                      aAddr[i] + (uint32_t)(ks * 32));
#pragma unroll
            for (int j = 0; j < 3; j++) {
                b2[j][0] = lds32(bAddr[j] + (uint32_t)(ks * 32));
                b2[j][1] = lds32(bAddr[j] + (uint32_t)(ks * 32 + 16));
            }
#pragma unroll
            for (int i = 0; i < 4; i++)
#pragma unroll
                for (int j = 0; j < 3; j++)
                    mma16(acc[i][j], a[i], b2[j]);
        }

        // stage D as bf16 [col][132 rows]
#pragma unroll
        for (int i = 0; i < 4; i++)
#pragma unroll
            for (int j = 0; j < 3; j++) {
                int row = wr * 64 + i * 16 + g;
                int col = wc * 24 + j * 8 + 2 * tig;
                sDb[col * 132 + row]           = __float2bfloat16_rn(acc[i][j][0]);
                sDb[(col + 1) * 132 + row]     = __float2bfloat16_rn(acc[i][j][1]);
                sDb[col * 132 + row + 8]       = __float2bfloat16_rn(acc[i][j][2]);
                sDb[(col + 1) * 132 + row + 8] = __float2bfloat16_rn(acc[i][j][3]);
            }
        __syncthreads();

        const uint32_t* sDu = (const uint32_t*)sDb;
#pragma unroll
        for (int u = tid; u < 6144; u += 256) {
            int col = u >> 6, q = u & 63;
            ((uint32_t*)(qkv + (((size_t)(nb * 96 + col)) << 17) + m0))[q]
                = sDu[col * 66 + q];
        }
        __syncthreads();
    }
}

// ================= dilated attention (packed ch-pairs) =================
// SMEM u32 arrays: k [cp:8][row:8][144] at 0, v same at +9216. u32 = 2 bf16 ch.
__global__ __launch_bounds__(256)
void attn_kernel(const __nv_bfloat16* __restrict__ qkvp,
                 __nv_bfloat16* __restrict__ attn) {
    extern __shared__ __align__(16) uint32_t sm32[];
    const int tid = threadIdx.x;
    const int b = blockIdx.x >> 6;
    const int h0 = (blockIdx.x & 63) << 1;
    const int hd = blockIdx.y;
    const int grp = hd >> 1;
    const int dil = grp + 1;
    const int cb = grp * 32 + (hd & 1) * 16;
    const int nr = 2 + 2 * dil;

    {
        float4 z = make_float4(0.f, 0.f, 0.f, 0.f);
        float4* smv = (float4*)sm32;
#pragma unroll
        for (int i = 0; i < 18; i++) smv[i * 256 + tid] = z;
    }
    __syncthreads();

    const int baseh = h0 - dil;
    for (int u = tid; u < (nr << 7); u += 256) {
        int q8 = u & 15, seg = u >> 4;
        int cp = seg / nr, row = seg - cp * nr;
        int hr = baseh + row;
        if ((unsigned)hr < 128u) {
            size_t gofs = ((size_t)b << 14) + (hr << 7) + q8 * 8;
            uint4 k0 = *(const uint4*)(qkvp + (((size_t)(96 + cb + 2 * cp)) << 17) + gofs);
            uint4 k1 = *(const uint4*)(qkvp + (((size_t)(97 + cb + 2 * cp)) << 17) + gofs);
            uint4 v0 = *(const uint4*)(qkvp + (((size_t)(192 + cb + 2 * cp)) << 17) + gofs);
            uint4 v1 = *(const uint4*)(qkvp + (((size_t)(193 + cb + 2 * cp)) << 17) + gofs);
            int di = cp * 1152 + row * 144 + 8 + q8 * 8;
            uint4 o;
            o.x = __byte_perm(k0.x, k1.x, 0x5410); o.y = __byte_perm(k0.x, k1.x, 0x7632);
            o.z = __byte_perm(k0.y, k1.y, 0x5410); o.w = __byte_perm(k0.y, k1.y, 0x7632);
            *(uint4*)(sm32 + di) = o;
            o.x = __byte_perm(k0.z, k1.z, 0x5410); o.y = __byte_perm(k0.z, k1.z, 0x7632);
            o.z = __byte_perm(k0.w, k1.w, 0x5410); o.w = __byte_perm(k0.w, k1.w, 0x7632);
            *(uint4*)(sm32 + di + 4) = o;
            o.x = __byte_perm(v0.x, v1.x, 0x5410); o.y = __byte_perm(v0.x, v1.x, 0x7632);
            o.z = __byte_perm(v0.y, v1.y, 0x5410); o.w = __byte_perm(v0.y, v1.y, 0x7632);
            *(uint4*)(sm32 + di + 9216) = o;
            o.x = __byte_perm(v0.z, v1.z, 0x5410); o.y = __byte_perm(v0.z, v1.z, 0x7632);
            o.z = __byte_perm(v0.w, v1.w, 0x5410); o.w = __byte_perm(v0.w, v1.w, 0x7632);
            *(uint4*)(sm32 + di + 9220) = o;
        }
    }
    __syncthreads();

    const int r = tid >> 7, w = tid & 127;
    const size_t p = ((size_t)b << 14) + ((size_t)(h0 + r) << 7) + w;

    float ql[8], qh[8];
#pragma unroll
    for (int cp = 0; cp < 8; cp++) {
        ql[cp] = __bfloat162float(qkvp[(((size_t)(cb + 2 * cp)) << 17) + p]);
        qh[cp] = __bfloat162float(qkvp[(((size_t)(cb + 2 * cp + 1)) << 17) + p]);
    }

    float sc[9];
#pragma unroll
    for (int i = 0; i < 3; i++)
#pragma unroll
        for (int j = 0; j < 3; j++) {
            int base = (r + i * dil) * 144 + (8 + w + (j - 1) * dil);
            float d = 0.f;
#pragma unroll
            for (int cp = 0; cp < 8; cp++) {
                uint32_t u = sm32[cp * 1152 + base];
                d = fmaf(ql[cp], bflo(u), d);
                d = fmaf(qh[cp], bfhi(u), d);
            }
            sc[i * 3 + j] = d * 0.25f;          // SCALE = 16^-0.5
        }

    float mx = sc[0];
#pragma unroll
    for (int k = 1; k < 9; k++) mx = fmaxf(mx, sc[k]);
    float ssum = 0.f;
#pragma unroll
    for (int k = 0; k < 9; k++) { sc[k] = __expf(sc[k] - mx); ssum += sc[k]; }
    float inv = 1.f / ssum;

    float ol[8], oh[8];
#pragma unroll
    for (int cp = 0; cp < 8; cp++) { ol[cp] = 0.f; oh[cp] = 0.f; }
#pragma unroll
    for (int i = 0; i < 3; i++)
#pragma unroll
        for (int j = 0; j < 3; j++) {
            float wgt = sc[i * 3 + j] * inv;
            int base = 9216 + (r + i * dil) * 144 + (8 + w + (j - 1) * dil);
#pragma unroll
            for (int cp = 0; cp < 8; cp++) {
                uint32_t u = sm32[cp * 1152 + base];
                ol[cp] = fmaf(wgt, bflo(u), ol[cp]);
                oh[cp] = fmaf(wgt, bfhi(u), oh[cp]);
            }
        }

    __syncthreads();
#pragma unroll
    for (int cp = 0; cp < 8; cp++)
        sm32[tid * 17 + cp] = packbf(ol[cp], oh[cp]);
    __syncthreads();
    const size_t p0 = ((size_t)b << 14) + ((size_t)h0 << 7);
#pragma unroll
    for (int u = tid; u < 2048; u += 256) {
        int row = u >> 3, wq = u & 7;
        ((uint32_t*)(attn + (p0 + row) * 96 + cb))[wq] = sm32[row * 17 + wq];
    }
}

// ================= proj GEMM (bf16 HMMA, EPI: +bias +planar res -> fp32) ====
#define P_SZ 99328
__global__ __launch_bounds__(256)
void k_proj(const __nv_bfloat16* __restrict__ A, const __nv_bfloat16* __restrict__ W,
            const float* __restrict__ bias, const float* __restrict__ res,
            float* __restrict__ outf) {
    extern __shared__ __align__(16) char dsm[];
    const uint32_t sAa = smem_u32(dsm);
    const uint32_t sWa = sAa + 26624;

    const int tid = threadIdx.x;
    const int lane = tid & 31;
    const int wid = tid >> 5;
    const int wr = wid >> 2, wc = wid & 3;
    const int g = lane >> 2, tig = lane & 3;
    const int m0 = blockIdx.x * 128;

    float acc[4][3][4];
#pragma unroll
    for (int i = 0; i < 4; i++)
#pragma unroll
        for (int j = 0; j < 3; j++)
#pragma unroll
            for (int q = 0; q < 4; q++) acc[i][j][q] = 0.f;

    uint32_t aAddr[4];
#pragma unroll
    for (int i = 0; i < 4; i++)
        aAddr[i] = sAa + (uint32_t)((wr * 64 + i * 16 + (lane & 15)) * 208
                                    + (lane >> 4) * 16);
    uint32_t bAddr[3];
#pragma unroll
    for (int j = 0; j < 3; j++)
        bAddr[j] = sWa + (uint32_t)((wc * 24 + j * 8 + g) * 208 + tig * 4);

    const __nv_bfloat16* Ab = A + (size_t)m0 * 96;
#pragma unroll
    for (int it = 0; it < 6; it++) {
        int u = it * 256 + tid;
        int rr = u / 12, cc = u - rr * 12;
        cpa16(sAa + (uint32_t)(rr * 208 + cc * 16), Ab + (size_t)rr * 96 + cc * 8);
    }
    for (int u = tid; u < 1152; u += 256) {
        int rr = u / 12, cc = u - rr * 12;
        cpa16(sWa + (uint32_t)(rr * 208 + cc * 16), W + rr * 96 + cc * 8);
    }
    cp_commit(); cp_wait0();
    __syncthreads();

#pragma unroll
    for (int ks = 0; ks < 6; ks++) {
        uint32_t a[4][4], b2[3][2];
#pragma unroll
        for (int i = 0; i < 4; i++)
            LDSM4(a[i][0], a[i][1], a[i][2], a[i][3],
                  aAddr[i] + (uint32_t)(ks * 32));
#pragma unroll
        for (int j = 0; j < 3; j++) {
            b2[j][0] = lds32(bAddr[j] + (uint32_t)(ks * 32));
            b2[j][1] = lds32(bAddr[j] + (uint32_t)(ks * 32 + 16));
        }
#pragma unroll
        for (int i = 0; i < 4; i++)
#pragma unroll
            for (int j = 0; j < 3; j++)
                mma16(acc[i][j], a[i], b2[j]);
    }
    __syncthreads();

    float* stgD = (float*)dsm;                     // 128 x 97 fp32
    float* stgR = (float*)(dsm + 49664);           // 128 x 97 fp32
#pragma unroll
    for (int i = 0; i < 4; i++)
#pragma unroll
        for (int j = 0; j < 3; j++) {
            int row = wr * 64 + i * 16 + g;
            int col = wc * 24 + j * 8 + 2 * tig;
            stgD[row * 97 + col]           = acc[i][j][0];
            stgD[row * 97 + col + 1]       = acc[i][j][1];
            stgD[(row + 8) * 97 + col]     = acc[i][j][2];
            stgD[(row + 8) * 97 + col + 1] = acc[i][j][3];
        }
    {
        int bb = m0 >> 14, ss0 = m0 & 16383;
#pragma unroll 4
        for (int u = tid; u < 12288; u += 256) {
            int col = u >> 7, rr = u & 127;
            stgR[rr * 97 + col] =
                res[(((size_t)bb * 96 + col) << 14) + ss0 + rr];
        }
    }
    __syncthreads();
#pragma unroll 4
    for (int u = tid; u < 12288; u += 256) {
        int rr = u / 96, col = u - rr * 96;
        outf[(size_t)(m0 + rr) * 96 + col] =
            stgD[rr * 97 + col] + __ldg(bias + col) + stgR[rr * 97 + col];
    }
}

// ================= fused LN2 + fc1 + GELU + fc2 + residual -> planar =========
// SMEM: sX [128][104] fp32 @0 (53248) | sH [128][392] bf16 @53248 (100352)
//       | sA [128][104] bf16 @153600 (26624) | sW [96][104] bf16 @180224 (19968)
// epilogue: sD 48x132 fp32 reuses sA region.  total 200192.
#define M_SZ 200192

__global__ __launch_bounds__(256)
void k_mlp(const float* __restrict__ x1,
           const __nv_bfloat16* __restrict__ w1, const float* __restrict__ b1,
           const __nv_bfloat16* __restrict__ w2, const float* __restrict__ b2,
           const float* __restrict__ lnw, const float* __restrict__ lnb,
           float* __restrict__ out) {
    extern __shared__ __align__(16) char dsm[];
    float* sXf = (float*)dsm;
    const uint32_t sHa = smem_u32(dsm) + 53248;
    const uint32_t sAa = smem_u32(dsm) + 153600;
    const uint32_t sWa = smem_u32(dsm) + 180224;
    uint32_t* sAw = (uint32_t*)(dsm + 153600);
    __nv_bfloat16* sHb = (__nv_bfloat16*)(dsm + 53248);
    float* sDf = (float*)(dsm + 153600);

    const int tid = threadIdx.x;
    const int m0 = blockIdx.x * 128;

    // ---- load x1 tile ----
    {
        const float* xb = x1 + (size_t)m0 * 96;
        uint32_t sXa = smem_u32(dsm);
#pragma unroll
        for (int it = 0; it < 12; it++) {          // 3072 x 16B
            int u = it * 256 + tid;
            int rr = u / 24, cc = u - rr * 24;
            cpa16(sXa + (uint32_t)(rr * 416 + cc * 16), xb + rr * 96 + cc * 4);
        }
        cp_commit(); cp_wait0();
        __syncthreads();
    }

    // ---- LN2 ----
    {
        int px = tid >> 1, half = tid & 1;
        const float* xr = sXf + px * 104 + half * 48;
        float sum = 0.f, sq = 0.f;
#pragma unroll
        for (int i = 0; i < 48; i++) {
            float v = xr[i];
            sum += v;
            sq = fmaf(v, v, sq);
        }
        sum += __shfl_xor_sync(0xffffffffu, sum, 1);
        sq  += __shfl_xor_sync(0xffffffffu, sq, 1);
        float mu = sum * (1.f / 96.f);
        float rs = rsqrtf(sq * (1.f / 96.f) - mu * mu + 1e-5f);
#pragma unroll
        for (int i = 0; i < 24; i++) {
            int c = half * 48 + 2 * i;
            float a0 = (xr[2 * i] - mu) * rs * __ldg(lnw + c) + __ldg(lnb + c);
            float a1 = (xr[2 * i + 1] - mu) * rs * __ldg(lnw + c + 1)
                     + __ldg(lnb + c + 1);
            sAw[px * 52 + half * 24 + i] = packbf(a0, a1);
        }
    }
    __syncthreads();

    const int lane = tid & 31;
    const int wid = tid >> 5;
    const int wr = wid >> 2, wc = wid & 3;
    const int g = lane >> 2, tig = lane & 3;

    uint32_t aAddr[4], hAddr[4], bAddr[3];
#pragma unroll
    for (int i = 0; i < 4; i++) {
        aAddr[i] = sAa + (uint32_t)((wr * 64 + i * 16 + (lane & 15)) * 208
                                    + (lane >> 4) * 16);
        hAddr[i] = sHa + (uint32_t)((wr * 64 + i * 16 + (lane & 15)) * 784
                                    + (lane >> 4) * 16);
    }
#pragma unroll
    for (int j = 0; j < 3; j++)
        bAddr[j] = sWa + (uint32_t)((wc * 24 + j * 8 + g) * 208 + tig * 4);

    // ---- fc1 + GELU -> sH ----
#pragma unroll 1
    for (int nb = 0; nb < 4; nb++) {
        const __nv_bfloat16* Wb = w1 + (size_t)nb * 96 * 96;
        for (int u = tid; u < 1152; u += 256) {
            int rr = u / 12, cc = u - rr * 12;
            cpa16(sWa + (uint32_t)(rr * 208 + cc * 16), Wb + rr * 96 + cc * 8);
        }
        cp_commit(); cp_wait0();
        __syncthreads();

        float acc[4][3][4];
#pragma unroll
        for (int i = 0; i < 4; i++)
#pragma unroll
            for (int j = 0; j < 3; j++)
#pragma unroll
                for (int q = 0; q < 4; q++) acc[i][j][q] = 0.f;

#pragma unroll
        for (int ks = 0; ks < 6; ks++) {
            uint32_t a[4][4], b2[3][2];
#pragma unroll
            for (int i = 0; i < 4; i++)
                LDSM4(a[i][0], a[i][1], a[i][2], a[i][3],
                      aAddr[i] + (uint32_t)(ks * 32));
#pragma unroll
            for (int j = 0; j < 3; j++) {
                b2[j][0] = lds32(bAddr[j] + (uint32_t)(ks * 32));
                b2[j][1] = lds32(bAddr[j] + (uint32_t)(ks * 32 + 16));
            }
#pragma unroll
            for (int i = 0; i < 4; i++)
#pragma unroll
                for (int j = 0; j < 3; j++)
                    mma16(acc[i][j], a[i], b2[j]);
        }

        // GELU + bias, pack 2 cols -> sH
        uint32_t* sHu = (uint32_t*)sHb;
#pragma unroll
        for (int i = 0; i < 4; i++)
#pragma unroll
            for (int j = 0; j < 3; j++) {
                int row = wr * 64 + i * 16 + g;
                int col = wc * 24 + j * 8 + 2 * tig;
                float bi0 = __ldg(b1 + nb * 96 + col);
                float bi1 = __ldg(b1 + nb * 96 + col + 1);
                float t0 = acc[i][j][0] + bi0;
                float t1 = acc[i][j][1] + bi1;
                float t2 = acc[i][j][2] + bi0;
                float t3 = acc[i][j][3] + bi1;
                t0 = 0.5f * t0 * (1.f + erff(t0 * 0.70710678118654752f));
                t1 = 0.5f * t1 * (1.f + erff(t1 * 0.70710678118654752f));
                t2 = 0.5f * t2 * (1.f + erff(t2 * 0.70710678118654752f));
                t3 = 0.5f * t3 * (1.f + erff(t3 * 0.70710678118654752f));
                sHu[(row * 392 + nb * 96 + col) >> 1]       = packbf(t0, t1);
                sHu[((row + 8) * 392 + nb * 96 + col) >> 1] = packbf(t2, t3);
            }
        __syncthreads();
    }

    // ---- fc2: K=384 in 4 chunks from sH ----
    float acc2[4][3][4];
#pragma unroll
    for (int i = 0; i < 4; i++)
#pragma unroll
        for (int j = 0; j < 3; j++)
#pragma unroll
            for (int q = 0; q < 4; q++) acc2[i][j][q] = 0.f;

#pragma unroll 1
    for (int kc = 0; kc < 4; kc++) {
        for (int u = tid; u < 1152; u += 256) {
            int rr = u / 12, cc = u - rr * 12;
            cpa16(sWa + (uint32_t)(rr * 208 + cc * 16),
                  w2 + rr * 384 + kc * 96 + cc * 8);
        }
        cp_commit(); cp_wait0();
        __syncthreads();

#pragma unroll
        for (int ks = 0; ks < 6; ks++) {
            uint32_t a[4][4], b2[3][2];
#pragma unroll
            for (int i = 0; i < 4; i++)
                LDSM4(a[i][0], a[i][1], a[i][2], a[i][3],
                      hAddr[i] + (uint32_t)(kc * 192 + ks * 32));
#pragma unroll
            for (int j = 0; j < 3; j++) {
                b2[j][0] = lds32(bAddr[j] + (uint32_t)(ks * 32));
                b2[j][1] = lds32(bAddr[j] + (uint32_t)(ks * 32 + 16));
            }
#pragma unroll
            for (int i = 0; i < 4; i++)
#pragma unroll
                for (int j = 0; j < 3; j++)
                    mma16(acc2[i][j], a[i], b2[j]);
        }
        __syncthreads();
    }

    // ---- epilogue: 2 passes of 48 cols, +bias +residual, planar fp32 ----
    const int bb = m0 >> 14, ss0 = m0 & 16383;
#pragma unroll 1
    for (int p = 0; p < 2; p++) {
        if ((wc >> 1) == p) {
#pragma unroll
            for (int i = 0; i < 4; i++)
#pragma unroll
                for (int j = 0; j < 3; j++) {
                    int row = wr * 64 + i * 16 + g;
                    int chl = (wc & 1) * 24 + j * 8 + 2 * tig;
                    sDf[chl * 132 + row]           = acc2[i][j][0];
                    sDf[(chl + 1) * 132 + row]     = acc2[i][j][1];
                    sDf[chl * 132 + row + 8]       = acc2[i][j][2];
                    sDf[(chl + 1) * 132 + row + 8] = acc2[i][j][3];
                }
        }
        __syncthreads();
#pragma unroll 4
        for (int u = tid; u < 6144; u += 256) {
            int px = u & 127, chl = u >> 7;
            int ch = p * 48 + chl;
            float val = sDf[chl * 132 + px] + __ldg(b2 + ch)
                      + sXf[px * 104 + ch];
            out[(((size_t)bb * 96 + ch) << 14) + ss0 + px] = val;
        }
        __syncthreads();
    }
}

// ---------------- launch ----------------
extern "C" void kernel_launch(void* const* d_in, const int* in_sizes, int n_in,
                              void* d_out, int out_size) {
    (void)in_sizes; (void)n_in; (void)out_size;
    const float* x      = (const float*)d_in[0];
    const float* qkv_w  = (const float*)d_in[1];
    const float* proj_w = (const float*)d_in[2];
    const float* proj_b = (const float*)d_in[3];
    const float* ln1w   = (const float*)d_in[4];
    const float* ln1b   = (const float*)d_in[5];
    const float* ln2w   = (const float*)d_in[6];
    const float* ln2b   = (const float*)d_in[7];
    const float* fc1w   = (const float*)d_in[8];
    const float* fc1b   = (const float*)d_in[9];
    const float* fc2w   = (const float*)d_in[10];
    const float* fc2b   = (const float*)d_in[11];
    float* out = (float*)d_out;

    cudaFuncSetAttribute(k_ln1_qkv,
                         cudaFuncAttributeMaxDynamicSharedMemorySize, A_SZ);
    cudaFuncSetAttribute(attn_kernel,
                         cudaFuncAttributeMaxDynamicSharedMemorySize, 73728);
    cudaFuncSetAttribute(k_proj,
                         cudaFuncAttributeMaxDynamicSharedMemorySize, P_SZ);
    cudaFuncSetAttribute(k_mlp,
                         cudaFuncAttributeMaxDynamicSharedMemorySize, M_SZ);

    __nv_bfloat16 *pqkv, *pattn, *pwb;
    float *px1;
    cudaGetSymbolAddress((void**)&pqkv, g_qkv);
    cudaGetSymbolAddress((void**)&pattn, g_attn);
    cudaGetSymbolAddress((void**)&px1, g_x1);
    cudaGetSymbolAddress((void**)&pwb, g_wb);

    round_w<<<432, 256>>>(qkv_w, proj_w, fc1w, fc2w);
    k_ln1_qkv<<<PTOT / 128, 256, A_SZ>>>(x, pwb, ln1w, ln1b, pqkv);
    attn_kernel<<<dim3(512, 6), 256, 73728>>>(pqkv, pattn);
    k_proj<<<PTOT / 128, 256, P_SZ>>>(pattn, pwb + 27648, proj_b, x, px1);
    k_mlp<<<PTOT / 128, 256, M_SZ>>>(px1, pwb + 36864, fc1b,
                                     pwb + 73728, fc2b, ln2w, ln2b, out);
}

// round 6
// speedup vs baseline: 4.1862x; 1.1350x over previous
#include <cuda_runtime.h>
#include <cuda_bf16.h>
#include <cstdint>
#include <cstddef>

// ---------------- problem constants ----------------
#define HW    16384            // 128*128
#define PTOT  131072           // 8*128*128 = 1<<17

// ---------------- scratch (device globals; no allocation) ----------------
__device__ __align__(16) __nv_bfloat16 g_qkv [(size_t)PTOT * 288];  // PLANAR [288][P]
__device__ __align__(16) __nv_bfloat16 g_attn[(size_t)PTOT * 96];   // row-major P x 96
__device__ __align__(16) __nv_bfloat16 g_wb  [110592];              // bf16 weights

// ---------------- helpers ----------------
__device__ __forceinline__ uint32_t smem_u32(const void* p) {
    uint32_t a;
    asm("{ .reg .u64 t; cvta.to.shared.u64 t, %1; cvt.u32.u64 %0, t; }"
        : "=r"(a) : "l"(p));
    return a;
}
__device__ __forceinline__ void cpa16(uint32_t dst, const void* src) {
    asm volatile("cp.async.cg.shared.global [%0], [%1], 16;"
                 :: "r"(dst), "l"(src));
}
__device__ __forceinline__ void cp_commit() {
    asm volatile("cp.async.commit_group;" ::: "memory");
}
__device__ __forceinline__ void cp_wait0() {
    asm volatile("cp.async.wait_group 0;" ::: "memory");
}
#define LDSM4(r0, r1, r2, r3, addr) \
    asm volatile("ldmatrix.sync.aligned.m8n8.x4.shared.b16 {%0,%1,%2,%3}, [%4];" \
                 : "=r"(r0), "=r"(r1), "=r"(r2), "=r"(r3) : "r"(addr))
__device__ __forceinline__ uint32_t lds32(uint32_t addr) {
    uint32_t v;
    asm volatile("ld.shared.b32 %0, [%1];" : "=r"(v) : "r"(addr));
    return v;
}
__device__ __forceinline__ void mma16(float* d, const uint32_t* a,
                                      const uint32_t* b) {
    asm volatile(
        "mma.sync.aligned.m16n8k16.row.col.f32.bf16.bf16.f32 "
        "{%0,%1,%2,%3}, {%4,%5,%6,%7}, {%8,%9}, {%0,%1,%2,%3};"
        : "+f"(d[0]), "+f"(d[1]), "+f"(d[2]), "+f"(d[3])
        : "r"(a[0]), "r"(a[1]), "r"(a[2]), "r"(a[3]), "r"(b[0]), "r"(b[1]));
}
__device__ __forceinline__ uint32_t packbf(float a, float b) {
    __nv_bfloat162 p = __floats2bfloat162_rn(a, b);
    return *(uint32_t*)&p;
}
__device__ __forceinline__ float bflo(uint32_t u) {
    return __uint_as_float(u << 16);
}
__device__ __forceinline__ float bfhi(uint32_t u) {
    return __uint_as_float(u & 0xffff0000u);
}

// ---------------- weight conversion fp32 -> bf16 ----------------
__global__ __launch_bounds__(256)
void round_w(const float* __restrict__ qkv, const float* __restrict__ proj,
             const float* __restrict__ fc1, const float* __restrict__ fc2) {
    int i = blockIdx.x * 256 + threadIdx.x;
    float v;
    if (i < 27648)        v = qkv[i];
    else if (i < 36864)   v = proj[i - 27648];
    else if (i < 73728)   v = fc1[i - 36864];
    else                  v = fc2[i - 73728];
    g_wb[i] = __float2bfloat16_rn(v);
}

// ================= fused LN1 + qkv GEMM (256 thr) =================
// SMEM region R @0 (65280 B):
//   phase1: sXp fp32 [96][132] (channel-major x tile) = 50688
//   phase2: sW0 @0 (19968) | sW1 @19968 (19968) | sD bf16 [96][132] @39936 (25344)
// sA bf16 [128][104] @65280 (26624).  Total 91904.
#define A_SZ 91904

__global__ __launch_bounds__(256)
void k_ln1_qkv(const float* __restrict__ x, const __nv_bfloat16* __restrict__ wq,
               const float* __restrict__ lnw, const float* __restrict__ lnb,
               __nv_bfloat16* __restrict__ qkv) {
    extern __shared__ __align__(16) char dsm[];
    const uint32_t sb = smem_u32(dsm);
    float* sXp = (float*)dsm;                       // stride 132
    __nv_bfloat16* sDb = (__nv_bfloat16*)(dsm + 39936);
    uint32_t* sAw = (uint32_t*)(dsm + 65280);
    const uint32_t sAa = sb + 65280;

    const int tid = threadIdx.x;
    const int m0 = blockIdx.x * 128;
    const int bb = m0 >> 14, ss0 = m0 & 16383;

    // ---- stage x (planar) channel-major into sXp ----
#pragma unroll
    for (int it = 0; it < 12; it++) {               // 3072 x 16B
        int u = it * 256 + tid;
        int c = u >> 5, q = u & 31;
        cpa16(sb + (uint32_t)(c * 528 + q * 16),
              x + (((size_t)(bb * 96 + c)) << 14) + ss0 + q * 4);
    }
    cp_commit(); cp_wait0();
    __syncthreads();

    // ---- LN1: one thread per pixel ----
    if (tid < 128) {
        const int px = tid;
        float sum = 0.f, sq = 0.f;
#pragma unroll
        for (int c = 0; c < 96; c++) {
            float v = sXp[c * 132 + px];
            sum += v;
            sq = fmaf(v, v, sq);
        }
        float mu = sum * (1.f / 96.f);
        float rs = rsqrtf(sq * (1.f / 96.f) - mu * mu + 1e-5f);
#pragma unroll
        for (int i = 0; i < 48; i++) {
            float a0 = (sXp[(2 * i) * 132 + px] - mu) * rs * __ldg(lnw + 2 * i)
                     + __ldg(lnb + 2 * i);
            float a1 = (sXp[(2 * i + 1) * 132 + px] - mu) * rs
                     * __ldg(lnw + 2 * i + 1) + __ldg(lnb + 2 * i + 1);
            sAw[px * 52 + i] = packbf(a0, a1);
        }
    }
    __syncthreads();                                // sXp dead; sW region live

    // ---- GEMM over 3 N-blocks, double-buffered weights ----
    const int lane = tid & 31;
    const int wid = tid >> 5;
    const int wr = wid >> 2, wc = wid & 3;
    const int g = lane >> 2, tig = lane & 3;

    uint32_t aAddr[4];
#pragma unroll
    for (int i = 0; i < 4; i++)
        aAddr[i] = sAa + (uint32_t)((wr * 64 + i * 16 + (lane & 15)) * 208
                                    + (lane >> 4) * 16);
    uint32_t bRel[3];
#pragma unroll
    for (int j = 0; j < 3; j++)
        bRel[j] = (uint32_t)((wc * 24 + j * 8 + g) * 208 + tig * 4);

    // preload nb0 weights into buf0
    for (int u = tid; u < 1152; u += 256) {
        int rr = u / 12, cc = u - rr * 12;
        cpa16(sb + (uint32_t)(rr * 208 + cc * 16), wq + rr * 96 + cc * 8);
    }
    cp_commit();

#pragma unroll 1
    for (int nb = 0; nb < 3; nb++) {
        cp_wait0();
        __syncthreads();
        if (nb < 2) {                                // prefetch nb+1
            const __nv_bfloat16* Wn = wq + (size_t)(nb + 1) * 9216;
            uint32_t dst = sb + (uint32_t)(((nb + 1) & 1) * 19968);
            for (int u = tid; u < 1152; u += 256) {
                int rr = u / 12, cc = u - rr * 12;
                cpa16(dst + (uint32_t)(rr * 208 + cc * 16), Wn + rr * 96 + cc * 8);
            }
            cp_commit();
        }
        const uint32_t wb = sb + (uint32_t)((nb & 1) * 19968);

        float acc[4][3][4];
#pragma unroll
        for (int i = 0; i < 4; i++)
#pragma unroll
            for (int j = 0; j < 3; j++)
#pragma unroll
                for (int q = 0; q < 4; q++) acc[i][j][q] = 0.f;

#pragma unroll
        for (int ks = 0; ks < 6; ks++) {
            uint32_t a[4][4], b2[3][2];
#pragma unroll
            for (int i = 0; i < 4; i++)
                LDSM4(a[i][0], a[i][1], a[i][2], a[i][3],
                      aAddr[i] + (uint32_t)(ks * 32));
#pragma unroll
            for (int j = 0; j < 3; j++) {
                b2[j][0] = lds32(wb + bRel[j] + (uint32_t)(ks * 32));
                b2[j][1] = lds32(wb + bRel[j] + (uint32_t)(ks * 32 + 16));
            }
#pragma unroll
            for (int i = 0; i < 4; i++)
#pragma unroll
                for (int j = 0; j < 3; j++)
                    mma16(acc[i][j], a[i], b2[j]);
        }

        // stage D bf16 [col][132]
#pragma unroll
        for (int i = 0; i < 4; i++)
#pragma unroll
            for (int j = 0; j < 3; j++) {
                int row = wr * 64 + i * 16 + g;
                int col = wc * 24 + j * 8 + 2 * tig;
                sDb[col * 132 + row]           = __float2bfloat16_rn(acc[i][j][0]);
                sDb[(col + 1) * 132 + row]     = __float2bfloat16_rn(acc[i][j][1]);
                sDb[col * 132 + row + 8]       = __float2bfloat16_rn(acc[i][j][2]);
                sDb[(col + 1) * 132 + row + 8] = __float2bfloat16_rn(acc[i][j][3]);
            }
        __syncthreads();
        const uint32_t* sDu = (const uint32_t*)sDb;
#pragma unroll
        for (int u = tid; u < 6144; u += 256) {
            int col = u >> 6, q = u & 63;
            ((uint32_t*)(qkv + (((size_t)(nb * 96 + col)) << 17) + m0))[q]
                = sDu[col * 66 + q];
        }
        __syncthreads();
    }
}

// ================= dilated attention (packed ch-pairs) =================
__global__ __launch_bounds__(256)
void attn_kernel(const __nv_bfloat16* __restrict__ qkvp,
                 __nv_bfloat16* __restrict__ attn) {
    extern __shared__ __align__(16) uint32_t sm32[];
    const int tid = threadIdx.x;
    const int b = blockIdx.x >> 6;
    const int h0 = (blockIdx.x & 63) << 1;
    const int hd = blockIdx.y;
    const int grp = hd >> 1;
    const int dil = grp + 1;
    const int cb = grp * 32 + (hd & 1) * 16;
    const int nr = 2 + 2 * dil;

    {
        float4 z = make_float4(0.f, 0.f, 0.f, 0.f);
        float4* smv = (float4*)sm32;
#pragma unroll
        for (int i = 0; i < 18; i++) smv[i * 256 + tid] = z;
    }
    __syncthreads();

    const int baseh = h0 - dil;
    for (int u = tid; u < (nr << 7); u += 256) {
        int q8 = u & 15, seg = u >> 4;
        int cp = seg / nr, row = seg - cp * nr;
        int hr = baseh + row;
        if ((unsigned)hr < 128u) {
            size_t gofs = ((size_t)b << 14) + (hr << 7) + q8 * 8;
            uint4 k0 = *(const uint4*)(qkvp + (((size_t)(96 + cb + 2 * cp)) << 17) + gofs);
            uint4 k1 = *(const uint4*)(qkvp + (((size_t)(97 + cb + 2 * cp)) << 17) + gofs);
            uint4 v0 = *(const uint4*)(qkvp + (((size_t)(192 + cb + 2 * cp)) << 17) + gofs);
            uint4 v1 = *(const uint4*)(qkvp + (((size_t)(193 + cb + 2 * cp)) << 17) + gofs);
            int di = cp * 1152 + row * 144 + 8 + q8 * 8;
            uint4 o;
            o.x = __byte_perm(k0.x, k1.x, 0x5410); o.y = __byte_perm(k0.x, k1.x, 0x7632);
            o.z = __byte_perm(k0.y, k1.y, 0x5410); o.w = __byte_perm(k0.y, k1.y, 0x7632);
            *(uint4*)(sm32 + di) = o;
            o.x = __byte_perm(k0.z, k1.z, 0x5410); o.y = __byte_perm(k0.z, k1.z, 0x7632);
            o.z = __byte_perm(k0.w, k1.w, 0x5410); o.w = __byte_perm(k0.w, k1.w, 0x7632);
            *(uint4*)(sm32 + di + 4) = o;
            o.x = __byte_perm(v0.x, v1.x, 0x5410); o.y = __byte_perm(v0.x, v1.x, 0x7632);
            o.z = __byte_perm(v0.y, v1.y, 0x5410); o.w = __byte_perm(v0.y, v1.y, 0x7632);
            *(uint4*)(sm32 + di + 9216) = o;
            o.x = __byte_perm(v0.z, v1.z, 0x5410); o.y = __byte_perm(v0.z, v1.z, 0x7632);
            o.z = __byte_perm(v0.w, v1.w, 0x5410); o.w = __byte_perm(v0.w, v1.w, 0x7632);
            *(uint4*)(sm32 + di + 9220) = o;
        }
    }
    __syncthreads();

    const int r = tid >> 7, w = tid & 127;
    const size_t p = ((size_t)b << 14) + ((size_t)(h0 + r) << 7) + w;

    float ql[8], qh[8];
#pragma unroll
    for (int cp = 0; cp < 8; cp++) {
        ql[cp] = __bfloat162float(qkvp[(((size_t)(cb + 2 * cp)) << 17) + p]);
        qh[cp] = __bfloat162float(qkvp[(((size_t)(cb + 2 * cp + 1)) << 17) + p]);
    }

    float sc[9];
#pragma unroll
    for (int i = 0; i < 3; i++)
#pragma unroll
        for (int j = 0; j < 3; j++) {
            int base = (r + i * dil) * 144 + (8 + w + (j - 1) * dil);
            float d = 0.f;
#pragma unroll
            for (int cp = 0; cp < 8; cp++) {
                uint32_t u = sm32[cp * 1152 + base];
                d = fmaf(ql[cp], bflo(u), d);
                d = fmaf(qh[cp], bfhi(u), d);
            }
            sc[i * 3 + j] = d * 0.25f;
        }

    float mx = sc[0];
#pragma unroll
    for (int k = 1; k < 9; k++) mx = fmaxf(mx, sc[k]);
    float ssum = 0.f;
#pragma unroll
    for (int k = 0; k < 9; k++) { sc[k] = __expf(sc[k] - mx); ssum += sc[k]; }
    float inv = 1.f / ssum;

    float ol[8], oh[8];
#pragma unroll
    for (int cp = 0; cp < 8; cp++) { ol[cp] = 0.f; oh[cp] = 0.f; }
#pragma unroll
    for (int i = 0; i < 3; i++)
#pragma unroll
        for (int j = 0; j < 3; j++) {
            float wgt = sc[i * 3 + j] * inv;
            int base = 9216 + (r + i * dil) * 144 + (8 + w + (j - 1) * dil);
#pragma unroll
            for (int cp = 0; cp < 8; cp++) {
                uint32_t u = sm32[cp * 1152 + base];
                ol[cp] = fmaf(wgt, bflo(u), ol[cp]);
                oh[cp] = fmaf(wgt, bfhi(u), oh[cp]);
            }
        }

    __syncthreads();
#pragma unroll
    for (int cp = 0; cp < 8; cp++)
        sm32[tid * 17 + cp] = packbf(ol[cp], oh[cp]);
    __syncthreads();
    const size_t p0 = ((size_t)b << 14) + ((size_t)h0 << 7);
#pragma unroll
    for (int u = tid; u < 2048; u += 256) {
        int row = u >> 3, wq = u & 7;
        ((uint32_t*)(attn + (p0 + row) * 96 + cb))[wq] = sm32[row * 17 + wq];
    }
}

// ================= mega-fused proj + residual + LN2 + MLP (512 thr) =========
// x1 lives only in SMEM. SMEM map:
//   sX  fp32 [128][97]  @0       49664
//   sH  bf16 [128][392] @49664   100352  (also fp32 staging [128][97] in proj)
//   sA  bf16 [128][104] @150016  26624   (A tile; LN2 out; fp32 sD 48x132 epi)
//   sW  2 x [96][104]   @176640  39936
#define M_SZ 216576

__global__ __launch_bounds__(512)
void k_pm(const __nv_bfloat16* __restrict__ attn,
          const __nv_bfloat16* __restrict__ wp, const float* __restrict__ pb,
          const float* __restrict__ x,
          const __nv_bfloat16* __restrict__ w1, const float* __restrict__ b1,
          const __nv_bfloat16* __restrict__ w2, const float* __restrict__ b2,
          const float* __restrict__ lnw, const float* __restrict__ lnb,
          float* __restrict__ out) {
    extern __shared__ __align__(16) char dsm[];
    const uint32_t sb = smem_u32(dsm);
    float* sX = (float*)dsm;
    float* sHf = (float*)(dsm + 49664);
    uint32_t* sHu = (uint32_t*)(dsm + 49664);
    uint32_t* sAw = (uint32_t*)(dsm + 150016);
    float* sDf = (float*)(dsm + 150016);
    const uint32_t sHa = sb + 49664;
    const uint32_t sAa = sb + 150016;
    const uint32_t sWa = sb + 176640;

    const int tid = threadIdx.x;
    const int lane = tid & 31;
    const int wid = tid >> 5;                        // 0..15
    const int wr = wid >> 2, wc = wid & 3;           // 4x4 warps
    const int g = lane >> 2, tig = lane & 3;
    const int m0 = blockIdx.x * 128;
    const int bb = m0 >> 14, ss0 = m0 & 16383;

    uint32_t aAddr[2], hAddr[2], bRel[3];
#pragma unroll
    for (int i = 0; i < 2; i++) {
        int row = wr * 32 + i * 16 + (lane & 15);
        aAddr[i] = sAa + (uint32_t)(row * 208 + (lane >> 4) * 16);
        hAddr[i] = sHa + (uint32_t)(row * 784 + (lane >> 4) * 16);
    }
#pragma unroll
    for (int j = 0; j < 3; j++)
        bRel[j] = (uint32_t)((wc * 24 + j * 8 + g) * 208 + tig * 4);

    // ---- load attn tile + proj weights ----
    const __nv_bfloat16* Ab = attn + (size_t)m0 * 96;
#pragma unroll
    for (int it = 0; it < 3; it++) {                 // 1536 x 16B
        int u = it * 512 + tid;
        int rr = u / 12, cc = u - rr * 12;
        cpa16(sAa + (uint32_t)(rr * 208 + cc * 16), Ab + (size_t)rr * 96 + cc * 8);
    }
    for (int u = tid; u < 1152; u += 512) {
        int rr = u / 12, cc = u - rr * 12;
        cpa16(sWa + (uint32_t)(rr * 208 + cc * 16), wp + rr * 96 + cc * 8);
    }
    cp_commit(); cp_wait0();
    __syncthreads();

    // prefetch fc1 nb0 -> buf1 (overlaps proj mma)
    for (int u = tid; u < 1152; u += 512) {
        int rr = u / 12, cc = u - rr * 12;
        cpa16(sWa + 19968u + (uint32_t)(rr * 208 + cc * 16), w1 + rr * 96 + cc * 8);
    }
    cp_commit();

    // ---- proj mma ----
    float acc[2][3][4];
#pragma unroll
    for (int i = 0; i < 2; i++)
#pragma unroll
        for (int j = 0; j < 3; j++)
#pragma unroll
            for (int q = 0; q < 4; q++) acc[i][j][q] = 0.f;
#pragma unroll
    for (int ks = 0; ks < 6; ks++) {
        uint32_t a[2][4], b2[3][2];
#pragma unroll
        for (int i = 0; i < 2; i++)
            LDSM4(a[i][0], a[i][1], a[i][2], a[i][3],
                  aAddr[i] + (uint32_t)(ks * 32));
#pragma unroll
        for (int j = 0; j < 3; j++) {
            b2[j][0] = lds32(sWa + bRel[j] + (uint32_t)(ks * 32));
            b2[j][1] = lds32(sWa + bRel[j] + (uint32_t)(ks * 32 + 16));
        }
#pragma unroll
        for (int i = 0; i < 2; i++)
#pragma unroll
            for (int j = 0; j < 3; j++)
                mma16(acc[i][j], a[i], b2[j]);
    }

    // stage proj D (fp32) into sH region
#pragma unroll
    for (int i = 0; i < 2; i++)
#pragma unroll
        for (int j = 0; j < 3; j++) {
            int row = wr * 32 + i * 16 + g;
            int col = wc * 24 + j * 8 + 2 * tig;
            sHf[row * 97 + col]           = acc[i][j][0];
            sHf[row * 97 + col + 1]       = acc[i][j][1];
            sHf[(row + 8) * 97 + col]     = acc[i][j][2];
            sHf[(row + 8) * 97 + col + 1] = acc[i][j][3];
        }
    __syncthreads();

    // ---- x1 = projD + bias + x(planar), SMEM only ----
#pragma unroll
    for (int u = tid; u < 12288; u += 512) {
        int col = u >> 7, px = u & 127;
        sX[px * 97 + col] = sHf[px * 97 + col] + __ldg(pb + col)
            + __ldg(x + (((size_t)(bb * 96 + col)) << 14) + ss0 + px);
    }
    __syncthreads();

    // ---- LN2 (pair-split, 256 threads) -> sA bf16 ----
    if (tid < 256) {
        int px = tid >> 1, half = tid & 1;
        const float* xr = sX + px * 97 + half * 48;
        float sum = 0.f, sq = 0.f;
#pragma unroll
        for (int i = 0; i < 48; i++) {
            float v = xr[i];
            sum += v;
            sq = fmaf(v, v, sq);
        }
        sum += __shfl_xor_sync(0xffffffffu, sum, 1);
        sq  += __shfl_xor_sync(0xffffffffu, sq, 1);
        float mu = sum * (1.f / 96.f);
        float rs = rsqrtf(sq * (1.f / 96.f) - mu * mu + 1e-5f);
#pragma unroll
        for (int i = 0; i < 24; i++) {
            int c = half * 48 + 2 * i;
            float a0 = (xr[2 * i] - mu) * rs * __ldg(lnw + c) + __ldg(lnb + c);
            float a1 = (xr[2 * i + 1] - mu) * rs * __ldg(lnw + c + 1)
                     + __ldg(lnb + c + 1);
            sAw[px * 52 + half * 24 + i] = packbf(a0, a1);
        }
    }
    __syncthreads();

    // ---- fc1 + GELU -> sH (weights double-buffered; buf(nb) = (nb+1)&1) ----
#pragma unroll 1
    for (int nb = 0; nb < 4; nb++) {
        cp_wait0();
        __syncthreads();
        {   // prefetch next stage weights into buf nb&1
            const __nv_bfloat16* Wn = (nb < 3) ? (w1 + (size_t)(nb + 1) * 9216)
                                               : w2;   // fc2 kc0 chunk
            uint32_t dst = sWa + (uint32_t)((nb & 1) * 19968);
            if (nb < 3) {
                for (int u = tid; u < 1152; u += 512) {
                    int rr = u / 12, cc = u - rr * 12;
                    cpa16(dst + (uint32_t)(rr * 208 + cc * 16), Wn + rr * 96 + cc * 8);
                }
            } else {
                for (int u = tid; u < 1152; u += 512) {
                    int rr = u / 12, cc = u - rr * 12;
                    cpa16(dst + (uint32_t)(rr * 208 + cc * 16), w2 + rr * 384 + cc * 8);
                }
            }
            cp_commit();
        }
        const uint32_t wbuf = sWa + (uint32_t)(((nb + 1) & 1) * 19968);

        float a1c[2][3][4];
#pragma unroll
        for (int i = 0; i < 2; i++)
#pragma unroll
            for (int j = 0; j < 3; j++)
#pragma unroll
                for (int q = 0; q < 4; q++) a1c[i][j][q] = 0.f;
#pragma unroll
        for (int ks = 0; ks < 6; ks++) {
            uint32_t a[2][4], b2[3][2];
#pragma unroll
            for (int i = 0; i < 2; i++)
                LDSM4(a[i][0], a[i][1], a[i][2], a[i][3],
                      aAddr[i] + (uint32_t)(ks * 32));
#pragma unroll
            for (int j = 0; j < 3; j++) {
                b2[j][0] = lds32(wbuf + bRel[j] + (uint32_t)(ks * 32));
                b2[j][1] = lds32(wbuf + bRel[j] + (uint32_t)(ks * 32 + 16));
            }
#pragma unroll
            for (int i = 0; i < 2; i++)
#pragma unroll
                for (int j = 0; j < 3; j++)
                    mma16(a1c[i][j], a[i], b2[j]);
        }
#pragma unroll
        for (int i = 0; i < 2; i++)
#pragma unroll
            for (int j = 0; j < 3; j++) {
                int row = wr * 32 + i * 16 + g;
                int col = wc * 24 + j * 8 + 2 * tig;
                float bi0 = __ldg(b1 + nb * 96 + col);
                float bi1 = __ldg(b1 + nb * 96 + col + 1);
                float t0 = a1c[i][j][0] + bi0;
                float t1 = a1c[i][j][1] + bi1;
                float t2 = a1c[i][j][2] + bi0;
                float t3 = a1c[i][j][3] + bi1;
                t0 = 0.5f * t0 * (1.f + erff(t0 * 0.70710678118654752f));
                t1 = 0.5f * t1 * (1.f + erff(t1 * 0.70710678118654752f));
                t2 = 0.5f * t2 * (1.f + erff(t2 * 0.70710678118654752f));
                t3 = 0.5f * t3 * (1.f + erff(t3 * 0.70710678118654752f));
                sHu[(row * 392 + nb * 96 + col) >> 1]       = packbf(t0, t1);
                sHu[((row + 8) * 392 + nb * 96 + col) >> 1] = packbf(t2, t3);
            }
    }

    // ---- fc2: 4 K-chunks from sH (weights buf(kc) = (kc+1)&1) ----
    float acc2[2][3][4];
#pragma unroll
    for (int i = 0; i < 2; i++)
#pragma unroll
        for (int j = 0; j < 3; j++)
#pragma unroll
            for (int q = 0; q < 4; q++) acc2[i][j][q] = 0.f;

#pragma unroll 1
    for (int kc = 0; kc < 4; kc++) {
        cp_wait0();
        __syncthreads();
        if (kc < 3) {
            uint32_t dst = sWa + (uint32_t)((kc & 1) * 19968);
            for (int u = tid; u < 1152; u += 512) {
                int rr = u / 12, cc = u - rr * 12;
                cpa16(dst + (uint32_t)(rr * 208 + cc * 16),
                      w2 + rr * 384 + (kc + 1) * 96 + cc * 8);
            }
            cp_commit();
        }
        const uint32_t wbuf = sWa + (uint32_t)(((kc + 1) & 1) * 19968);

#pragma unroll
        for (int ks = 0; ks < 6; ks++) {
            uint32_t a[2][4], b2[3][2];
#pragma unroll
            for (int i = 0; i < 2; i++)
                LDSM4(a[i][0], a[i][1], a[i][2], a[i][3],
                      hAddr[i] + (uint32_t)(kc * 192 + ks * 32));
#pragma unroll
            for (int j = 0; j < 3; j++) {
                b2[j][0] = lds32(wbuf + bRel[j] + (uint32_t)(ks * 32));
                b2[j][1] = lds32(wbuf + bRel[j] + (uint32_t)(ks * 32 + 16));
            }
#pragma unroll
            for (int i = 0; i < 2; i++)
#pragma unroll
                for (int j = 0; j < 3; j++)
                    mma16(acc2[i][j], a[i], b2[j]);
        }
    }
    __syncthreads();

    // ---- epilogue: 2 passes of 48 cols via sD (sA region) ----
#pragma unroll 1
    for (int p = 0; p < 2; p++) {
        if ((wc >> 1) == p) {
#pragma unroll
            for (int i = 0; i < 2; i++)
#pragma unroll
                for (int j = 0; j < 3; j++) {
                    int row = wr * 32 + i * 16 + g;
                    int chl = (wc & 1) * 24 + j * 8 + 2 * tig;
                    sDf[chl * 132 + row]           = acc2[i][j][0];
                    sDf[(chl + 1) * 132 + row]     = acc2[i][j][1];
                    sDf[chl * 132 + row + 8]       = acc2[i][j][2];
                    sDf[(chl + 1) * 132 + row + 8] = acc2[i][j][3];
                }
        }
        __syncthreads();
#pragma unroll
        for (int u = tid; u < 6144; u += 512) {
            int px = u & 127, chl = u >> 7;
            int ch = p * 48 + chl;
            float val = sDf[chl * 132 + px] + __ldg(b2 + ch) + sX[px * 97 + ch];
            out[(((size_t)(bb * 96 + ch)) << 14) + ss0 + px] = val;
        }
        __syncthreads();
    }
}

// ---------------- launch ----------------
extern "C" void kernel_launch(void* const* d_in, const int* in_sizes, int n_in,
                              void* d_out, int out_size) {
    (void)in_sizes; (void)n_in; (void)out_size;
    const float* x      = (const float*)d_in[0];
    const float* qkv_w  = (const float*)d_in[1];
    const float* proj_w = (const float*)d_in[2];
    const float* proj_b = (const float*)d_in[3];
    const float* ln1w   = (const float*)d_in[4];
    const float* ln1b   = (const float*)d_in[5];
    const float* ln2w   = (const float*)d_in[6];
    const float* ln2b   = (const float*)d_in[7];
    const float* fc1w   = (const float*)d_in[8];
    const float* fc1b   = (const float*)d_in[9];
    const float* fc2w   = (const float*)d_in[10];
    const float* fc2b   = (const float*)d_in[11];
    float* out = (float*)d_out;

    cudaFuncSetAttribute(k_ln1_qkv,
                         cudaFuncAttributeMaxDynamicSharedMemorySize, A_SZ);
    cudaFuncSetAttribute(attn_kernel,
                         cudaFuncAttributeMaxDynamicSharedMemorySize, 73728);
    cudaFuncSetAttribute(k_pm,
                         cudaFuncAttributeMaxDynamicSharedMemorySize, M_SZ);

    __nv_bfloat16 *pqkv, *pattn, *pwb;
    cudaGetSymbolAddress((void**)&pqkv, g_qkv);
    cudaGetSymbolAddress((void**)&pattn, g_attn);
    cudaGetSymbolAddress((void**)&pwb, g_wb);

    round_w<<<432, 256>>>(qkv_w, proj_w, fc1w, fc2w);
    k_ln1_qkv<<<PTOT / 128, 256, A_SZ>>>(x, pwb, ln1w, ln1b, pqkv);
    attn_kernel<<<dim3(512, 6), 256, 73728>>>(pqkv, pattn);
    k_pm<<<PTOT / 128, 512, M_SZ>>>(pattn, pwb + 27648, proj_b, x,
                                    pwb + 36864, fc1b, pwb + 73728, fc2b,
                                    ln2w, ln2b, out);
}

// round 7
// speedup vs baseline: 4.3501x; 1.0391x over previous
#include <cuda_runtime.h>
#include <cuda_bf16.h>
#include <cstdint>
#include <cstddef>

// ---------------- problem constants ----------------
#define HW    16384            // 128*128
#define PTOT  131072           // 8*128*128 = 1<<17

// ---------------- scratch (device globals; no allocation) ----------------
__device__ __align__(16) __nv_bfloat16 g_qkv [(size_t)PTOT * 288];  // PLANAR [288][P]
__device__ __align__(16) __nv_bfloat16 g_attn[(size_t)PTOT * 96];   // row-major P x 96
__device__ __align__(16) __nv_bfloat16 g_wb  [110592];              // bf16 weights

// ---------------- helpers ----------------
__device__ __forceinline__ uint32_t smem_u32(const void* p) {
    uint32_t a;
    asm("{ .reg .u64 t; cvta.to.shared.u64 t, %1; cvt.u32.u64 %0, t; }"
        : "=r"(a) : "l"(p));
    return a;
}
__device__ __forceinline__ void cpa16(uint32_t dst, const void* src) {
    asm volatile("cp.async.cg.shared.global [%0], [%1], 16;"
                 :: "r"(dst), "l"(src));
}
__device__ __forceinline__ void cp_commit() {
    asm volatile("cp.async.commit_group;" ::: "memory");
}
__device__ __forceinline__ void cp_wait0() {
    asm volatile("cp.async.wait_group 0;" ::: "memory");
}
#define LDSM4(r0, r1, r2, r3, addr) \
    asm volatile("ldmatrix.sync.aligned.m8n8.x4.shared.b16 {%0,%1,%2,%3}, [%4];" \
                 : "=r"(r0), "=r"(r1), "=r"(r2), "=r"(r3) : "r"(addr))
#define LDSM2(r0, r1, addr) \
    asm volatile("ldmatrix.sync.aligned.m8n8.x2.shared.b16 {%0,%1}, [%2];" \
                 : "=r"(r0), "=r"(r1) : "r"(addr))
__device__ __forceinline__ void mma16(float* d, const uint32_t* a,
                                      const uint32_t* b) {
    asm volatile(
        "mma.sync.aligned.m16n8k16.row.col.f32.bf16.bf16.f32 "
        "{%0,%1,%2,%3}, {%4,%5,%6,%7}, {%8,%9}, {%0,%1,%2,%3};"
        : "+f"(d[0]), "+f"(d[1]), "+f"(d[2]), "+f"(d[3])
        : "r"(a[0]), "r"(a[1]), "r"(a[2]), "r"(a[3]), "r"(b[0]), "r"(b[1]));
}
__device__ __forceinline__ uint32_t packbf(float a, float b) {
    __nv_bfloat162 p = __floats2bfloat162_rn(a, b);
    return *(uint32_t*)&p;
}
__device__ __forceinline__ float bflo(uint32_t u) {
    return __uint_as_float(u << 16);
}
__device__ __forceinline__ float bfhi(uint32_t u) {
    return __uint_as_float(u & 0xffff0000u);
}

// B-fragment ldmatrix relative addresses (row stride 208 B, 3 j-tiles / warp).
// x4 covers j0(k0,k8)+j1(k0,k8); x2 covers j2(k0,k8).
__device__ __forceinline__ void bfrag_addrs(int wc, int lane,
                                            uint32_t& bA01, uint32_t& bA2) {
    int rw = lane & 7;
    int hi16 = (lane >> 3) & 1;                // byte +16 = k 8..15
    bA01 = (uint32_t)((wc * 24 + ((lane >> 4) << 3) + rw) * 208 + (hi16 << 4));
    bA2  = (uint32_t)((wc * 24 + 16 + rw) * 208 + (hi16 << 4));
}

// ---------------- weight conversion fp32 -> bf16 ----------------
__global__ __launch_bounds__(256)
void round_w(const float* __restrict__ qkv, const float* __restrict__ proj,
             const float* __restrict__ fc1, const float* __restrict__ fc2) {
    int i = blockIdx.x * 256 + threadIdx.x;
    float v;
    if (i < 27648)        v = qkv[i];
    else if (i < 36864)   v = proj[i - 27648];
    else if (i < 73728)   v = fc1[i - 36864];
    else                  v = fc2[i - 73728];
    g_wb[i] = __float2bfloat16_rn(v);
}

// ================= fused LN1 + qkv GEMM (256 thr) =================
// SMEM region R @0 (65280 B):
//   phase1: sXp fp32 [96][132] (channel-major x tile) = 50688
//   phase2: sW0 @0 (19968) | sW1 @19968 (19968) | sD bf16 [96][132] @39936
// sA bf16 [128][104] @65280 (26624).  Total 91904.
#define A_SZ 91904

__global__ __launch_bounds__(256)
void k_ln1_qkv(const float* __restrict__ x, const __nv_bfloat16* __restrict__ wq,
               const float* __restrict__ lnw, const float* __restrict__ lnb,
               __nv_bfloat16* __restrict__ qkv) {
    extern __shared__ __align__(16) char dsm[];
    const uint32_t sb = smem_u32(dsm);
    float* sXp = (float*)dsm;                       // stride 132
    __nv_bfloat16* sDb = (__nv_bfloat16*)(dsm + 39936);
    uint32_t* sAw = (uint32_t*)(dsm + 65280);
    const uint32_t sAa = sb + 65280;

    const int tid = threadIdx.x;
    const int m0 = blockIdx.x * 128;
    const int bb = m0 >> 14, ss0 = m0 & 16383;

    // ---- stage x (planar) channel-major into sXp ----
#pragma unroll
    for (int it = 0; it < 12; it++) {               // 3072 x 16B
        int u = it * 256 + tid;
        int c = u >> 5, q = u & 31;
        cpa16(sb + (uint32_t)(c * 528 + q * 16),
              x + (((size_t)(bb * 96 + c)) << 14) + ss0 + q * 4);
    }
    cp_commit(); cp_wait0();
    __syncthreads();

    // ---- LN1: two threads per pixel ----
    {
        const int px = tid >> 1, half = tid & 1;
        float sum = 0.f, sq = 0.f;
#pragma unroll
        for (int i = 0; i < 48; i++) {
            float v = sXp[(half * 48 + i) * 132 + px];
            sum += v;
            sq = fmaf(v, v, sq);
        }
        sum += __shfl_xor_sync(0xffffffffu, sum, 1);
        sq  += __shfl_xor_sync(0xffffffffu, sq, 1);
        float mu = sum * (1.f / 96.f);
        float rs = rsqrtf(sq * (1.f / 96.f) - mu * mu + 1e-5f);
#pragma unroll
        for (int i = 0; i < 24; i++) {
            int c = half * 48 + 2 * i;
            float a0 = (sXp[c * 132 + px] - mu) * rs * __ldg(lnw + c)
                     + __ldg(lnb + c);
            float a1 = (sXp[(c + 1) * 132 + px] - mu) * rs * __ldg(lnw + c + 1)
                     + __ldg(lnb + c + 1);
            sAw[px * 52 + half * 24 + i] = packbf(a0, a1);
        }
    }
    __syncthreads();                                // sXp dead; sW region live

    // ---- GEMM over 3 N-blocks, double-buffered weights ----
    const int lane = tid & 31;
    const int wid = tid >> 5;
    const int wr = wid >> 2, wc = wid & 3;
    const int g = lane >> 2, tig = lane & 3;

    uint32_t aAddr[4];
#pragma unroll
    for (int i = 0; i < 4; i++)
        aAddr[i] = sAa + (uint32_t)((wr * 64 + i * 16 + (lane & 15)) * 208
                                    + (lane >> 4) * 16);
    uint32_t bA01, bA2;
    bfrag_addrs(wc, lane, bA01, bA2);

    // preload nb0 weights into buf0
    for (int u = tid; u < 1152; u += 256) {
        int rr = u / 12, cc = u - rr * 12;
        cpa16(sb + (uint32_t)(rr * 208 + cc * 16), wq + rr * 96 + cc * 8);
    }
    cp_commit();

#pragma unroll 1
    for (int nb = 0; nb < 3; nb++) {
        cp_wait0();
        __syncthreads();
        if (nb < 2) {                                // prefetch nb+1
            const __nv_bfloat16* Wn = wq + (size_t)(nb + 1) * 9216;
            uint32_t dst = sb + (uint32_t)(((nb + 1) & 1) * 19968);
            for (int u = tid; u < 1152; u += 256) {
                int rr = u / 12, cc = u - rr * 12;
                cpa16(dst + (uint32_t)(rr * 208 + cc * 16), Wn + rr * 96 + cc * 8);
            }
            cp_commit();
        }
        const uint32_t wb = sb + (uint32_t)((nb & 1) * 19968);

        float acc[4][3][4];
#pragma unroll
        for (int i = 0; i < 4; i++)
#pragma unroll
            for (int j = 0; j < 3; j++)
#pragma unroll
                for (int q = 0; q < 4; q++) acc[i][j][q] = 0.f;

#pragma unroll
        for (int ks = 0; ks < 6; ks++) {
            uint32_t a[4][4], b01[4], b2x[2];
            LDSM4(b01[0], b01[1], b01[2], b01[3], wb + bA01 + (uint32_t)(ks * 32));
            LDSM2(b2x[0], b2x[1], wb + bA2 + (uint32_t)(ks * 32));
#pragma unroll
            for (int i = 0; i < 4; i++)
                LDSM4(a[i][0], a[i][1], a[i][2], a[i][3],
                      aAddr[i] + (uint32_t)(ks * 32));
#pragma unroll
            for (int i = 0; i < 4; i++) {
                mma16(acc[i][0], a[i], b01);
                mma16(acc[i][1], a[i], b01 + 2);
                mma16(acc[i][2], a[i], b2x);
            }
        }

        // stage D bf16 [col][132]
#pragma unroll
        for (int i = 0; i < 4; i++)
#pragma unroll
            for (int j = 0; j < 3; j++) {
                int row = wr * 64 + i * 16 + g;
                int col = wc * 24 + j * 8 + 2 * tig;
                sDb[col * 132 + row]           = __float2bfloat16_rn(acc[i][j][0]);
                sDb[(col + 1) * 132 + row]     = __float2bfloat16_rn(acc[i][j][1]);
                sDb[col * 132 + row + 8]       = __float2bfloat16_rn(acc[i][j][2]);
                sDb[(col + 1) * 132 + row + 8] = __float2bfloat16_rn(acc[i][j][3]);
            }
        __syncthreads();
        const uint32_t* sDu = (const uint32_t*)sDb;
#pragma unroll
        for (int u = tid; u < 6144; u += 256) {
            int col = u >> 6, q = u & 63;
            ((uint32_t*)(qkv + (((size_t)(nb * 96 + col)) << 17) + m0))[q]
                = sDu[col * 66 + q];
        }
        __syncthreads();
    }
}

// ================= dilated attention (packed ch-pairs) =================
__global__ __launch_bounds__(256)
void attn_kernel(const __nv_bfloat16* __restrict__ qkvp,
                 __nv_bfloat16* __restrict__ attn) {
    extern __shared__ __align__(16) uint32_t sm32[];
    const int tid = threadIdx.x;
    const int b = blockIdx.x >> 6;
    const int h0 = (blockIdx.x & 63) << 1;
    const int hd = blockIdx.y;
    const int grp = hd >> 1;
    const int dil = grp + 1;
    const int cb = grp * 32 + (hd & 1) * 16;
    const int nr = 2 + 2 * dil;

    {
        float4 z = make_float4(0.f, 0.f, 0.f, 0.f);
        float4* smv = (float4*)sm32;
#pragma unroll
        for (int i = 0; i < 18; i++) smv[i * 256 + tid] = z;
    }
    __syncthreads();

    const int baseh = h0 - dil;
    for (int u = tid; u < (nr << 7); u += 256) {
        int q8 = u & 15, seg = u >> 4;
        int cp = seg / nr, row = seg - cp * nr;
        int hr = baseh + row;
        if ((unsigned)hr < 128u) {
            size_t gofs = ((size_t)b << 14) + (hr << 7) + q8 * 8;
            uint4 k0 = *(const uint4*)(qkvp + (((size_t)(96 + cb + 2 * cp)) << 17) + gofs);
            uint4 k1 = *(const uint4*)(qkvp + (((size_t)(97 + cb + 2 * cp)) << 17) + gofs);
            uint4 v0 = *(const uint4*)(qkvp + (((size_t)(192 + cb + 2 * cp)) << 17) + gofs);
            uint4 v1 = *(const uint4*)(qkvp + (((size_t)(193 + cb + 2 * cp)) << 17) + gofs);
            int di = cp * 1152 + row * 144 + 8 + q8 * 8;
            uint4 o;
            o.x = __byte_perm(k0.x, k1.x, 0x5410); o.y = __byte_perm(k0.x, k1.x, 0x7632);
            o.z = __byte_perm(k0.y, k1.y, 0x5410); o.w = __byte_perm(k0.y, k1.y, 0x7632);
            *(uint4*)(sm32 + di) = o;
            o.x = __byte_perm(k0.z, k1.z, 0x5410); o.y = __byte_perm(k0.z, k1.z, 0x7632);
            o.z = __byte_perm(k0.w, k1.w, 0x5410); o.w = __byte_perm(k0.w, k1.w, 0x7632);
            *(uint4*)(sm32 + di + 4) = o;
            o.x = __byte_perm(v0.x, v1.x, 0x5410); o.y = __byte_perm(v0.x, v1.x, 0x7632);
            o.z = __byte_perm(v0.y, v1.y, 0x5410); o.w = __byte_perm(v0.y, v1.y, 0x7632);
            *(uint4*)(sm32 + di + 9216) = o;
            o.x = __byte_perm(v0.z, v1.z, 0x5410); o.y = __byte_perm(v0.z, v1.z, 0x7632);
            o.z = __byte_perm(v0.w, v1.w, 0x5410); o.w = __byte_perm(v0.w, v1.w, 0x7632);
            *(uint4*)(sm32 + di + 9220) = o;
        }
    }
    __syncthreads();

    const int r = tid >> 7, w = tid & 127;
    const size_t p = ((size_t)b << 14) + ((size_t)(h0 + r) << 7) + w;

    float ql[8], qh[8];
#pragma unroll
    for (int cp = 0; cp < 8; cp++) {
        ql[cp] = __bfloat162float(qkvp[(((size_t)(cb + 2 * cp)) << 17) + p]);
        qh[cp] = __bfloat162float(qkvp[(((size_t)(cb + 2 * cp + 1)) << 17) + p]);
    }

    float sc[9];
#pragma unroll
    for (int i = 0; i < 3; i++)
#pragma unroll
        for (int j = 0; j < 3; j++) {
            int base = (r + i * dil) * 144 + (8 + w + (j - 1) * dil);
            float d = 0.f;
#pragma unroll
            for (int cp = 0; cp < 8; cp++) {
                uint32_t u = sm32[cp * 1152 + base];
                d = fmaf(ql[cp], bflo(u), d);
                d = fmaf(qh[cp], bfhi(u), d);
            }
            sc[i * 3 + j] = d * 0.25f;
        }

    float mx = sc[0];
#pragma unroll
    for (int k = 1; k < 9; k++) mx = fmaxf(mx, sc[k]);
    float ssum = 0.f;
#pragma unroll
    for (int k = 0; k < 9; k++) { sc[k] = __expf(sc[k] - mx); ssum += sc[k]; }
    float inv = 1.f / ssum;

    float ol[8], oh[8];
#pragma unroll
    for (int cp = 0; cp < 8; cp++) { ol[cp] = 0.f; oh[cp] = 0.f; }
#pragma unroll
    for (int i = 0; i < 3; i++)
#pragma unroll
        for (int j = 0; j < 3; j++) {
            float wgt = sc[i * 3 + j] * inv;
            int base = 9216 + (r + i * dil) * 144 + (8 + w + (j - 1) * dil);
#pragma unroll
            for (int cp = 0; cp < 8; cp++) {
                uint32_t u = sm32[cp * 1152 + base];
                ol[cp] = fmaf(wgt, bflo(u), ol[cp]);
                oh[cp] = fmaf(wgt, bfhi(u), oh[cp]);
            }
        }

    __syncthreads();
#pragma unroll
    for (int cp = 0; cp < 8; cp++)
        sm32[tid * 17 + cp] = packbf(ol[cp], oh[cp]);
    __syncthreads();
    const size_t p0 = ((size_t)b << 14) + ((size_t)h0 << 7);
#pragma unroll
    for (int u = tid; u < 2048; u += 256) {
        int row = u >> 3, wq = u & 7;
        ((uint32_t*)(attn + (p0 + row) * 96 + cb))[wq] = sm32[row * 17 + wq];
    }
}

// ================= mega-fused proj + residual + LN2 + MLP (512 thr) =========
// SMEM map:
//   sX  fp32 [128][97]  @0       49664   (x1; also final residual)
//   sH  bf16 [128][392] @49664   100352  (h1; also fp32 [128][97] epi staging)
//   sA  bf16 [128][104] @150016  26624   (A tile: attn, then LN2 out)
//   sW  2 x [96][104]   @176640  39936
#define M_SZ 216576

__global__ __launch_bounds__(512)
void k_pm(const __nv_bfloat16* __restrict__ attn,
          const __nv_bfloat16* __restrict__ wp, const float* __restrict__ pb,
          const float* __restrict__ x,
          const __nv_bfloat16* __restrict__ w1, const float* __restrict__ b1,
          const __nv_bfloat16* __restrict__ w2, const float* __restrict__ b2,
          const float* __restrict__ lnw, const float* __restrict__ lnb,
          float* __restrict__ out) {
    extern __shared__ __align__(16) char dsm[];
    const uint32_t sb = smem_u32(dsm);
    float* sX = (float*)dsm;
    float* sHf = (float*)(dsm + 49664);
    uint32_t* sHu = (uint32_t*)(dsm + 49664);
    uint32_t* sAw = (uint32_t*)(dsm + 150016);
    const uint32_t sHa = sb + 49664;
    const uint32_t sAa = sb + 150016;
    const uint32_t sWa = sb + 176640;

    const int tid = threadIdx.x;
    const int lane = tid & 31;
    const int wid = tid >> 5;                        // 0..15
    const int wr = wid >> 2, wc = wid & 3;           // 4x4 warps
    const int g = lane >> 2, tig = lane & 3;
    const int m0 = blockIdx.x * 128;
    const int bb = m0 >> 14, ss0 = m0 & 16383;

    uint32_t aAddr[2], hAddr[2];
#pragma unroll
    for (int i = 0; i < 2; i++) {
        int row = wr * 32 + i * 16 + (lane & 15);
        aAddr[i] = sAa + (uint32_t)(row * 208 + (lane >> 4) * 16);
        hAddr[i] = sHa + (uint32_t)(row * 784 + (lane >> 4) * 16);
    }
    uint32_t bA01, bA2;
    bfrag_addrs(wc, lane, bA01, bA2);

    // ---- load attn tile + proj weights ----
    const __nv_bfloat16* Ab = attn + (size_t)m0 * 96;
#pragma unroll
    for (int it = 0; it < 3; it++) {                 // 1536 x 16B
        int u = it * 512 + tid;
        int rr = u / 12, cc = u - rr * 12;
        cpa16(sAa + (uint32_t)(rr * 208 + cc * 16), Ab + (size_t)rr * 96 + cc * 8);
    }
    for (int u = tid; u < 1152; u += 512) {
        int rr = u / 12, cc = u - rr * 12;
        cpa16(sWa + (uint32_t)(rr * 208 + cc * 16), wp + rr * 96 + cc * 8);
    }
    cp_commit(); cp_wait0();
    __syncthreads();

    // prefetch fc1 nb0 -> buf1 (overlaps proj mma)
    for (int u = tid; u < 1152; u += 512) {
        int rr = u / 12, cc = u - rr * 12;
        cpa16(sWa + 19968u + (uint32_t)(rr * 208 + cc * 16), w1 + rr * 96 + cc * 8);
    }
    cp_commit();

    // ---- proj mma ----
    float acc[2][3][4];
#pragma unroll
    for (int i = 0; i < 2; i++)
#pragma unroll
        for (int j = 0; j < 3; j++)
#pragma unroll
            for (int q = 0; q < 4; q++) acc[i][j][q] = 0.f;
#pragma unroll
    for (int ks = 0; ks < 6; ks++) {
        uint32_t a[2][4], b01[4], b2x[2];
        LDSM4(b01[0], b01[1], b01[2], b01[3], sWa + bA01 + (uint32_t)(ks * 32));
        LDSM2(b2x[0], b2x[1], sWa + bA2 + (uint32_t)(ks * 32));
#pragma unroll
        for (int i = 0; i < 2; i++)
            LDSM4(a[i][0], a[i][1], a[i][2], a[i][3],
                  aAddr[i] + (uint32_t)(ks * 32));
#pragma unroll
        for (int i = 0; i < 2; i++) {
            mma16(acc[i][0], a[i], b01);
            mma16(acc[i][1], a[i], b01 + 2);
            mma16(acc[i][2], a[i], b2x);
        }
    }

    // ---- x1 = projD + bias directly into sX ----
#pragma unroll
    for (int i = 0; i < 2; i++)
#pragma unroll
        for (int j = 0; j < 3; j++) {
            int row = wr * 32 + i * 16 + g;
            int col = wc * 24 + j * 8 + 2 * tig;
            float bi0 = __ldg(pb + col), bi1 = __ldg(pb + col + 1);
            sX[row * 97 + col]           = acc[i][j][0] + bi0;
            sX[row * 97 + col + 1]       = acc[i][j][1] + bi1;
            sX[(row + 8) * 97 + col]     = acc[i][j][2] + bi0;
            sX[(row + 8) * 97 + col + 1] = acc[i][j][3] + bi1;
        }
    __syncthreads();

    // ---- += x (planar, coalesced) ----
#pragma unroll
    for (int u = tid; u < 12288; u += 512) {
        int col = u >> 7, px = u & 127;
        sX[px * 97 + col] += __ldg(x + (((size_t)(bb * 96 + col)) << 14) + ss0 + px);
    }
    __syncthreads();

    // ---- LN2: 4 threads per pixel ----
    {
        const int px = tid >> 2, q = tid & 3;
        const float* xr = sX + px * 97 + q * 24;
        float sum = 0.f, sq = 0.f;
#pragma unroll
        for (int i = 0; i < 24; i++) {
            float v = xr[i];
            sum += v;
            sq = fmaf(v, v, sq);
        }
        sum += __shfl_xor_sync(0xffffffffu, sum, 1);
        sq  += __shfl_xor_sync(0xffffffffu, sq, 1);
        sum += __shfl_xor_sync(0xffffffffu, sum, 2);
        sq  += __shfl_xor_sync(0xffffffffu, sq, 2);
        float mu = sum * (1.f / 96.f);
        float rs = rsqrtf(sq * (1.f / 96.f) - mu * mu + 1e-5f);
#pragma unroll
        for (int i = 0; i < 12; i++) {
            int c = q * 24 + 2 * i;
            float a0 = (xr[2 * i] - mu) * rs * __ldg(lnw + c) + __ldg(lnb + c);
            float a1 = (xr[2 * i + 1] - mu) * rs * __ldg(lnw + c + 1)
                     + __ldg(lnb + c + 1);
            sAw[px * 52 + q * 12 + i] = packbf(a0, a1);
        }
    }
    __syncthreads();

    // ---- fc1 + GELU -> sH (weights double-buffered; buf(nb) = (nb+1)&1) ----
#pragma unroll 1
    for (int nb = 0; nb < 4; nb++) {
        cp_wait0();
        __syncthreads();
        {   // prefetch next stage weights into buf nb&1
            uint32_t dst = sWa + (uint32_t)((nb & 1) * 19968);
            if (nb < 3) {
                const __nv_bfloat16* Wn = w1 + (size_t)(nb + 1) * 9216;
                for (int u = tid; u < 1152; u += 512) {
                    int rr = u / 12, cc = u - rr * 12;
                    cpa16(dst + (uint32_t)(rr * 208 + cc * 16), Wn + rr * 96 + cc * 8);
                }
            } else {
                for (int u = tid; u < 1152; u += 512) {
                    int rr = u / 12, cc = u - rr * 12;
                    cpa16(dst + (uint32_t)(rr * 208 + cc * 16), w2 + rr * 384 + cc * 8);
                }
            }
            cp_commit();
        }
        const uint32_t wbuf = sWa + (uint32_t)(((nb + 1) & 1) * 19968);

        float a1c[2][3][4];
#pragma unroll
        for (int i = 0; i < 2; i++)
#pragma unroll
            for (int j = 0; j < 3; j++)
#pragma unroll
                for (int q = 0; q < 4; q++) a1c[i][j][q] = 0.f;
#pragma unroll
        for (int ks = 0; ks < 6; ks++) {
            uint32_t a[2][4], b01[4], b2x[2];
            LDSM4(b01[0], b01[1], b01[2], b01[3], wbuf + bA01 + (uint32_t)(ks * 32));
            LDSM2(b2x[0], b2x[1], wbuf + bA2 + (uint32_t)(ks * 32));
#pragma unroll
            for (int i = 0; i < 2; i++)
                LDSM4(a[i][0], a[i][1], a[i][2], a[i][3],
                      aAddr[i] + (uint32_t)(ks * 32));
#pragma unroll
            for (int i = 0; i < 2; i++) {
                mma16(a1c[i][0], a[i], b01);
                mma16(a1c[i][1], a[i], b01 + 2);
                mma16(a1c[i][2], a[i], b2x);
            }
        }
#pragma unroll
        for (int i = 0; i < 2; i++)
#pragma unroll
            for (int j = 0; j < 3; j++) {
                int row = wr * 32 + i * 16 + g;
                int col = wc * 24 + j * 8 + 2 * tig;
                float bi0 = __ldg(b1 + nb * 96 + col);
                float bi1 = __ldg(b1 + nb * 96 + col + 1);
                float t0 = a1c[i][j][0] + bi0;
                float t1 = a1c[i][j][1] + bi1;
                float t2 = a1c[i][j][2] + bi0;
                float t3 = a1c[i][j][3] + bi1;
                t0 = 0.5f * t0 * (1.f + erff(t0 * 0.70710678118654752f));
                t1 = 0.5f * t1 * (1.f + erff(t1 * 0.70710678118654752f));
                t2 = 0.5f * t2 * (1.f + erff(t2 * 0.70710678118654752f));
                t3 = 0.5f * t3 * (1.f + erff(t3 * 0.70710678118654752f));
                sHu[(row * 392 + nb * 96 + col) >> 1]       = packbf(t0, t1);
                sHu[((row + 8) * 392 + nb * 96 + col) >> 1] = packbf(t2, t3);
            }
    }

    // ---- fc2: 4 K-chunks from sH (weights buf(kc) = (kc+1)&1) ----
    float acc2[2][3][4];
#pragma unroll
    for (int i = 0; i < 2; i++)
#pragma unroll
        for (int j = 0; j < 3; j++)
#pragma unroll
            for (int q = 0; q < 4; q++) acc2[i][j][q] = 0.f;

#pragma unroll 1
    for (int kc = 0; kc < 4; kc++) {
        cp_wait0();
        __syncthreads();
        if (kc < 3) {
            uint32_t dst = sWa + (uint32_t)((kc & 1) * 19968);
            for (int u = tid; u < 1152; u += 512) {
                int rr = u / 12, cc = u - rr * 12;
                cpa16(dst + (uint32_t)(rr * 208 + cc * 16),
                      w2 + rr * 384 + (kc + 1) * 96 + cc * 8);
            }
            cp_commit();
        }
        const uint32_t wbuf = sWa + (uint32_t)(((kc + 1) & 1) * 19968);

#pragma unroll
        for (int ks = 0; ks < 6; ks++) {
            uint32_t a[2][4], b01[4], b2x[2];
            LDSM4(b01[0], b01[1], b01[2], b01[3], wbuf + bA01 + (uint32_t)(ks * 32));
            LDSM2(b2x[0], b2x[1], wbuf + bA2 + (uint32_t)(ks * 32));
#pragma unroll
            for (int i = 0; i < 2; i++)
                LDSM4(a[i][0], a[i][1], a[i][2], a[i][3],
                      hAddr[i] + (uint32_t)(kc * 192 + ks * 32));
#pragma unroll
            for (int i = 0; i < 2; i++) {
                mma16(acc2[i][0], a[i], b01);
                mma16(acc2[i][1], a[i], b01 + 2);
                mma16(acc2[i][2], a[i], b2x);
            }
        }
    }
    __syncthreads();                                 // all fc2 sH reads done

    // ---- epilogue: stage all 96 cols fp32 into sH region, one pass ----
#pragma unroll
    for (int i = 0; i < 2; i++)
#pragma unroll
        for (int j = 0; j < 3; j++) {
            int row = wr * 32 + i * 16 + g;
            int col = wc * 24 + j * 8 + 2 * tig;
            sHf[row * 97 + col]           = acc2[i][j][0];
            sHf[row * 97 + col + 1]       = acc2[i][j][1];
            sHf[(row + 8) * 97 + col]     = acc2[i][j][2];
            sHf[(row + 8) * 97 + col + 1] = acc2[i][j][3];
        }
    __syncthreads();
#pragma unroll
    for (int u = tid; u < 12288; u += 512) {
        int col = u >> 7, px = u & 127;
        float val = sHf[px * 97 + col] + __ldg(b2 + col) + sX[px * 97 + col];
        out[(((size_t)(bb * 96 + col)) << 14) + ss0 + px] = val;
    }
}

// ---------------- launch ----------------
extern "C" void kernel_launch(void* const* d_in, const int* in_sizes, int n_in,
                              void* d_out, int out_size) {
    (void)in_sizes; (void)n_in; (void)out_size;
    const float* x      = (const float*)d_in[0];
    const float* qkv_w  = (const float*)d_in[1];
    const float* proj_w = (const float*)d_in[2];
    const float* proj_b = (const float*)d_in[3];
    const float* ln1w   = (const float*)d_in[4];
    const float* ln1b   = (const float*)d_in[5];
    const float* ln2w   = (const float*)d_in[6];
    const float* ln2b   = (const float*)d_in[7];
    const float* fc1w   = (const float*)d_in[8];
    const float* fc1b   = (const float*)d_in[9];
    const float* fc2w   = (const float*)d_in[10];
    const float* fc2b   = (const float*)d_in[11];
    float* out = (float*)d_out;

    cudaFuncSetAttribute(k_ln1_qkv,
                         cudaFuncAttributeMaxDynamicSharedMemorySize, A_SZ);
    cudaFuncSetAttribute(attn_kernel,
                         cudaFuncAttributeMaxDynamicSharedMemorySize, 73728);
    cudaFuncSetAttribute(k_pm,
                         cudaFuncAttributeMaxDynamicSharedMemorySize, M_SZ);

    __nv_bfloat16 *pqkv, *pattn, *pwb;
    cudaGetSymbolAddress((void**)&pqkv, g_qkv);
    cudaGetSymbolAddress((void**)&pattn, g_attn);
    cudaGetSymbolAddress((void**)&pwb, g_wb);

    round_w<<<432, 256>>>(qkv_w, proj_w, fc1w, fc2w);
    k_ln1_qkv<<<PTOT / 128, 256, A_SZ>>>(x, pwb, ln1w, ln1b, pqkv);
    attn_kernel<<<dim3(512, 6), 256, 73728>>>(pqkv, pattn);
    k_pm<<<PTOT / 128, 512, M_SZ>>>(pattn, pwb + 27648, proj_b, x,
                                    pwb + 36864, fc1b, pwb + 73728, fc2b,
                                    ln2w, ln2b, out);
}

// round 8
// speedup vs baseline: 4.4438x; 1.0216x over previous
#include <cuda_runtime.h>
#include <cuda_bf16.h>
#include <cstdint>
#include <cstddef>

// ---------------- problem constants ----------------
#define HW    16384            // 128*128
#define PTOT  131072           // 8*128*128 = 1<<17

// ---------------- scratch (device globals; no allocation) ----------------
__device__ __align__(16) __nv_bfloat16 g_qkv [(size_t)PTOT * 288];  // PLANAR [288][P]
__device__ __align__(16) __nv_bfloat16 g_attn[(size_t)PTOT * 96];   // row-major P x 96
__device__ __align__(16) __nv_bfloat16 g_wb  [110592];              // bf16 weights

// ---------------- helpers ----------------
__device__ __forceinline__ uint32_t smem_u32(const void* p) {
    uint32_t a;
    asm("{ .reg .u64 t; cvta.to.shared.u64 t, %1; cvt.u32.u64 %0, t; }"
        : "=r"(a) : "l"(p));
    return a;
}
__device__ __forceinline__ void cpa16(uint32_t dst, const void* src) {
    asm volatile("cp.async.cg.shared.global [%0], [%1], 16;"
                 :: "r"(dst), "l"(src));
}
__device__ __forceinline__ void cp_commit() {
    asm volatile("cp.async.commit_group;" ::: "memory");
}
__device__ __forceinline__ void cp_wait0() {
    asm volatile("cp.async.wait_group 0;" ::: "memory");
}
#define LDSM4(r0, r1, r2, r3, addr) \
    asm volatile("ldmatrix.sync.aligned.m8n8.x4.shared.b16 {%0,%1,%2,%3}, [%4];" \
                 : "=r"(r0), "=r"(r1), "=r"(r2), "=r"(r3) : "r"(addr))
#define LDSM2(r0, r1, addr) \
    asm volatile("ldmatrix.sync.aligned.m8n8.x2.shared.b16 {%0,%1}, [%2];" \
                 : "=r"(r0), "=r"(r1) : "r"(addr))
__device__ __forceinline__ void mma16(float* d, const uint32_t* a,
                                      const uint32_t* b) {
    asm volatile(
        "mma.sync.aligned.m16n8k16.row.col.f32.bf16.bf16.f32 "
        "{%0,%1,%2,%3}, {%4,%5,%6,%7}, {%8,%9}, {%0,%1,%2,%3};"
        : "+f"(d[0]), "+f"(d[1]), "+f"(d[2]), "+f"(d[3])
        : "r"(a[0]), "r"(a[1]), "r"(a[2]), "r"(a[3]), "r"(b[0]), "r"(b[1]));
}
__device__ __forceinline__ uint32_t packbf(float a, float b) {
    __nv_bfloat162 p = __floats2bfloat162_rn(a, b);
    return *(uint32_t*)&p;
}
__device__ __forceinline__ float bflo(uint32_t u) {
    return __uint_as_float(u << 16);
}
__device__ __forceinline__ float bfhi(uint32_t u) {
    return __uint_as_float(u & 0xffff0000u);
}

// B-fragment ldmatrix relative addresses (row stride 208 B, 3 j-tiles / warp).
// x4 covers j0(k0,k8)+j1(k0,k8); x2 covers j2(k0,k8).
__device__ __forceinline__ void bfrag_addrs(int wc, int lane,
                                            uint32_t& bA01, uint32_t& bA2) {
    int rw = lane & 7;
    int hi16 = (lane >> 3) & 1;                // byte +16 = k 8..15
    bA01 = (uint32_t)((wc * 24 + ((lane >> 4) << 3) + rw) * 208 + (hi16 << 4));
    bA2  = (uint32_t)((wc * 24 + 16 + rw) * 208 + (hi16 << 4));
}

// ---------------- weight conversion fp32 -> bf16 ----------------
__global__ __launch_bounds__(256)
void round_w(const float* __restrict__ qkv, const float* __restrict__ proj,
             const float* __restrict__ fc1, const float* __restrict__ fc2) {
    int i = blockIdx.x * 256 + threadIdx.x;
    float v;
    if (i < 27648)        v = qkv[i];
    else if (i < 36864)   v = proj[i - 27648];
    else if (i < 73728)   v = fc1[i - 36864];
    else                  v = fc2[i - 73728];
    g_wb[i] = __float2bfloat16_rn(v);
}

// ================= fused LN1 + qkv GEMM (256 thr) =================
// SMEM region R @0 (65280 B):
//   phase1: sXp fp32 [96][132] (channel-major x tile) = 50688
//   phase2: sW0 @0 (19968) | sW1 @19968 (19968) | sD bf16 [96][132] @39936
// sA bf16 [128][104] @65280 (26624).  Total 91904.
#define A_SZ 91904

__global__ __launch_bounds__(256)
void k_ln1_qkv(const float* __restrict__ x, const __nv_bfloat16* __restrict__ wq,
               const float* __restrict__ lnw, const float* __restrict__ lnb,
               __nv_bfloat16* __restrict__ qkv) {
    extern __shared__ __align__(16) char dsm[];
    const uint32_t sb = smem_u32(dsm);
    float* sXp = (float*)dsm;                       // stride 132
    __nv_bfloat16* sDb = (__nv_bfloat16*)(dsm + 39936);
    uint32_t* sAw = (uint32_t*)(dsm + 65280);
    const uint32_t sAa = sb + 65280;

    const int tid = threadIdx.x;
    const int m0 = blockIdx.x * 128;
    const int bb = m0 >> 14, ss0 = m0 & 16383;

    // ---- stage x (planar) channel-major into sXp ----
#pragma unroll
    for (int it = 0; it < 12; it++) {               // 3072 x 16B
        int u = it * 256 + tid;
        int c = u >> 5, q = u & 31;
        cpa16(sb + (uint32_t)(c * 528 + q * 16),
              x + (((size_t)(bb * 96 + c)) << 14) + ss0 + q * 4);
    }
    cp_commit(); cp_wait0();
    __syncthreads();

    // ---- LN1: two threads per pixel ----
    {
        const int px = tid >> 1, half = tid & 1;
        float sum = 0.f, sq = 0.f;
#pragma unroll
        for (int i = 0; i < 48; i++) {
            float v = sXp[(half * 48 + i) * 132 + px];
            sum += v;
            sq = fmaf(v, v, sq);
        }
        sum += __shfl_xor_sync(0xffffffffu, sum, 1);
        sq  += __shfl_xor_sync(0xffffffffu, sq, 1);
        float mu = sum * (1.f / 96.f);
        float rs = rsqrtf(sq * (1.f / 96.f) - mu * mu + 1e-5f);
#pragma unroll
        for (int i = 0; i < 24; i++) {
            int c = half * 48 + 2 * i;
            float a0 = (sXp[c * 132 + px] - mu) * rs * __ldg(lnw + c)
                     + __ldg(lnb + c);
            float a1 = (sXp[(c + 1) * 132 + px] - mu) * rs * __ldg(lnw + c + 1)
                     + __ldg(lnb + c + 1);
            sAw[px * 52 + half * 24 + i] = packbf(a0, a1);
        }
    }
    __syncthreads();                                // sXp dead; sW region live

    // ---- GEMM over 3 N-blocks, double-buffered weights ----
    const int lane = tid & 31;
    const int wid = tid >> 5;
    const int wr = wid >> 2, wc = wid & 3;
    const int g = lane >> 2, tig = lane & 3;

    uint32_t aAddr[4];
#pragma unroll
    for (int i = 0; i < 4; i++)
        aAddr[i] = sAa + (uint32_t)((wr * 64 + i * 16 + (lane & 15)) * 208
                                    + (lane >> 4) * 16);
    uint32_t bA01, bA2;
    bfrag_addrs(wc, lane, bA01, bA2);

    // preload nb0 weights into buf0
    for (int u = tid; u < 1152; u += 256) {
        int rr = u / 12, cc = u - rr * 12;
        cpa16(sb + (uint32_t)(rr * 208 + cc * 16), wq + rr * 96 + cc * 8);
    }
    cp_commit();

#pragma unroll 1
    for (int nb = 0; nb < 3; nb++) {
        cp_wait0();
        __syncthreads();
        if (nb < 2) {                                // prefetch nb+1
            const __nv_bfloat16* Wn = wq + (size_t)(nb + 1) * 9216;
            uint32_t dst = sb + (uint32_t)(((nb + 1) & 1) * 19968);
            for (int u = tid; u < 1152; u += 256) {
                int rr = u / 12, cc = u - rr * 12;
                cpa16(dst + (uint32_t)(rr * 208 + cc * 16), Wn + rr * 96 + cc * 8);
            }
            cp_commit();
        }
        const uint32_t wb = sb + (uint32_t)((nb & 1) * 19968);

        float acc[4][3][4];
#pragma unroll
        for (int i = 0; i < 4; i++)
#pragma unroll
            for (int j = 0; j < 3; j++)
#pragma unroll
                for (int q = 0; q < 4; q++) acc[i][j][q] = 0.f;

#pragma unroll
        for (int ks = 0; ks < 6; ks++) {
            uint32_t a[4][4], b01[4], b2x[2];
            LDSM4(b01[0], b01[1], b01[2], b01[3], wb + bA01 + (uint32_t)(ks * 32));
            LDSM2(b2x[0], b2x[1], wb + bA2 + (uint32_t)(ks * 32));
#pragma unroll
            for (int i = 0; i < 4; i++)
                LDSM4(a[i][0], a[i][1], a[i][2], a[i][3],
                      aAddr[i] + (uint32_t)(ks * 32));
#pragma unroll
            for (int i = 0; i < 4; i++) {
                mma16(acc[i][0], a[i], b01);
                mma16(acc[i][1], a[i], b01 + 2);
                mma16(acc[i][2], a[i], b2x);
            }
        }

        // stage D bf16 [col][132]
#pragma unroll
        for (int i = 0; i < 4; i++)
#pragma unroll
            for (int j = 0; j < 3; j++) {
                int row = wr * 64 + i * 16 + g;
                int col = wc * 24 + j * 8 + 2 * tig;
                sDb[col * 132 + row]           = __float2bfloat16_rn(acc[i][j][0]);
                sDb[(col + 1) * 132 + row]     = __float2bfloat16_rn(acc[i][j][1]);
                sDb[col * 132 + row + 8]       = __float2bfloat16_rn(acc[i][j][2]);
                sDb[(col + 1) * 132 + row + 8] = __float2bfloat16_rn(acc[i][j][3]);
            }
        __syncthreads();
        const uint32_t* sDu = (const uint32_t*)sDb;
#pragma unroll
        for (int u = tid; u < 6144; u += 256) {
            int col = u >> 6, q = u & 63;
            ((uint32_t*)(qkv + (((size_t)(nb * 96 + col)) << 17) + m0))[q]
                = sDu[col * 66 + q];
        }
        __syncthreads();
    }
}

// ================= dilated attention (packed ch-pairs) =================
__global__ __launch_bounds__(256)
void attn_kernel(const __nv_bfloat16* __restrict__ qkvp,
                 __nv_bfloat16* __restrict__ attn) {
    extern __shared__ __align__(16) uint32_t sm32[];
    const int tid = threadIdx.x;
    const int b = blockIdx.x >> 6;
    const int h0 = (blockIdx.x & 63) << 1;
    const int hd = blockIdx.y;
    const int grp = hd >> 1;
    const int dil = grp + 1;
    const int cb = grp * 32 + (hd & 1) * 16;
    const int nr = 2 + 2 * dil;

    {
        float4 z = make_float4(0.f, 0.f, 0.f, 0.f);
        float4* smv = (float4*)sm32;
#pragma unroll
        for (int i = 0; i < 18; i++) smv[i * 256 + tid] = z;
    }
    __syncthreads();

    const int baseh = h0 - dil;
    for (int u = tid; u < (nr << 7); u += 256) {
        int q8 = u & 15, seg = u >> 4;
        int cp = seg / nr, row = seg - cp * nr;
        int hr = baseh + row;
        if ((unsigned)hr < 128u) {
            size_t gofs = ((size_t)b << 14) + (hr << 7) + q8 * 8;
            uint4 k0 = *(const uint4*)(qkvp + (((size_t)(96 + cb + 2 * cp)) << 17) + gofs);
            uint4 k1 = *(const uint4*)(qkvp + (((size_t)(97 + cb + 2 * cp)) << 17) + gofs);
            uint4 v0 = *(const uint4*)(qkvp + (((size_t)(192 + cb + 2 * cp)) << 17) + gofs);
            uint4 v1 = *(const uint4*)(qkvp + (((size_t)(193 + cb + 2 * cp)) << 17) + gofs);
            int di = cp * 1152 + row * 144 + 8 + q8 * 8;
            uint4 o;
            o.x = __byte_perm(k0.x, k1.x, 0x5410); o.y = __byte_perm(k0.x, k1.x, 0x7632);
            o.z = __byte_perm(k0.y, k1.y, 0x5410); o.w = __byte_perm(k0.y, k1.y, 0x7632);
            *(uint4*)(sm32 + di) = o;
            o.x = __byte_perm(k0.z, k1.z, 0x5410); o.y = __byte_perm(k0.z, k1.z, 0x7632);
            o.z = __byte_perm(k0.w, k1.w, 0x5410); o.w = __byte_perm(k0.w, k1.w, 0x7632);
            *(uint4*)(sm32 + di + 4) = o;
            o.x = __byte_perm(v0.x, v1.x, 0x5410); o.y = __byte_perm(v0.x, v1.x, 0x7632);
            o.z = __byte_perm(v0.y, v1.y, 0x5410); o.w = __byte_perm(v0.y, v1.y, 0x7632);
            *(uint4*)(sm32 + di + 9216) = o;
            o.x = __byte_perm(v0.z, v1.z, 0x5410); o.y = __byte_perm(v0.z, v1.z, 0x7632);
            o.z = __byte_perm(v0.w, v1.w, 0x5410); o.w = __byte_perm(v0.w, v1.w, 0x7632);
            *(uint4*)(sm32 + di + 9220) = o;
        }
    }
    __syncthreads();

    const int r = tid >> 7, w = tid & 127;
    const size_t p = ((size_t)b << 14) + ((size_t)(h0 + r) << 7) + w;

    float ql[8], qh[8];
#pragma unroll
    for (int cp = 0; cp < 8; cp++) {
        ql[cp] = __bfloat162float(qkvp[(((size_t)(cb + 2 * cp)) << 17) + p]);
        qh[cp] = __bfloat162float(qkvp[(((size_t)(cb + 2 * cp + 1)) << 17) + p]);
    }

    float sc[9];
#pragma unroll
    for (int i = 0; i < 3; i++)
#pragma unroll
        for (int j = 0; j < 3; j++) {
            int base = (r + i * dil) * 144 + (8 + w + (j - 1) * dil);
            float d = 0.f;
#pragma unroll
            for (int cp = 0; cp < 8; cp++) {
                uint32_t u = sm32[cp * 1152 + base];
                d = fmaf(ql[cp], bflo(u), d);
                d = fmaf(qh[cp], bfhi(u), d);
            }
            sc[i * 3 + j] = d * 0.25f;
        }

    float mx = sc[0];
#pragma unroll
    for (int k = 1; k < 9; k++) mx = fmaxf(mx, sc[k]);
    float ssum = 0.f;
#pragma unroll
    for (int k = 0; k < 9; k++) { sc[k] = __expf(sc[k] - mx); ssum += sc[k]; }
    float inv = 1.f / ssum;

    float ol[8], oh[8];
#pragma unroll
    for (int cp = 0; cp < 8; cp++) { ol[cp] = 0.f; oh[cp] = 0.f; }
#pragma unroll
    for (int i = 0; i < 3; i++)
#pragma unroll
        for (int j = 0; j < 3; j++) {
            float wgt = sc[i * 3 + j] * inv;
            int base = 9216 + (r + i * dil) * 144 + (8 + w + (j - 1) * dil);
#pragma unroll
            for (int cp = 0; cp < 8; cp++) {
                uint32_t u = sm32[cp * 1152 + base];
                ol[cp] = fmaf(wgt, bflo(u), ol[cp]);
                oh[cp] = fmaf(wgt, bfhi(u), oh[cp]);
            }
        }

    __syncthreads();
#pragma unroll
    for (int cp = 0; cp < 8; cp++)
        sm32[tid * 17 + cp] = packbf(ol[cp], oh[cp]);
    __syncthreads();
    const size_t p0 = ((size_t)b << 14) + ((size_t)h0 << 7);
#pragma unroll
    for (int u = tid; u < 2048; u += 256) {
        int row = u >> 3, wq = u & 7;
        ((uint32_t*)(attn + (p0 + row) * 96 + cb))[wq] = sm32[row * 17 + wq];
    }
}

// ================= mega-fused proj+res+LN2+MLP, M=64 tile, 2 CTAs/SM ========
// SMEM map (108288 B total -> 2 CTAs/SM):
//   sX  fp32 [64][97]  @0      24832   (x1; final residual)
//   sH  bf16 [64][392] @24832  50176   (h1; also fp32 [64][97] epi staging)
//   sA  bf16 [64][104] @75008  13312   (A tile: attn, then LN2 out)
//   sW  [96][104] bf16 @88320  19968   (single-buffered weights)
#define M_SZ 108288

__global__ __launch_bounds__(256, 2)
void k_pm(const __nv_bfloat16* __restrict__ attn,
          const __nv_bfloat16* __restrict__ wp, const float* __restrict__ pb,
          const float* __restrict__ x,
          const __nv_bfloat16* __restrict__ w1, const float* __restrict__ b1,
          const __nv_bfloat16* __restrict__ w2, const float* __restrict__ b2,
          const float* __restrict__ lnw, const float* __restrict__ lnb,
          float* __restrict__ out) {
    extern __shared__ __align__(16) char dsm[];
    const uint32_t sb = smem_u32(dsm);
    float* sX = (float*)dsm;
    float* sHf = (float*)(dsm + 24832);
    uint32_t* sHu = (uint32_t*)(dsm + 24832);
    uint32_t* sAw = (uint32_t*)(dsm + 75008);
    const uint32_t sHa = sb + 24832;
    const uint32_t sAa = sb + 75008;
    const uint32_t sWa = sb + 88320;

    const int tid = threadIdx.x;
    const int lane = tid & 31;
    const int wid = tid >> 5;                        // 0..7
    const int wr = wid >> 2, wc = wid & 3;           // 2x4 warps
    const int g = lane >> 2, tig = lane & 3;
    const int m0 = blockIdx.x * 64;
    const int bb = m0 >> 14, ss0 = m0 & 16383;

    uint32_t aAddr[2], hAddr[2];
#pragma unroll
    for (int i = 0; i < 2; i++) {
        int row = wr * 32 + i * 16 + (lane & 15);
        aAddr[i] = sAa + (uint32_t)(row * 208 + (lane >> 4) * 16);
        hAddr[i] = sHa + (uint32_t)(row * 784 + (lane >> 4) * 16);
    }
    uint32_t bA01, bA2;
    bfrag_addrs(wc, lane, bA01, bA2);

    // ---- load attn tile (64x96) + proj weights ----
    const __nv_bfloat16* Ab = attn + (size_t)m0 * 96;
#pragma unroll
    for (int it = 0; it < 3; it++) {                 // 768 x 16B
        int u = it * 256 + tid;
        int rr = u / 12, cc = u - rr * 12;
        cpa16(sAa + (uint32_t)(rr * 208 + cc * 16), Ab + (size_t)rr * 96 + cc * 8);
    }
    for (int u = tid; u < 1152; u += 256) {
        int rr = u / 12, cc = u - rr * 12;
        cpa16(sWa + (uint32_t)(rr * 208 + cc * 16), wp + rr * 96 + cc * 8);
    }
    cp_commit(); cp_wait0();
    __syncthreads();

    // ---- proj mma ----
    float acc[2][3][4];
#pragma unroll
    for (int i = 0; i < 2; i++)
#pragma unroll
        for (int j = 0; j < 3; j++)
#pragma unroll
            for (int q = 0; q < 4; q++) acc[i][j][q] = 0.f;
#pragma unroll
    for (int ks = 0; ks < 6; ks++) {
        uint32_t a[2][4], b01[4], b2x[2];
        LDSM4(b01[0], b01[1], b01[2], b01[3], sWa + bA01 + (uint32_t)(ks * 32));
        LDSM2(b2x[0], b2x[1], sWa + bA2 + (uint32_t)(ks * 32));
#pragma unroll
        for (int i = 0; i < 2; i++)
            LDSM4(a[i][0], a[i][1], a[i][2], a[i][3],
                  aAddr[i] + (uint32_t)(ks * 32));
#pragma unroll
        for (int i = 0; i < 2; i++) {
            mma16(acc[i][0], a[i], b01);
            mma16(acc[i][1], a[i], b01 + 2);
            mma16(acc[i][2], a[i], b2x);
        }
    }

    // ---- x1 = projD + bias directly into sX ----
#pragma unroll
    for (int i = 0; i < 2; i++)
#pragma unroll
        for (int j = 0; j < 3; j++) {
            int row = wr * 32 + i * 16 + g;
            int col = wc * 24 + j * 8 + 2 * tig;
            float bi0 = __ldg(pb + col), bi1 = __ldg(pb + col + 1);
            sX[row * 97 + col]           = acc[i][j][0] + bi0;
            sX[row * 97 + col + 1]       = acc[i][j][1] + bi1;
            sX[(row + 8) * 97 + col]     = acc[i][j][2] + bi0;
            sX[(row + 8) * 97 + col + 1] = acc[i][j][3] + bi1;
        }
    __syncthreads();

    // ---- += x (planar, coalesced) ----
#pragma unroll
    for (int u = tid; u < 6144; u += 256) {
        int col = u >> 6, px = u & 63;
        sX[px * 97 + col] += __ldg(x + (((size_t)(bb * 96 + col)) << 14) + ss0 + px);
    }
    __syncthreads();

    // ---- LN2: 4 threads per pixel (64 px x 4 = 256) ----
    {
        const int px = tid >> 2, q = tid & 3;
        const float* xr = sX + px * 97 + q * 24;
        float sum = 0.f, sq = 0.f;
#pragma unroll
        for (int i = 0; i < 24; i++) {
            float v = xr[i];
            sum += v;
            sq = fmaf(v, v, sq);
        }
        sum += __shfl_xor_sync(0xffffffffu, sum, 1);
        sq  += __shfl_xor_sync(0xffffffffu, sq, 1);
        sum += __shfl_xor_sync(0xffffffffu, sum, 2);
        sq  += __shfl_xor_sync(0xffffffffu, sq, 2);
        float mu = sum * (1.f / 96.f);
        float rs = rsqrtf(sq * (1.f / 96.f) - mu * mu + 1e-5f);
#pragma unroll
        for (int i = 0; i < 12; i++) {
            int c = q * 24 + 2 * i;
            float a0 = (xr[2 * i] - mu) * rs * __ldg(lnw + c) + __ldg(lnb + c);
            float a1 = (xr[2 * i + 1] - mu) * rs * __ldg(lnw + c + 1)
                     + __ldg(lnb + c + 1);
            sAw[px * 52 + q * 12 + i] = packbf(a0, a1);
        }
    }

    // ---- fc1 + GELU -> sH (single weight buffer; 2 CTAs/SM hide latency) ----
#pragma unroll 1
    for (int nb = 0; nb < 4; nb++) {
        __syncthreads();                             // prior sW reads done
        const __nv_bfloat16* Wn = w1 + (size_t)nb * 9216;
        for (int u = tid; u < 1152; u += 256) {
            int rr = u / 12, cc = u - rr * 12;
            cpa16(sWa + (uint32_t)(rr * 208 + cc * 16), Wn + rr * 96 + cc * 8);
        }
        cp_commit(); cp_wait0();
        __syncthreads();

        float a1c[2][3][4];
#pragma unroll
        for (int i = 0; i < 2; i++)
#pragma unroll
            for (int j = 0; j < 3; j++)
#pragma unroll
                for (int q = 0; q < 4; q++) a1c[i][j][q] = 0.f;
#pragma unroll
        for (int ks = 0; ks < 6; ks++) {
            uint32_t a[2][4], b01[4], b2x[2];
            LDSM4(b01[0], b01[1], b01[2], b01[3], sWa + bA01 + (uint32_t)(ks * 32));
            LDSM2(b2x[0], b2x[1], sWa + bA2 + (uint32_t)(ks * 32));
#pragma unroll
            for (int i = 0; i < 2; i++)
                LDSM4(a[i][0], a[i][1], a[i][2], a[i][3],
                      aAddr[i] + (uint32_t)(ks * 32));
#pragma unroll
            for (int i = 0; i < 2; i++) {
                mma16(a1c[i][0], a[i], b01);
                mma16(a1c[i][1], a[i], b01 + 2);
                mma16(a1c[i][2], a[i], b2x);
            }
        }
#pragma unroll
        for (int i = 0; i < 2; i++)
#pragma unroll
            for (int j = 0; j < 3; j++) {
                int row = wr * 32 + i * 16 + g;
                int col = wc * 24 + j * 8 + 2 * tig;
                float bi0 = __ldg(b1 + nb * 96 + col);
                float bi1 = __ldg(b1 + nb * 96 + col + 1);
                float t0 = a1c[i][j][0] + bi0;
                float t1 = a1c[i][j][1] + bi1;
                float t2 = a1c[i][j][2] + bi0;
                float t3 = a1c[i][j][3] + bi1;
                t0 = 0.5f * t0 * (1.f + erff(t0 * 0.70710678118654752f));
                t1 = 0.5f * t1 * (1.f + erff(t1 * 0.70710678118654752f));
                t2 = 0.5f * t2 * (1.f + erff(t2 * 0.70710678118654752f));
                t3 = 0.5f * t3 * (1.f + erff(t3 * 0.70710678118654752f));
                sHu[(row * 392 + nb * 96 + col) >> 1]       = packbf(t0, t1);
                sHu[((row + 8) * 392 + nb * 96 + col) >> 1] = packbf(t2, t3);
            }
    }

    // ---- fc2: 4 K-chunks from sH ----
    float acc2[2][3][4];
#pragma unroll
    for (int i = 0; i < 2; i++)
#pragma unroll
        for (int j = 0; j < 3; j++)
#pragma unroll
            for (int q = 0; q < 4; q++) acc2[i][j][q] = 0.f;

#pragma unroll 1
    for (int kc = 0; kc < 4; kc++) {
        __syncthreads();                             // prior sW reads done
        for (int u = tid; u < 1152; u += 256) {
            int rr = u / 12, cc = u - rr * 12;
            cpa16(sWa + (uint32_t)(rr * 208 + cc * 16),
                  w2 + rr * 384 + kc * 96 + cc * 8);
        }
        cp_commit(); cp_wait0();
        __syncthreads();

#pragma unroll
        for (int ks = 0; ks < 6; ks++) {
            uint32_t a[2][4], b01[4], b2x[2];
            LDSM4(b01[0], b01[1], b01[2], b01[3], sWa + bA01 + (uint32_t)(ks * 32));
            LDSM2(b2x[0], b2x[1], sWa + bA2 + (uint32_t)(ks * 32));
#pragma unroll
            for (int i = 0; i < 2; i++)
                LDSM4(a[i][0], a[i][1], a[i][2], a[i][3],
                      hAddr[i] + (uint32_t)(kc * 192 + ks * 32));
#pragma unroll
            for (int i = 0; i < 2; i++) {
                mma16(acc2[i][0], a[i], b01);
                mma16(acc2[i][1], a[i], b01 + 2);
                mma16(acc2[i][2], a[i], b2x);
            }
        }
    }
    __syncthreads();                                 // all fc2 sH reads done

    // ---- epilogue: stage 96 cols fp32 into sH region, single pass ----
#pragma unroll
    for (int i = 0; i < 2; i++)
#pragma unroll
        for (int j = 0; j < 3; j++) {
            int row = wr * 32 + i * 16 + g;
            int col = wc * 24 + j * 8 + 2 * tig;
            sHf[row * 97 + col]           = acc2[i][j][0];
            sHf[row * 97 + col + 1]       = acc2[i][j][1];
            sHf[(row + 8) * 97 + col]     = acc2[i][j][2];
            sHf[(row + 8) * 97 + col + 1] = acc2[i][j][3];
        }
    __syncthreads();
#pragma unroll
    for (int u = tid; u < 6144; u += 256) {
        int col = u >> 6, px = u & 63;
        float val = sHf[px * 97 + col] + __ldg(b2 + col) + sX[px * 97 + col];
        out[(((size_t)(bb * 96 + col)) << 14) + ss0 + px] = val;
    }
}

// ---------------- launch ----------------
extern "C" void kernel_launch(void* const* d_in, const int* in_sizes, int n_in,
                              void* d_out, int out_size) {
    (void)in_sizes; (void)n_in; (void)out_size;
    const float* x      = (const float*)d_in[0];
    const float* qkv_w  = (const float*)d_in[1];
    const float* proj_w = (const float*)d_in[2];
    const float* proj_b = (const float*)d_in[3];
    const float* ln1w   = (const float*)d_in[4];
    const float* ln1b   = (const float*)d_in[5];
    const float* ln2w   = (const float*)d_in[6];
    const float* ln2b   = (const float*)d_in[7];
    const float* fc1w   = (const float*)d_in[8];
    const float* fc1b   = (const float*)d_in[9];
    const float* fc2w   = (const float*)d_in[10];
    const float* fc2b   = (const float*)d_in[11];
    float* out = (float*)d_out;

    cudaFuncSetAttribute(k_ln1_qkv,
                         cudaFuncAttributeMaxDynamicSharedMemorySize, A_SZ);
    cudaFuncSetAttribute(attn_kernel,
                         cudaFuncAttributeMaxDynamicSharedMemorySize, 73728);
    cudaFuncSetAttribute(k_pm,
                         cudaFuncAttributeMaxDynamicSharedMemorySize, M_SZ);

    __nv_bfloat16 *pqkv, *pattn, *pwb;
    cudaGetSymbolAddress((void**)&pqkv, g_qkv);
    cudaGetSymbolAddress((void**)&pattn, g_attn);
    cudaGetSymbolAddress((void**)&pwb, g_wb);

    round_w<<<432, 256>>>(qkv_w, proj_w, fc1w, fc2w);
    k_ln1_qkv<<<PTOT / 128, 256, A_SZ>>>(x, pwb, ln1w, ln1b, pqkv);
    attn_kernel<<<dim3(512, 6), 256, 73728>>>(pqkv, pattn);
    k_pm<<<PTOT / 64, 256, M_SZ>>>(pattn, pwb + 27648, proj_b, x,
                                   pwb + 36864, fc1b, pwb + 73728, fc2b,
                                   ln2w, ln2b, out);
}

// round 9
// speedup vs baseline: 4.9808x; 1.1208x over previous
#include <cuda_runtime.h>
#include <cuda_bf16.h>
#include <cstdint>
#include <cstddef>

// ---------------- problem constants ----------------
#define HW    16384            // 128*128
#define PTOT  131072           // 8*128*128 = 1<<17

// ---------------- scratch (device globals; no allocation) ----------------
__device__ __align__(16) __nv_bfloat16 g_qkv [(size_t)PTOT * 288];  // PLANAR [288][P]
__device__ __align__(16) __nv_bfloat16 g_attn[(size_t)PTOT * 96];   // row-major P x 96
__device__ __align__(16) __nv_bfloat16 g_wb  [110592];              // bf16 weights

// ---------------- helpers ----------------
__device__ __forceinline__ uint32_t smem_u32(const void* p) {
    uint32_t a;
    asm("{ .reg .u64 t; cvta.to.shared.u64 t, %1; cvt.u32.u64 %0, t; }"
        : "=r"(a) : "l"(p));
    return a;
}
__device__ __forceinline__ void cpa16(uint32_t dst, const void* src) {
    asm volatile("cp.async.cg.shared.global [%0], [%1], 16;"
                 :: "r"(dst), "l"(src));
}
__device__ __forceinline__ void cp_commit() {
    asm volatile("cp.async.commit_group;" ::: "memory");
}
__device__ __forceinline__ void cp_wait0() {
    asm volatile("cp.async.wait_group 0;" ::: "memory");
}
#define LDSM4(r0, r1, r2, r3, addr) \
    asm volatile("ldmatrix.sync.aligned.m8n8.x4.shared.b16 {%0,%1,%2,%3}, [%4];" \
                 : "=r"(r0), "=r"(r1), "=r"(r2), "=r"(r3) : "r"(addr))
#define LDSM2(r0, r1, addr) \
    asm volatile("ldmatrix.sync.aligned.m8n8.x2.shared.b16 {%0,%1}, [%2];" \
                 : "=r"(r0), "=r"(r1) : "r"(addr))
__device__ __forceinline__ void mma16(float* d, const uint32_t* a,
                                      const uint32_t* b) {
    asm volatile(
        "mma.sync.aligned.m16n8k16.row.col.f32.bf16.bf16.f32 "
        "{%0,%1,%2,%3}, {%4,%5,%6,%7}, {%8,%9}, {%0,%1,%2,%3};"
        : "+f"(d[0]), "+f"(d[1]), "+f"(d[2]), "+f"(d[3])
        : "r"(a[0]), "r"(a[1]), "r"(a[2]), "r"(a[3]), "r"(b[0]), "r"(b[1]));
}
__device__ __forceinline__ uint32_t packbf(float a, float b) {
    __nv_bfloat162 p = __floats2bfloat162_rn(a, b);
    return *(uint32_t*)&p;
}
__device__ __forceinline__ float bflo(uint32_t u) {
    return __uint_as_float(u << 16);
}
__device__ __forceinline__ float bfhi(uint32_t u) {
    return __uint_as_float(u & 0xffff0000u);
}
// tanh-form GELU via hardware MUFU.TANH (~5 instrs vs ~18 for erff).
__device__ __forceinline__ float gelu_f(float t) {
    float u = 0.7978845608f * t * fmaf(t * t, 0.044715f, 1.0f);
    float th;
    asm("tanh.approx.f32 %0, %1;" : "=f"(th) : "f"(u));
    return 0.5f * t * (1.f + th);
}

// B-fragment ldmatrix relative addresses (row stride 208 B, 3 j-tiles / warp).
// x4 covers j0(k0,k8)+j1(k0,k8); x2 covers j2(k0,k8).
__device__ __forceinline__ void bfrag_addrs(int wc, int lane,
                                            uint32_t& bA01, uint32_t& bA2) {
    int rw = lane & 7;
    int hi16 = (lane >> 3) & 1;                // byte +16 = k 8..15
    bA01 = (uint32_t)((wc * 24 + ((lane >> 4) << 3) + rw) * 208 + (hi16 << 4));
    bA2  = (uint32_t)((wc * 24 + 16 + rw) * 208 + (hi16 << 4));
}

// ---------------- weight conversion fp32 -> bf16 ----------------
__global__ __launch_bounds__(256)
void round_w(const float* __restrict__ qkv, const float* __restrict__ proj,
             const float* __restrict__ fc1, const float* __restrict__ fc2) {
    int i = blockIdx.x * 256 + threadIdx.x;
    float v;
    if (i < 27648)        v = qkv[i];
    else if (i < 36864)   v = proj[i - 27648];
    else if (i < 73728)   v = fc1[i - 36864];
    else                  v = fc2[i - 73728];
    g_wb[i] = __float2bfloat16_rn(v);
}

// ================= fused LN1 + qkv GEMM (256 thr) =================
// SMEM region R @0 (65280 B):
//   phase1: sXp fp32 [96][132] (channel-major x tile) = 50688
//   phase2: sW0 @0 (19968) | sW1 @19968 (19968) | sD bf16 [96][132] @39936
// sA bf16 [128][104] @65280 (26624).  Total 91904.
#define A_SZ 91904

__global__ __launch_bounds__(256)
void k_ln1_qkv(const float* __restrict__ x, const __nv_bfloat16* __restrict__ wq,
               const float* __restrict__ lnw, const float* __restrict__ lnb,
               __nv_bfloat16* __restrict__ qkv) {
    extern __shared__ __align__(16) char dsm[];
    const uint32_t sb = smem_u32(dsm);
    float* sXp = (float*)dsm;                       // stride 132
    __nv_bfloat16* sDb = (__nv_bfloat16*)(dsm + 39936);
    uint32_t* sAw = (uint32_t*)(dsm + 65280);
    const uint32_t sAa = sb + 65280;

    const int tid = threadIdx.x;
    const int m0 = blockIdx.x * 128;
    const int bb = m0 >> 14, ss0 = m0 & 16383;

    // ---- stage x (planar) channel-major into sXp ----
#pragma unroll
    for (int it = 0; it < 12; it++) {               // 3072 x 16B
        int u = it * 256 + tid;
        int c = u >> 5, q = u & 31;
        cpa16(sb + (uint32_t)(c * 528 + q * 16),
              x + (((size_t)(bb * 96 + c)) << 14) + ss0 + q * 4);
    }
    cp_commit(); cp_wait0();
    __syncthreads();

    // ---- LN1: two threads per pixel ----
    {
        const int px = tid >> 1, half = tid & 1;
        float sum = 0.f, sq = 0.f;
#pragma unroll
        for (int i = 0; i < 48; i++) {
            float v = sXp[(half * 48 + i) * 132 + px];
            sum += v;
            sq = fmaf(v, v, sq);
        }
        sum += __shfl_xor_sync(0xffffffffu, sum, 1);
        sq  += __shfl_xor_sync(0xffffffffu, sq, 1);
        float mu = sum * (1.f / 96.f);
        float rs = rsqrtf(sq * (1.f / 96.f) - mu * mu + 1e-5f);
#pragma unroll
        for (int i = 0; i < 24; i++) {
            int c = half * 48 + 2 * i;
            float a0 = (sXp[c * 132 + px] - mu) * rs * __ldg(lnw + c)
                     + __ldg(lnb + c);
            float a1 = (sXp[(c + 1) * 132 + px] - mu) * rs * __ldg(lnw + c + 1)
                     + __ldg(lnb + c + 1);
            sAw[px * 52 + half * 24 + i] = packbf(a0, a1);
        }
    }
    __syncthreads();                                // sXp dead; sW region live

    // ---- GEMM over 3 N-blocks, double-buffered weights ----
    const int lane = tid & 31;
    const int wid = tid >> 5;
    const int wr = wid >> 2, wc = wid & 3;
    const int g = lane >> 2, tig = lane & 3;

    uint32_t aAddr[4];
#pragma unroll
    for (int i = 0; i < 4; i++)
        aAddr[i] = sAa + (uint32_t)((wr * 64 + i * 16 + (lane & 15)) * 208
                                    + (lane >> 4) * 16);
    uint32_t bA01, bA2;
    bfrag_addrs(wc, lane, bA01, bA2);

    // preload nb0 weights into buf0
    for (int u = tid; u < 1152; u += 256) {
        int rr = u / 12, cc = u - rr * 12;
        cpa16(sb + (uint32_t)(rr * 208 + cc * 16), wq + rr * 96 + cc * 8);
    }
    cp_commit();

#pragma unroll 1
    for (int nb = 0; nb < 3; nb++) {
        cp_wait0();
        __syncthreads();
        if (nb < 2) {                                // prefetch nb+1
            const __nv_bfloat16* Wn = wq + (size_t)(nb + 1) * 9216;
            uint32_t dst = sb + (uint32_t)(((nb + 1) & 1) * 19968);
            for (int u = tid; u < 1152; u += 256) {
                int rr = u / 12, cc = u - rr * 12;
                cpa16(dst + (uint32_t)(rr * 208 + cc * 16), Wn + rr * 96 + cc * 8);
            }
            cp_commit();
        }
        const uint32_t wb = sb + (uint32_t)((nb & 1) * 19968);

        float acc[4][3][4];
#pragma unroll
        for (int i = 0; i < 4; i++)
#pragma unroll
            for (int j = 0; j < 3; j++)
#pragma unroll
                for (int q = 0; q < 4; q++) acc[i][j][q] = 0.f;

#pragma unroll
        for (int ks = 0; ks < 6; ks++) {
            uint32_t a[4][4], b01[4], b2x[2];
            LDSM4(b01[0], b01[1], b01[2], b01[3], wb + bA01 + (uint32_t)(ks * 32));
            LDSM2(b2x[0], b2x[1], wb + bA2 + (uint32_t)(ks * 32));
#pragma unroll
            for (int i = 0; i < 4; i++)
                LDSM4(a[i][0], a[i][1], a[i][2], a[i][3],
                      aAddr[i] + (uint32_t)(ks * 32));
#pragma unroll
            for (int i = 0; i < 4; i++) {
                mma16(acc[i][0], a[i], b01);
                mma16(acc[i][1], a[i], b01 + 2);
                mma16(acc[i][2], a[i], b2x);
            }
        }

        // stage D bf16 [col][132]
#pragma unroll
        for (int i = 0; i < 4; i++)
#pragma unroll
            for (int j = 0; j < 3; j++) {
                int row = wr * 64 + i * 16 + g;
                int col = wc * 24 + j * 8 + 2 * tig;
                sDb[col * 132 + row]           = __float2bfloat16_rn(acc[i][j][0]);
                sDb[(col + 1) * 132 + row]     = __float2bfloat16_rn(acc[i][j][1]);
                sDb[col * 132 + row + 8]       = __float2bfloat16_rn(acc[i][j][2]);
                sDb[(col + 1) * 132 + row + 8] = __float2bfloat16_rn(acc[i][j][3]);
            }
        __syncthreads();
        const uint32_t* sDu = (const uint32_t*)sDb;
#pragma unroll
        for (int u = tid; u < 6144; u += 256) {
            int col = u >> 6, q = u & 63;
            ((uint32_t*)(qkv + (((size_t)(nb * 96 + col)) << 17) + m0))[q]
                = sDu[col * 66 + q];
        }
        __syncthreads();
    }
}

// ================= dilated attention (packed ch-pairs) =================
__global__ __launch_bounds__(256)
void attn_kernel(const __nv_bfloat16* __restrict__ qkvp,
                 __nv_bfloat16* __restrict__ attn) {
    extern __shared__ __align__(16) uint32_t sm32[];
    const int tid = threadIdx.x;
    const int b = blockIdx.x >> 6;
    const int h0 = (blockIdx.x & 63) << 1;
    const int hd = blockIdx.y;
    const int grp = hd >> 1;
    const int dil = grp + 1;
    const int cb = grp * 32 + (hd & 1) * 16;
    const int nr = 2 + 2 * dil;

    {
        float4 z = make_float4(0.f, 0.f, 0.f, 0.f);
        float4* smv = (float4*)sm32;
#pragma unroll
        for (int i = 0; i < 18; i++) smv[i * 256 + tid] = z;
    }
    __syncthreads();

    const int baseh = h0 - dil;
    for (int u = tid; u < (nr << 7); u += 256) {
        int q8 = u & 15, seg = u >> 4;
        int cp = seg / nr, row = seg - cp * nr;
        int hr = baseh + row;
        if ((unsigned)hr < 128u) {
            size_t gofs = ((size_t)b << 14) + (hr << 7) + q8 * 8;
            uint4 k0 = *(const uint4*)(qkvp + (((size_t)(96 + cb + 2 * cp)) << 17) + gofs);
            uint4 k1 = *(const uint4*)(qkvp + (((size_t)(97 + cb + 2 * cp)) << 17) + gofs);
            uint4 v0 = *(const uint4*)(qkvp + (((size_t)(192 + cb + 2 * cp)) << 17) + gofs);
            uint4 v1 = *(const uint4*)(qkvp + (((size_t)(193 + cb + 2 * cp)) << 17) + gofs);
            int di = cp * 1152 + row * 144 + 8 + q8 * 8;
            uint4 o;
            o.x = __byte_perm(k0.x, k1.x, 0x5410); o.y = __byte_perm(k0.x, k1.x, 0x7632);
            o.z = __byte_perm(k0.y, k1.y, 0x5410); o.w = __byte_perm(k0.y, k1.y, 0x7632);
            *(uint4*)(sm32 + di) = o;
            o.x = __byte_perm(k0.z, k1.z, 0x5410); o.y = __byte_perm(k0.z, k1.z, 0x7632);
            o.z = __byte_perm(k0.w, k1.w, 0x5410); o.w = __byte_perm(k0.w, k1.w, 0x7632);
            *(uint4*)(sm32 + di + 4) = o;
            o.x = __byte_perm(v0.x, v1.x, 0x5410); o.y = __byte_perm(v0.x, v1.x, 0x7632);
            o.z = __byte_perm(v0.y, v1.y, 0x5410); o.w = __byte_perm(v0.y, v1.y, 0x7632);
            *(uint4*)(sm32 + di + 9216) = o;
            o.x = __byte_perm(v0.z, v1.z, 0x5410); o.y = __byte_perm(v0.z, v1.z, 0x7632);
            o.z = __byte_perm(v0.w, v1.w, 0x5410); o.w = __byte_perm(v0.w, v1.w, 0x7632);
            *(uint4*)(sm32 + di + 9220) = o;
        }
    }
    __syncthreads();

    const int r = tid >> 7, w = tid & 127;
    const size_t p = ((size_t)b << 14) + ((size_t)(h0 + r) << 7) + w;

    float ql[8], qh[8];
#pragma unroll
    for (int cp = 0; cp < 8; cp++) {
        ql[cp] = __bfloat162float(qkvp[(((size_t)(cb + 2 * cp)) << 17) + p]);
        qh[cp] = __bfloat162float(qkvp[(((size_t)(cb + 2 * cp + 1)) << 17) + p]);
    }

    float sc[9];
#pragma unroll
    for (int i = 0; i < 3; i++)
#pragma unroll
        for (int j = 0; j < 3; j++) {
            int base = (r + i * dil) * 144 + (8 + w + (j - 1) * dil);
            float d = 0.f;
#pragma unroll
            for (int cp = 0; cp < 8; cp++) {
                uint32_t u = sm32[cp * 1152 + base];
                d = fmaf(ql[cp], bflo(u), d);
                d = fmaf(qh[cp], bfhi(u), d);
            }
            sc[i * 3 + j] = d * 0.25f;
        }

    float mx = sc[0];
#pragma unroll
    for (int k = 1; k < 9; k++) mx = fmaxf(mx, sc[k]);
    float ssum = 0.f;
#pragma unroll
    for (int k = 0; k < 9; k++) { sc[k] = __expf(sc[k] - mx); ssum += sc[k]; }
    float inv = 1.f / ssum;

    float ol[8], oh[8];
#pragma unroll
    for (int cp = 0; cp < 8; cp++) { ol[cp] = 0.f; oh[cp] = 0.f; }
#pragma unroll
    for (int i = 0; i < 3; i++)
#pragma unroll
        for (int j = 0; j < 3; j++) {
            float wgt = sc[i * 3 + j] * inv;
            int base = 9216 + (r + i * dil) * 144 + (8 + w + (j - 1) * dil);
#pragma unroll
            for (int cp = 0; cp < 8; cp++) {
                uint32_t u = sm32[cp * 1152 + base];
                ol[cp] = fmaf(wgt, bflo(u), ol[cp]);
                oh[cp] = fmaf(wgt, bfhi(u), oh[cp]);
            }
        }

    __syncthreads();
#pragma unroll
    for (int cp = 0; cp < 8; cp++)
        sm32[tid * 17 + cp] = packbf(ol[cp], oh[cp]);
    __syncthreads();
    const size_t p0 = ((size_t)b << 14) + ((size_t)h0 << 7);
#pragma unroll
    for (int u = tid; u < 2048; u += 256) {
        int row = u >> 3, wq = u & 7;
        ((uint32_t*)(attn + (p0 + row) * 96 + cb))[wq] = sm32[row * 17 + wq];
    }
}

// ================= mega-fused proj+res+LN2+MLP, M=64 tile, 2 CTAs/SM ========
// SMEM map (108288 B total -> 2 CTAs/SM):
//   sX  fp32 [64][97]  @0      24832   (x1; final residual)
//   sH  bf16 [64][392] @24832  50176   (h1; also fp32 [64][97] epi staging)
//   sA  bf16 [64][104] @75008  13312   (A tile: attn, then LN2 out)
//   sW  [96][104] bf16 @88320  19968   (single-buffered weights)
#define M_SZ 108288

__global__ __launch_bounds__(256, 2)
void k_pm(const __nv_bfloat16* __restrict__ attn,
          const __nv_bfloat16* __restrict__ wp, const float* __restrict__ pb,
          const float* __restrict__ x,
          const __nv_bfloat16* __restrict__ w1, const float* __restrict__ b1,
          const __nv_bfloat16* __restrict__ w2, const float* __restrict__ b2,
          const float* __restrict__ lnw, const float* __restrict__ lnb,
          float* __restrict__ out) {
    extern __shared__ __align__(16) char dsm[];
    const uint32_t sb = smem_u32(dsm);
    float* sX = (float*)dsm;
    float* sHf = (float*)(dsm + 24832);
    uint32_t* sHu = (uint32_t*)(dsm + 24832);
    uint32_t* sAw = (uint32_t*)(dsm + 75008);
    const uint32_t sHa = sb + 24832;
    const uint32_t sAa = sb + 75008;
    const uint32_t sWa = sb + 88320;

    const int tid = threadIdx.x;
    const int lane = tid & 31;
    const int wid = tid >> 5;                        // 0..7
    const int wr = wid >> 2, wc = wid & 3;           // 2x4 warps
    const int g = lane >> 2, tig = lane & 3;
    const int m0 = blockIdx.x * 64;
    const int bb = m0 >> 14, ss0 = m0 & 16383;

    uint32_t aAddr[2], hAddr[2];
#pragma unroll
    for (int i = 0; i < 2; i++) {
        int row = wr * 32 + i * 16 + (lane & 15);
        aAddr[i] = sAa + (uint32_t)(row * 208 + (lane >> 4) * 16);
        hAddr[i] = sHa + (uint32_t)(row * 784 + (lane >> 4) * 16);
    }
    uint32_t bA01, bA2;
    bfrag_addrs(wc, lane, bA01, bA2);

    // ---- load attn tile (64x96) + proj weights ----
    const __nv_bfloat16* Ab = attn + (size_t)m0 * 96;
#pragma unroll
    for (int it = 0; it < 3; it++) {                 // 768 x 16B
        int u = it * 256 + tid;
        int rr = u / 12, cc = u - rr * 12;
        cpa16(sAa + (uint32_t)(rr * 208 + cc * 16), Ab + (size_t)rr * 96 + cc * 8);
    }
    for (int u = tid; u < 1152; u += 256) {
        int rr = u / 12, cc = u - rr * 12;
        cpa16(sWa + (uint32_t)(rr * 208 + cc * 16), wp + rr * 96 + cc * 8);
    }
    cp_commit(); cp_wait0();
    __syncthreads();

    // ---- proj mma ----
    float acc[2][3][4];
#pragma unroll
    for (int i = 0; i < 2; i++)
#pragma unroll
        for (int j = 0; j < 3; j++)
#pragma unroll
            for (int q = 0; q < 4; q++) acc[i][j][q] = 0.f;
#pragma unroll
    for (int ks = 0; ks < 6; ks++) {
        uint32_t a[2][4], b01[4], b2x[2];
        LDSM4(b01[0], b01[1], b01[2], b01[3], sWa + bA01 + (uint32_t)(ks * 32));
        LDSM2(b2x[0], b2x[1], sWa + bA2 + (uint32_t)(ks * 32));
#pragma unroll
        for (int i = 0; i < 2; i++)
            LDSM4(a[i][0], a[i][1], a[i][2], a[i][3],
                  aAddr[i] + (uint32_t)(ks * 32));
#pragma unroll
        for (int i = 0; i < 2; i++) {
            mma16(acc[i][0], a[i], b01);
            mma16(acc[i][1], a[i], b01 + 2);
            mma16(acc[i][2], a[i], b2x);
        }
    }

    // ---- x1 = projD + bias directly into sX ----
#pragma unroll
    for (int i = 0; i < 2; i++)
#pragma unroll
        for (int j = 0; j < 3; j++) {
            int row = wr * 32 + i * 16 + g;
            int col = wc * 24 + j * 8 + 2 * tig;
            float bi0 = __ldg(pb + col), bi1 = __ldg(pb + col + 1);
            sX[row * 97 + col]           = acc[i][j][0] + bi0;
            sX[row * 97 + col + 1]       = acc[i][j][1] + bi1;
            sX[(row + 8) * 97 + col]     = acc[i][j][2] + bi0;
            sX[(row + 8) * 97 + col + 1] = acc[i][j][3] + bi1;
        }
    __syncthreads();

    // ---- += x (planar, coalesced) ----
#pragma unroll
    for (int u = tid; u < 6144; u += 256) {
        int col = u >> 6, px = u & 63;
        sX[px * 97 + col] += __ldg(x + (((size_t)(bb * 96 + col)) << 14) + ss0 + px);
    }
    __syncthreads();

    // ---- LN2: 4 threads per pixel (64 px x 4 = 256) ----
    {
        const int px = tid >> 2, q = tid & 3;
        const float* xr = sX + px * 97 + q * 24;
        float sum = 0.f, sq = 0.f;
#pragma unroll
        for (int i = 0; i < 24; i++) {
            float v = xr[i];
            sum += v;
            sq = fmaf(v, v, sq);
        }
        sum += __shfl_xor_sync(0xffffffffu, sum, 1);
        sq  += __shfl_xor_sync(0xffffffffu, sq, 1);
        sum += __shfl_xor_sync(0xffffffffu, sum, 2);
        sq  += __shfl_xor_sync(0xffffffffu, sq, 2);
        float mu = sum * (1.f / 96.f);
        float rs = rsqrtf(sq * (1.f / 96.f) - mu * mu + 1e-5f);
#pragma unroll
        for (int i = 0; i < 12; i++) {
            int c = q * 24 + 2 * i;
            float a0 = (xr[2 * i] - mu) * rs * __ldg(lnw + c) + __ldg(lnb + c);
            float a1 = (xr[2 * i + 1] - mu) * rs * __ldg(lnw + c + 1)
                     + __ldg(lnb + c + 1);
            sAw[px * 52 + q * 12 + i] = packbf(a0, a1);
        }
    }

    // ---- fc1 + GELU -> sH (single weight buffer; 2 CTAs/SM hide latency) ----
#pragma unroll 1
    for (int nb = 0; nb < 4; nb++) {
        __syncthreads();                             // prior sW reads done
        const __nv_bfloat16* Wn = w1 + (size_t)nb * 9216;
        for (int u = tid; u < 1152; u += 256) {
            int rr = u / 12, cc = u - rr * 12;
            cpa16(sWa + (uint32_t)(rr * 208 + cc * 16), Wn + rr * 96 + cc * 8);
        }
        cp_commit(); cp_wait0();
        __syncthreads();

        float a1c[2][3][4];
#pragma unroll
        for (int i = 0; i < 2; i++)
#pragma unroll
            for (int j = 0; j < 3; j++)
#pragma unroll
                for (int q = 0; q < 4; q++) a1c[i][j][q] = 0.f;
#pragma unroll
        for (int ks = 0; ks < 6; ks++) {
            uint32_t a[2][4], b01[4], b2x[2];
            LDSM4(b01[0], b01[1], b01[2], b01[3], sWa + bA01 + (uint32_t)(ks * 32));
            LDSM2(b2x[0], b2x[1], sWa + bA2 + (uint32_t)(ks * 32));
#pragma unroll
            for (int i = 0; i < 2; i++)
                LDSM4(a[i][0], a[i][1], a[i][2], a[i][3],
                      aAddr[i] + (uint32_t)(ks * 32));
#pragma unroll
            for (int i = 0; i < 2; i++) {
                mma16(a1c[i][0], a[i], b01);
                mma16(a1c[i][1], a[i], b01 + 2);
                mma16(a1c[i][2], a[i], b2x);
            }
        }
#pragma unroll
        for (int i = 0; i < 2; i++)
#pragma unroll
            for (int j = 0; j < 3; j++) {
                int row = wr * 32 + i * 16 + g;
                int col = wc * 24 + j * 8 + 2 * tig;
                float bi0 = __ldg(b1 + nb * 96 + col);
                float bi1 = __ldg(b1 + nb * 96 + col + 1);
                float t0 = gelu_f(a1c[i][j][0] + bi0);
                float t1 = gelu_f(a1c[i][j][1] + bi1);
                float t2 = gelu_f(a1c[i][j][2] + bi0);
                float t3 = gelu_f(a1c[i][j][3] + bi1);
                sHu[(row * 392 + nb * 96 + col) >> 1]       = packbf(t0, t1);
                sHu[((row + 8) * 392 + nb * 96 + col) >> 1] = packbf(t2, t3);
            }
    }

    // ---- fc2: 4 K-chunks from sH ----
    float acc2[2][3][4];
#pragma unroll
    for (int i = 0; i < 2; i++)
#pragma unroll
        for (int j = 0; j < 3; j++)
#pragma unroll
            for (int q = 0; q < 4; q++) acc2[i][j][q] = 0.f;

#pragma unroll 1
    for (int kc = 0; kc < 4; kc++) {
        __syncthreads();                             // prior sW reads done
        for (int u = tid; u < 1152; u += 256) {
            int rr = u / 12, cc = u - rr * 12;
            cpa16(sWa + (uint32_t)(rr * 208 + cc * 16),
                  w2 + rr * 384 + kc * 96 + cc * 8);
        }
        cp_commit(); cp_wait0();
        __syncthreads();

#pragma unroll
        for (int ks = 0; ks < 6; ks++) {
            uint32_t a[2][4], b01[4], b2x[2];
            LDSM4(b01[0], b01[1], b01[2], b01[3], sWa + bA01 + (uint32_t)(ks * 32));
            LDSM2(b2x[0], b2x[1], sWa + bA2 + (uint32_t)(ks * 32));
#pragma unroll
            for (int i = 0; i < 2; i++)
                LDSM4(a[i][0], a[i][1], a[i][2], a[i][3],
                      hAddr[i] + (uint32_t)(kc * 192 + ks * 32));
#pragma unroll
            for (int i = 0; i < 2; i++) {
                mma16(acc2[i][0], a[i], b01);
                mma16(acc2[i][1], a[i], b01 + 2);
                mma16(acc2[i][2], a[i], b2x);
            }
        }
    }
    __syncthreads();                                 // all fc2 sH reads done

    // ---- epilogue: stage 96 cols fp32 into sH region, single pass ----
#pragma unroll
    for (int i = 0; i < 2; i++)
#pragma unroll
        for (int j = 0; j < 3; j++) {
            int row = wr * 32 + i * 16 + g;
            int col = wc * 24 + j * 8 + 2 * tig;
            sHf[row * 97 + col]           = acc2[i][j][0];
            sHf[row * 97 + col + 1]       = acc2[i][j][1];
            sHf[(row + 8) * 97 + col]     = acc2[i][j][2];
            sHf[(row + 8) * 97 + col + 1] = acc2[i][j][3];
        }
    __syncthreads();
#pragma unroll
    for (int u = tid; u < 6144; u += 256) {
        int col = u >> 6, px = u & 63;
        float val = sHf[px * 97 + col] + __ldg(b2 + col) + sX[px * 97 + col];
        out[(((size_t)(bb * 96 + col)) << 14) + ss0 + px] = val;
    }
}

// ---------------- launch ----------------
extern "C" void kernel_launch(void* const* d_in, const int* in_sizes, int n_in,
                              void* d_out, int out_size) {
    (void)in_sizes; (void)n_in; (void)out_size;
    const float* x      = (const float*)d_in[0];
    const float* qkv_w  = (const float*)d_in[1];
    const float* proj_w = (const float*)d_in[2];
    const float* proj_b = (const float*)d_in[3];
    const float* ln1w   = (const float*)d_in[4];
    const float* ln1b   = (const float*)d_in[5];
    const float* ln2w   = (const float*)d_in[6];
    const float* ln2b   = (const float*)d_in[7];
    const float* fc1w   = (const float*)d_in[8];
    const float* fc1b   = (const float*)d_in[9];
    const float* fc2w   = (const float*)d_in[10];
    const float* fc2b   = (const float*)d_in[11];
    float* out = (float*)d_out;

    cudaFuncSetAttribute(k_ln1_qkv,
                         cudaFuncAttributeMaxDynamicSharedMemorySize, A_SZ);
    cudaFuncSetAttribute(attn_kernel,
                         cudaFuncAttributeMaxDynamicSharedMemorySize, 73728);
    cudaFuncSetAttribute(k_pm,
                         cudaFuncAttributeMaxDynamicSharedMemorySize, M_SZ);

    __nv_bfloat16 *pqkv, *pattn, *pwb;
    cudaGetSymbolAddress((void**)&pqkv, g_qkv);
    cudaGetSymbolAddress((void**)&pattn, g_attn);
    cudaGetSymbolAddress((void**)&pwb, g_wb);

    round_w<<<432, 256>>>(qkv_w, proj_w, fc1w, fc2w);
    k_ln1_qkv<<<PTOT / 128, 256, A_SZ>>>(x, pwb, ln1w, ln1b, pqkv);
    attn_kernel<<<dim3(512, 6), 256, 73728>>>(pqkv, pattn);
    k_pm<<<PTOT / 64, 256, M_SZ>>>(pattn, pwb + 27648, proj_b, x,
                                   pwb + 36864, fc1b, pwb + 73728, fc2b,
                                   ln2w, ln2b, out);
}

// round 10
// speedup vs baseline: 5.0238x; 1.0086x over previous
#include <cuda_runtime.h>
#include <cuda_bf16.h>
#include <cstdint>
#include <cstddef>

// ---------------- problem constants ----------------
#define HW    16384            // 128*128
#define PTOT  131072           // 8*128*128 = 1<<17

// ---------------- scratch (device globals; no allocation) ----------------
__device__ __align__(16) __nv_bfloat16 g_qkv [(size_t)PTOT * 288];  // PLANAR [288][P]
__device__ __align__(16) __nv_bfloat16 g_attn[(size_t)PTOT * 96];   // row-major P x 96
__device__ __align__(16) __nv_bfloat16 g_wb  [110592];              // bf16 weights

// ---------------- helpers ----------------
__device__ __forceinline__ uint32_t smem_u32(const void* p) {
    uint32_t a;
    asm("{ .reg .u64 t; cvta.to.shared.u64 t, %1; cvt.u32.u64 %0, t; }"
        : "=r"(a) : "l"(p));
    return a;
}
__device__ __forceinline__ void cpa16(uint32_t dst, const void* src) {
    asm volatile("cp.async.cg.shared.global [%0], [%1], 16;"
                 :: "r"(dst), "l"(src));
}
__device__ __forceinline__ void cp_commit() {
    asm volatile("cp.async.commit_group;" ::: "memory");
}
__device__ __forceinline__ void cp_wait0() {
    asm volatile("cp.async.wait_group 0;" ::: "memory");
}
#define LDSM4(r0, r1, r2, r3, addr) \
    asm volatile("ldmatrix.sync.aligned.m8n8.x4.shared.b16 {%0,%1,%2,%3}, [%4];" \
                 : "=r"(r0), "=r"(r1), "=r"(r2), "=r"(r3) : "r"(addr))
#define LDSM2(r0, r1, addr) \
    asm volatile("ldmatrix.sync.aligned.m8n8.x2.shared.b16 {%0,%1}, [%2];" \
                 : "=r"(r0), "=r"(r1) : "r"(addr))
__device__ __forceinline__ void mma16(float* d, const uint32_t* a,
                                      const uint32_t* b) {
    asm volatile(
        "mma.sync.aligned.m16n8k16.row.col.f32.bf16.bf16.f32 "
        "{%0,%1,%2,%3}, {%4,%5,%6,%7}, {%8,%9}, {%0,%1,%2,%3};"
        : "+f"(d[0]), "+f"(d[1]), "+f"(d[2]), "+f"(d[3])
        : "r"(a[0]), "r"(a[1]), "r"(a[2]), "r"(a[3]), "r"(b[0]), "r"(b[1]));
}
__device__ __forceinline__ uint32_t packbf(float a, float b) {
    __nv_bfloat162 p = __floats2bfloat162_rn(a, b);
    return *(uint32_t*)&p;
}
__device__ __forceinline__ float bflo(uint32_t u) {
    return __uint_as_float(u << 16);
}
__device__ __forceinline__ float bfhi(uint32_t u) {
    return __uint_as_float(u & 0xffff0000u);
}
// tanh-form GELU via hardware MUFU.TANH.
__device__ __forceinline__ float gelu_f(float t) {
    float u = 0.7978845608f * t * fmaf(t * t, 0.044715f, 1.0f);
    float th;
    asm("tanh.approx.f32 %0, %1;" : "=f"(th) : "f"(u));
    return 0.5f * t * (1.f + th);
}

// B-fragment ldmatrix relative addresses, row stride SB bytes.
// x4 covers j0(k0,k8)+j1(k0,k8); x2 covers j2(k0,k8).
template <int SB>
__device__ __forceinline__ void bfrag_addrs(int wc, int lane,
                                            uint32_t& bA01, uint32_t& bA2) {
    int rw = lane & 7;
    int hi16 = (lane >> 3) & 1;                // byte +16 = k 8..15
    bA01 = (uint32_t)((wc * 24 + ((lane >> 4) << 3) + rw) * SB + (hi16 << 4));
    bA2  = (uint32_t)((wc * 24 + 16 + rw) * SB + (hi16 << 4));
}

// ---------------- weight conversion fp32 -> bf16 ----------------
__global__ __launch_bounds__(256)
void round_w(const float* __restrict__ qkv, const float* __restrict__ proj,
             const float* __restrict__ fc1, const float* __restrict__ fc2) {
    int i = blockIdx.x * 256 + threadIdx.x;
    float v;
    if (i < 27648)        v = qkv[i];
    else if (i < 36864)   v = proj[i - 27648];
    else if (i < 73728)   v = fc1[i - 36864];
    else                  v = fc2[i - 73728];
    g_wb[i] = __float2bfloat16_rn(v);
}

// ================= fused LN1 + qkv GEMM (256 thr, 2 CTAs/SM) =================
// SMEM region R @0 (65280 B):
//   phase1: sXp fp32 [96][132] (channel-major x tile) = 50688
//   phase2: sW0 @0 (19968) | sW1 @19968 (19968) | sD bf16 [96][132] @39936
// sA bf16 [128][104] @65280 (26624).  Total 91904 (x2 = 183808, fits).
#define A_SZ 91904

__global__ __launch_bounds__(256, 2)
void k_ln1_qkv(const float* __restrict__ x, const __nv_bfloat16* __restrict__ wq,
               const float* __restrict__ lnw, const float* __restrict__ lnb,
               __nv_bfloat16* __restrict__ qkv) {
    extern __shared__ __align__(16) char dsm[];
    const uint32_t sb = smem_u32(dsm);
    float* sXp = (float*)dsm;                       // stride 132
    __nv_bfloat16* sDb = (__nv_bfloat16*)(dsm + 39936);
    uint32_t* sAw = (uint32_t*)(dsm + 65280);
    const uint32_t sAa = sb + 65280;

    const int tid = threadIdx.x;
    const int m0 = blockIdx.x * 128;
    const int bb = m0 >> 14, ss0 = m0 & 16383;

    // ---- stage x (planar) channel-major into sXp ----
#pragma unroll
    for (int it = 0; it < 12; it++) {               // 3072 x 16B
        int u = it * 256 + tid;
        int c = u >> 5, q = u & 31;
        cpa16(sb + (uint32_t)(c * 528 + q * 16),
              x + (((size_t)(bb * 96 + c)) << 14) + ss0 + q * 4);
    }
    cp_commit(); cp_wait0();
    __syncthreads();

    // ---- LN1: two threads per pixel ----
    {
        const int px = tid >> 1, half = tid & 1;
        float sum = 0.f, sq = 0.f;
#pragma unroll
        for (int i = 0; i < 48; i++) {
            float v = sXp[(half * 48 + i) * 132 + px];
            sum += v;
            sq = fmaf(v, v, sq);
        }
        sum += __shfl_xor_sync(0xffffffffu, sum, 1);
        sq  += __shfl_xor_sync(0xffffffffu, sq, 1);
        float mu = sum * (1.f / 96.f);
        float rs = rsqrtf(sq * (1.f / 96.f) - mu * mu + 1e-5f);
#pragma unroll
        for (int i = 0; i < 24; i++) {
            int c = half * 48 + 2 * i;
            float a0 = (sXp[c * 132 + px] - mu) * rs * __ldg(lnw + c)
                     + __ldg(lnb + c);
            float a1 = (sXp[(c + 1) * 132 + px] - mu) * rs * __ldg(lnw + c + 1)
                     + __ldg(lnb + c + 1);
            sAw[px * 52 + half * 24 + i] = packbf(a0, a1);
        }
    }
    __syncthreads();                                // sXp dead; sW region live

    // ---- GEMM over 3 N-blocks, double-buffered weights ----
    const int lane = tid & 31;
    const int wid = tid >> 5;
    const int wr = wid >> 2, wc = wid & 3;
    const int g = lane >> 2, tig = lane & 3;

    uint32_t aAddr[4];
#pragma unroll
    for (int i = 0; i < 4; i++)
        aAddr[i] = sAa + (uint32_t)((wr * 64 + i * 16 + (lane & 15)) * 208
                                    + (lane >> 4) * 16);
    uint32_t bA01, bA2;
    bfrag_addrs<208>(wc, lane, bA01, bA2);

    // preload nb0 weights into buf0
    for (int u = tid; u < 1152; u += 256) {
        int rr = u / 12, cc = u - rr * 12;
        cpa16(sb + (uint32_t)(rr * 208 + cc * 16), wq + rr * 96 + cc * 8);
    }
    cp_commit();

#pragma unroll 1
    for (int nb = 0; nb < 3; nb++) {
        cp_wait0();
        __syncthreads();
        if (nb < 2) {                                // prefetch nb+1
            const __nv_bfloat16* Wn = wq + (size_t)(nb + 1) * 9216;
            uint32_t dst = sb + (uint32_t)(((nb + 1) & 1) * 19968);
            for (int u = tid; u < 1152; u += 256) {
                int rr = u / 12, cc = u - rr * 12;
                cpa16(dst + (uint32_t)(rr * 208 + cc * 16), Wn + rr * 96 + cc * 8);
            }
            cp_commit();
        }
        const uint32_t wb = sb + (uint32_t)((nb & 1) * 19968);

        float acc[4][3][4];
#pragma unroll
        for (int i = 0; i < 4; i++)
#pragma unroll
            for (int j = 0; j < 3; j++)
#pragma unroll
                for (int q = 0; q < 4; q++) acc[i][j][q] = 0.f;

#pragma unroll
        for (int ks = 0; ks < 6; ks++) {
            uint32_t a[4][4], b01[4], b2x[2];
            LDSM4(b01[0], b01[1], b01[2], b01[3], wb + bA01 + (uint32_t)(ks * 32));
            LDSM2(b2x[0], b2x[1], wb + bA2 + (uint32_t)(ks * 32));
#pragma unroll
            for (int i = 0; i < 4; i++)
                LDSM4(a[i][0], a[i][1], a[i][2], a[i][3],
                      aAddr[i] + (uint32_t)(ks * 32));
#pragma unroll
            for (int i = 0; i < 4; i++) {
                mma16(acc[i][0], a[i], b01);
                mma16(acc[i][1], a[i], b01 + 2);
                mma16(acc[i][2], a[i], b2x);
            }
        }

        // stage D bf16 [col][132]
#pragma unroll
        for (int i = 0; i < 4; i++)
#pragma unroll
            for (int j = 0; j < 3; j++) {
                int row = wr * 64 + i * 16 + g;
                int col = wc * 24 + j * 8 + 2 * tig;
                sDb[col * 132 + row]           = __float2bfloat16_rn(acc[i][j][0]);
                sDb[(col + 1) * 132 + row]     = __float2bfloat16_rn(acc[i][j][1]);
                sDb[col * 132 + row + 8]       = __float2bfloat16_rn(acc[i][j][2]);
                sDb[(col + 1) * 132 + row + 8] = __float2bfloat16_rn(acc[i][j][3]);
            }
        __syncthreads();
        const uint32_t* sDu = (const uint32_t*)sDb;
#pragma unroll
        for (int u = tid; u < 6144; u += 256) {
            int col = u >> 6, q = u & 63;
            ((uint32_t*)(qkv + (((size_t)(nb * 96 + col)) << 17) + m0))[q]
                = sDu[col * 66 + q];
        }
        __syncthreads();
    }
}

// ================= dilated attention (packed ch-pairs) =================
__global__ __launch_bounds__(256)
void attn_kernel(const __nv_bfloat16* __restrict__ qkvp,
                 __nv_bfloat16* __restrict__ attn) {
    extern __shared__ __align__(16) uint32_t sm32[];
    const int tid = threadIdx.x;
    const int b = blockIdx.x >> 6;
    const int h0 = (blockIdx.x & 63) << 1;
    const int hd = blockIdx.y;
    const int grp = hd >> 1;
    const int dil = grp + 1;
    const int cb = grp * 32 + (hd & 1) * 16;
    const int nr = 2 + 2 * dil;

    {
        float4 z = make_float4(0.f, 0.f, 0.f, 0.f);
        float4* smv = (float4*)sm32;
#pragma unroll
        for (int i = 0; i < 18; i++) smv[i * 256 + tid] = z;
    }
    __syncthreads();

    const int baseh = h0 - dil;
    for (int u = tid; u < (nr << 7); u += 256) {
        int q8 = u & 15, seg = u >> 4;
        int cp = seg / nr, row = seg - cp * nr;
        int hr = baseh + row;
        if ((unsigned)hr < 128u) {
            size_t gofs = ((size_t)b << 14) + (hr << 7) + q8 * 8;
            uint4 k0 = *(const uint4*)(qkvp + (((size_t)(96 + cb + 2 * cp)) << 17) + gofs);
            uint4 k1 = *(const uint4*)(qkvp + (((size_t)(97 + cb + 2 * cp)) << 17) + gofs);
            uint4 v0 = *(const uint4*)(qkvp + (((size_t)(192 + cb + 2 * cp)) << 17) + gofs);
            uint4 v1 = *(const uint4*)(qkvp + (((size_t)(193 + cb + 2 * cp)) << 17) + gofs);
            int di = cp * 1152 + row * 144 + 8 + q8 * 8;
            uint4 o;
            o.x = __byte_perm(k0.x, k1.x, 0x5410); o.y = __byte_perm(k0.x, k1.x, 0x7632);
            o.z = __byte_perm(k0.y, k1.y, 0x5410); o.w = __byte_perm(k0.y, k1.y, 0x7632);
            *(uint4*)(sm32 + di) = o;
            o.x = __byte_perm(k0.z, k1.z, 0x5410); o.y = __byte_perm(k0.z, k1.z, 0x7632);
            o.z = __byte_perm(k0.w, k1.w, 0x5410); o.w = __byte_perm(k0.w, k1.w, 0x7632);
            *(uint4*)(sm32 + di + 4) = o;
            o.x = __byte_perm(v0.x, v1.x, 0x5410); o.y = __byte_perm(v0.x, v1.x, 0x7632);
            o.z = __byte_perm(v0.y, v1.y, 0x5410); o.w = __byte_perm(v0.y, v1.y, 0x7632);
            *(uint4*)(sm32 + di + 9216) = o;
            o.x = __byte_perm(v0.z, v1.z, 0x5410); o.y = __byte_perm(v0.z, v1.z, 0x7632);
            o.z = __byte_perm(v0.w, v1.w, 0x5410); o.w = __byte_perm(v0.w, v1.w, 0x7632);
            *(uint4*)(sm32 + di + 9220) = o;
        }
    }
    __syncthreads();

    const int r = tid >> 7, w = tid & 127;
    const size_t p = ((size_t)b << 14) + ((size_t)(h0 + r) << 7) + w;

    float ql[8], qh[8];
#pragma unroll
    for (int cp = 0; cp < 8; cp++) {
        ql[cp] = __bfloat162float(qkvp[(((size_t)(cb + 2 * cp)) << 17) + p]);
        qh[cp] = __bfloat162float(qkvp[(((size_t)(cb + 2 * cp + 1)) << 17) + p]);
    }

    float sc[9];
#pragma unroll
    for (int i = 0; i < 3; i++)
#pragma unroll
        for (int j = 0; j < 3; j++) {
            int base = (r + i * dil) * 144 + (8 + w + (j - 1) * dil);
            float d = 0.f;
#pragma unroll
            for (int cp = 0; cp < 8; cp++) {
                uint32_t u = sm32[cp * 1152 + base];
                d = fmaf(ql[cp], bflo(u), d);
                d = fmaf(qh[cp], bfhi(u), d);
            }
            sc[i * 3 + j] = d * 0.25f;
        }

    float mx = sc[0];
#pragma unroll
    for (int k = 1; k < 9; k++) mx = fmaxf(mx, sc[k]);
    float ssum = 0.f;
#pragma unroll
    for (int k = 0; k < 9; k++) { sc[k] = __expf(sc[k] - mx); ssum += sc[k]; }
    float inv = 1.f / ssum;

    float ol[8], oh[8];
#pragma unroll
    for (int cp = 0; cp < 8; cp++) { ol[cp] = 0.f; oh[cp] = 0.f; }
#pragma unroll
    for (int i = 0; i < 3; i++)
#pragma unroll
        for (int j = 0; j < 3; j++) {
            float wgt = sc[i * 3 + j] * inv;
            int base = 9216 + (r + i * dil) * 144 + (8 + w + (j - 1) * dil);
#pragma unroll
            for (int cp = 0; cp < 8; cp++) {
                uint32_t u = sm32[cp * 1152 + base];
                ol[cp] = fmaf(wgt, bflo(u), ol[cp]);
                oh[cp] = fmaf(wgt, bfhi(u), oh[cp]);
            }
        }

    __syncthreads();
#pragma unroll
    for (int cp = 0; cp < 8; cp++)
        sm32[tid * 17 + cp] = packbf(ol[cp], oh[cp]);
    __syncthreads();
    const size_t p0 = ((size_t)b << 14) + ((size_t)h0 << 7);
#pragma unroll
    for (int u = tid; u < 2048; u += 256) {
        int row = u >> 3, wq = u & 7;
        ((uint32_t*)(attn + (p0 + row) * 96 + cb))[wq] = sm32[row * 17 + wq];
    }
}

// ================= mega-fused proj+res+LN2+MLP, M=64, 2 CTAs/SM =============
// Half-chunk single-sync weight pipeline (two [96][56] bf16 buffers).
// SMEM map (109824 B -> 2 CTAs/SM):
//   sX  fp32 [64][97]  @0      24832   (x1; final residual)
//   sH  bf16 [64][392] @24832  50176   (h1; also fp32 [64][97] epi staging)
//   sA  bf16 [64][104] @75008  13312   (A tile: attn, then LN2 out)
//   sW0 [96][56] bf16  @88320  10752
//   sW1 [96][56] bf16  @99072  10752
#define M_SZ 109824

__global__ __launch_bounds__(256, 2)
void k_pm(const __nv_bfloat16* __restrict__ attn,
          const __nv_bfloat16* __restrict__ wp, const float* __restrict__ pb,
          const float* __restrict__ x,
          const __nv_bfloat16* __restrict__ w1, const float* __restrict__ b1,
          const __nv_bfloat16* __restrict__ w2, const float* __restrict__ b2,
          const float* __restrict__ lnw, const float* __restrict__ lnb,
          float* __restrict__ out) {
    extern __shared__ __align__(16) char dsm[];
    const uint32_t sb = smem_u32(dsm);
    float* sX = (float*)dsm;
    float* sHf = (float*)(dsm + 24832);
    uint32_t* sHu = (uint32_t*)(dsm + 24832);
    uint32_t* sAw = (uint32_t*)(dsm + 75008);
    const uint32_t sHa = sb + 24832;
    const uint32_t sAa = sb + 75008;
    const uint32_t sW0 = sb + 88320;
    const uint32_t sW1 = sb + 99072;

    const int tid = threadIdx.x;
    const int lane = tid & 31;
    const int wid = tid >> 5;                        // 0..7
    const int wr = wid >> 2, wc = wid & 3;           // 2x4 warps
    const int g = lane >> 2, tig = lane & 3;
    const int m0 = blockIdx.x * 64;
    const int bb = m0 >> 14, ss0 = m0 & 16383;

    uint32_t aAddr[2], hAddr[2];
#pragma unroll
    for (int i = 0; i < 2; i++) {
        int row = wr * 32 + i * 16 + (lane & 15);
        aAddr[i] = sAa + (uint32_t)(row * 208 + (lane >> 4) * 16);
        hAddr[i] = sHa + (uint32_t)(row * 784 + (lane >> 4) * 16);
    }
    uint32_t bA01, bA2;
    bfrag_addrs<112>(wc, lane, bA01, bA2);

    // issue one weight half: [96 rows][48 k-cols] from W(ld, col) -> buf
    auto issue_half = [&](const __nv_bfloat16* W, int ld, int col, uint32_t buf) {
#pragma unroll
        for (int it = 0; it < 3; it++) {
            int u = it * 256 + tid;
            if (u < 576) {
                int rr = u / 6, cc = u - rr * 6;
                cpa16(buf + (uint32_t)(rr * 112 + cc * 16),
                      W + (size_t)rr * ld + col + cc * 8);
            }
        }
        cp_commit();
    };

    // ---- initial: attn A-tile + proj half0 ----
    const __nv_bfloat16* Ab = attn + (size_t)m0 * 96;
#pragma unroll
    for (int it = 0; it < 3; it++) {                 // 768 x 16B
        int u = it * 256 + tid;
        int rr = u / 12, cc = u - rr * 12;
        cpa16(sAa + (uint32_t)(rr * 208 + cc * 16), Ab + (size_t)rr * 96 + cc * 8);
    }
    cp_commit();
    issue_half(wp, 96, 0, sW0);                      // proj h0

    float acc[2][3][4];
#pragma unroll
    for (int i = 0; i < 2; i++)
#pragma unroll
        for (int j = 0; j < 3; j++)
#pragma unroll
            for (int q = 0; q < 4; q++) acc[i][j][q] = 0.f;

    // half-mma macro body (reads 3 ks of one half)
#define HALF_MMA(ACC, ABASE0, ABASE1, WBUF, K0)                               \
    do {                                                                      \
        _Pragma("unroll")                                                     \
        for (int k = 0; k < 3; k++) {                                         \
            uint32_t a[2][4], b01[4], b2x[2];                                 \
            LDSM4(b01[0], b01[1], b01[2], b01[3],                             \
                  (WBUF) + bA01 + (uint32_t)(k * 32));                        \
            LDSM2(b2x[0], b2x[1], (WBUF) + bA2 + (uint32_t)(k * 32));         \
            LDSM4(a[0][0], a[0][1], a[0][2], a[0][3],                         \
                  (ABASE0) + (uint32_t)(((K0) + k) * 32));                    \
            LDSM4(a[1][0], a[1][1], a[1][2], a[1][3],                         \
                  (ABASE1) + (uint32_t)(((K0) + k) * 32));                    \
            _Pragma("unroll")                                                 \
            for (int i = 0; i < 2; i++) {                                     \
                mma16((ACC)[i][0], a[i], b01);                                \
                mma16((ACC)[i][1], a[i], b01 + 2);                            \
                mma16((ACC)[i][2], a[i], b2x);                                \
            }                                                                 \
        }                                                                     \
    } while (0)

    // ---- proj h0 ----
    cp_wait0(); __syncthreads();
    issue_half(wp, 96, 48, sW1);                     // proj h1
    HALF_MMA(acc, aAddr[0], aAddr[1], sW0, 0);
    // ---- proj h1 ----
    cp_wait0(); __syncthreads();
    issue_half(w1, 96, 0, sW0);                      // fc1 nb0 h0
    HALF_MMA(acc, aAddr[0], aAddr[1], sW1, 3);

    // ---- x1 = projD + bias into sX ----
#pragma unroll
    for (int i = 0; i < 2; i++)
#pragma unroll
        for (int j = 0; j < 3; j++) {
            int row = wr * 32 + i * 16 + g;
            int col = wc * 24 + j * 8 + 2 * tig;
            float bi0 = __ldg(pb + col), bi1 = __ldg(pb + col + 1);
            sX[row * 97 + col]           = acc[i][j][0] + bi0;
            sX[row * 97 + col + 1]       = acc[i][j][1] + bi1;
            sX[(row + 8) * 97 + col]     = acc[i][j][2] + bi0;
            sX[(row + 8) * 97 + col + 1] = acc[i][j][3] + bi1;
        }
    __syncthreads();

    // ---- += x (planar, coalesced) ----
#pragma unroll
    for (int u = tid; u < 6144; u += 256) {
        int col = u >> 6, px = u & 63;
        sX[px * 97 + col] += __ldg(x + (((size_t)(bb * 96 + col)) << 14) + ss0 + px);
    }
    __syncthreads();

    // ---- LN2: 4 threads per pixel -> sAw (proj reads of sA long done) ----
    {
        const int px = tid >> 2, q = tid & 3;
        const float* xr = sX + px * 97 + q * 24;
        float sum = 0.f, sq = 0.f;
#pragma unroll
        for (int i = 0; i < 24; i++) {
            float v = xr[i];
            sum += v;
            sq = fmaf(v, v, sq);
        }
        sum += __shfl_xor_sync(0xffffffffu, sum, 1);
        sq  += __shfl_xor_sync(0xffffffffu, sq, 1);
        sum += __shfl_xor_sync(0xffffffffu, sum, 2);
        sq  += __shfl_xor_sync(0xffffffffu, sq, 2);
        float mu = sum * (1.f / 96.f);
        float rs = rsqrtf(sq * (1.f / 96.f) - mu * mu + 1e-5f);
#pragma unroll
        for (int i = 0; i < 12; i++) {
            int c = q * 24 + 2 * i;
            float a0 = (xr[2 * i] - mu) * rs * __ldg(lnw + c) + __ldg(lnb + c);
            float a1 = (xr[2 * i + 1] - mu) * rs * __ldg(lnw + c + 1)
                     + __ldg(lnb + c + 1);
            sAw[px * 52 + q * 12 + i] = packbf(a0, a1);
        }
    }

    // ---- fc1 + GELU -> sH ----
#pragma unroll 1
    for (int nb = 0; nb < 4; nb++) {
        float a1c[2][3][4];
#pragma unroll
        for (int i = 0; i < 2; i++)
#pragma unroll
            for (int j = 0; j < 3; j++)
#pragma unroll
                for (int q = 0; q < 4; q++) a1c[i][j][q] = 0.f;

        // even half
        cp_wait0(); __syncthreads();
        issue_half(w1 + (size_t)nb * 9216, 96, 48, sW1);
        HALF_MMA(a1c, aAddr[0], aAddr[1], sW0, 0);
        // odd half
        cp_wait0(); __syncthreads();
        if (nb < 3) issue_half(w1 + (size_t)(nb + 1) * 9216, 96, 0, sW0);
        else        issue_half(w2, 384, 0, sW0);
        HALF_MMA(a1c, aAddr[0], aAddr[1], sW1, 3);

        // GELU + bias -> sH
#pragma unroll
        for (int i = 0; i < 2; i++)
#pragma unroll
            for (int j = 0; j < 3; j++) {
                int row = wr * 32 + i * 16 + g;
                int col = wc * 24 + j * 8 + 2 * tig;
                float bi0 = __ldg(b1 + nb * 96 + col);
                float bi1 = __ldg(b1 + nb * 96 + col + 1);
                float t0 = gelu_f(a1c[i][j][0] + bi0);
                float t1 = gelu_f(a1c[i][j][1] + bi1);
                float t2 = gelu_f(a1c[i][j][2] + bi0);
                float t3 = gelu_f(a1c[i][j][3] + bi1);
                sHu[(row * 392 + nb * 96 + col) >> 1]       = packbf(t0, t1);
                sHu[((row + 8) * 392 + nb * 96 + col) >> 1] = packbf(t2, t3);
            }
    }

    // ---- fc2: 4 K-chunks from sH ----
    float acc2[2][3][4];
#pragma unroll
    for (int i = 0; i < 2; i++)
#pragma unroll
        for (int j = 0; j < 3; j++)
#pragma unroll
            for (int q = 0; q < 4; q++) acc2[i][j][q] = 0.f;

#pragma unroll 1
    for (int kc = 0; kc < 4; kc++) {
        // even half
        cp_wait0(); __syncthreads();
        issue_half(w2, 384, kc * 96 + 48, sW1);
        HALF_MMA(acc2, hAddr[0] + (uint32_t)(kc * 192),
                       hAddr[1] + (uint32_t)(kc * 192), sW0, 0);
        // odd half
        cp_wait0(); __syncthreads();
        if (kc < 3) issue_half(w2, 384, (kc + 1) * 96, sW0);
        HALF_MMA(acc2, hAddr[0] + (uint32_t)(kc * 192),
                       hAddr[1] + (uint32_t)(kc * 192), sW1, 3);
    }
    __syncthreads();                                 // all fc2 sH reads done

    // ---- epilogue: stage 96 cols fp32 into sH region, single pass ----
#pragma unroll
    for (int i = 0; i < 2; i++)
#pragma unroll
        for (int j = 0; j < 3; j++) {
            int row = wr * 32 + i * 16 + g;
            int col = wc * 24 + j * 8 + 2 * tig;
            sHf[row * 97 + col]           = acc2[i][j][0];
            sHf[row * 97 + col + 1]       = acc2[i][j][1];
            sHf[(row + 8) * 97 + col]     = acc2[i][j][2];
            sHf[(row + 8) * 97 + col + 1] = acc2[i][j][3];
        }
    __syncthreads();
#pragma unroll
    for (int u = tid; u < 6144; u += 256) {
        int col = u >> 6, px = u & 63;
        float val = sHf[px * 97 + col] + __ldg(b2 + col) + sX[px * 97 + col];
        out[(((size_t)(bb * 96 + col)) << 14) + ss0 + px] = val;
    }
#undef HALF_MMA
}

// ---------------- launch ----------------
extern "C" void kernel_launch(void* const* d_in, const int* in_sizes, int n_in,
                              void* d_out, int out_size) {
    (void)in_sizes; (void)n_in; (void)out_size;
    const float* x      = (const float*)d_in[0];
    const float* qkv_w  = (const float*)d_in[1];
    const float* proj_w = (const float*)d_in[2];
    const float* proj_b = (const float*)d_in[3];
    const float* ln1w   = (const float*)d_in[4];
    const float* ln1b   = (const float*)d_in[5];
    const float* ln2w   = (const float*)d_in[6];
    const float* ln2b   = (const float*)d_in[7];
    const float* fc1w   = (const float*)d_in[8];
    const float* fc1b   = (const float*)d_in[9];
    const float* fc2w   = (const float*)d_in[10];
    const float* fc2b   = (const float*)d_in[11];
    float* out = (float*)d_out;

    cudaFuncSetAttribute(k_ln1_qkv,
                         cudaFuncAttributeMaxDynamicSharedMemorySize, A_SZ);
    cudaFuncSetAttribute(attn_kernel,
                         cudaFuncAttributeMaxDynamicSharedMemorySize, 73728);
    cudaFuncSetAttribute(k_pm,
                         cudaFuncAttributeMaxDynamicSharedMemorySize, M_SZ);

    __nv_bfloat16 *pqkv, *pattn, *pwb;
    cudaGetSymbolAddress((void**)&pqkv, g_qkv);
    cudaGetSymbolAddress((void**)&pattn, g_attn);
    cudaGetSymbolAddress((void**)&pwb, g_wb);

    round_w<<<432, 256>>>(qkv_w, proj_w, fc1w, fc2w);
    k_ln1_qkv<<<PTOT / 128, 256, A_SZ>>>(x, pwb, ln1w, ln1b, pqkv);
    attn_kernel<<<dim3(512, 6), 256, 73728>>>(pqkv, pattn);
    k_pm<<<PTOT / 64, 256, M_SZ>>>(pattn, pwb + 27648, proj_b, x,
                                   pwb + 36864, fc1b, pwb + 73728, fc2b,
                                   ln2w, ln2b, out);
}

// round 11
// speedup vs baseline: 5.1835x; 1.0318x over previous
#include <cuda_runtime.h>
#include <cuda_bf16.h>
#include <cstdint>
#include <cstddef>

// ---------------- problem constants ----------------
#define HW    16384            // 128*128
#define PTOT  131072           // 8*128*128 = 1<<17

// ---------------- scratch (device globals; no allocation) ----------------
__device__ __align__(16) __nv_bfloat16 g_qkv [(size_t)PTOT * 288];  // PLANAR [288][P]
__device__ __align__(16) __nv_bfloat16 g_attn[(size_t)PTOT * 96];   // row-major P x 96
__device__ __align__(16) __nv_bfloat16 g_wb  [110592];              // bf16 weights

// ---------------- helpers ----------------
__device__ __forceinline__ uint32_t smem_u32(const void* p) {
    uint32_t a;
    asm("{ .reg .u64 t; cvta.to.shared.u64 t, %1; cvt.u32.u64 %0, t; }"
        : "=r"(a) : "l"(p));
    return a;
}
__device__ __forceinline__ void cpa16(uint32_t dst, const void* src) {
    asm volatile("cp.async.cg.shared.global [%0], [%1], 16;"
                 :: "r"(dst), "l"(src));
}
__device__ __forceinline__ void cp_commit() {
    asm volatile("cp.async.commit_group;" ::: "memory");
}
__device__ __forceinline__ void cp_wait0() {
    asm volatile("cp.async.wait_group 0;" ::: "memory");
}
#define LDSM4(r0, r1, r2, r3, addr) \
    asm volatile("ldmatrix.sync.aligned.m8n8.x4.shared.b16 {%0,%1,%2,%3}, [%4];" \
                 : "=r"(r0), "=r"(r1), "=r"(r2), "=r"(r3) : "r"(addr))
#define LDSM2(r0, r1, addr) \
    asm volatile("ldmatrix.sync.aligned.m8n8.x2.shared.b16 {%0,%1}, [%2];" \
                 : "=r"(r0), "=r"(r1) : "r"(addr))
__device__ __forceinline__ void mma16(float* d, const uint32_t* a,
                                      const uint32_t* b) {
    asm volatile(
        "mma.sync.aligned.m16n8k16.row.col.f32.bf16.bf16.f32 "
        "{%0,%1,%2,%3}, {%4,%5,%6,%7}, {%8,%9}, {%0,%1,%2,%3};"
        : "+f"(d[0]), "+f"(d[1]), "+f"(d[2]), "+f"(d[3])
        : "r"(a[0]), "r"(a[1]), "r"(a[2]), "r"(a[3]), "r"(b[0]), "r"(b[1]));
}
__device__ __forceinline__ uint32_t packbf(float a, float b) {
    __nv_bfloat162 p = __floats2bfloat162_rn(a, b);
    return *(uint32_t*)&p;
}
__device__ __forceinline__ float bflo(uint32_t u) {
    return __uint_as_float(u << 16);
}
__device__ __forceinline__ float bfhi(uint32_t u) {
    return __uint_as_float(u & 0xffff0000u);
}
// tanh-form GELU via hardware MUFU.TANH.
__device__ __forceinline__ float gelu_f(float t) {
    float u = 0.7978845608f * t * fmaf(t * t, 0.044715f, 1.0f);
    float th;
    asm("tanh.approx.f32 %0, %1;" : "=f"(th) : "f"(u));
    return 0.5f * t * (1.f + th);
}

// B-fragment ldmatrix relative addresses, row stride SB bytes.
// x4 covers j0(k0,k8)+j1(k0,k8); x2 covers j2(k0,k8).
template <int SB>
__device__ __forceinline__ void bfrag_addrs(int wc, int lane,
                                            uint32_t& bA01, uint32_t& bA2) {
    int rw = lane & 7;
    int hi16 = (lane >> 3) & 1;                // byte +16 = k 8..15
    bA01 = (uint32_t)((wc * 24 + ((lane >> 4) << 3) + rw) * SB + (hi16 << 4));
    bA2  = (uint32_t)((wc * 24 + 16 + rw) * SB + (hi16 << 4));
}

// ---------------- weight conversion fp32 -> bf16 ----------------
__global__ __launch_bounds__(256)
void round_w(const float* __restrict__ qkv, const float* __restrict__ proj,
             const float* __restrict__ fc1, const float* __restrict__ fc2) {
    int i = blockIdx.x * 256 + threadIdx.x;
    float v;
    if (i < 27648)        v = qkv[i];
    else if (i < 36864)   v = proj[i - 27648];
    else if (i < 73728)   v = fc1[i - 36864];
    else                  v = fc2[i - 73728];
    g_wb[i] = __float2bfloat16_rn(v);
}

// ================= fused LN1 + qkv GEMM (256 thr, 2 CTAs/SM) =================
#define A_SZ 91904

__global__ __launch_bounds__(256, 2)
void k_ln1_qkv(const float* __restrict__ x, const __nv_bfloat16* __restrict__ wq,
               const float* __restrict__ lnw, const float* __restrict__ lnb,
               __nv_bfloat16* __restrict__ qkv) {
    extern __shared__ __align__(16) char dsm[];
    const uint32_t sb = smem_u32(dsm);
    float* sXp = (float*)dsm;                       // stride 132
    __nv_bfloat16* sDb = (__nv_bfloat16*)(dsm + 39936);
    uint32_t* sAw = (uint32_t*)(dsm + 65280);
    const uint32_t sAa = sb + 65280;

    const int tid = threadIdx.x;
    const int m0 = blockIdx.x * 128;
    const int bb = m0 >> 14, ss0 = m0 & 16383;

    // ---- stage x (planar) channel-major into sXp ----
#pragma unroll
    for (int it = 0; it < 12; it++) {               // 3072 x 16B
        int u = it * 256 + tid;
        int c = u >> 5, q = u & 31;
        cpa16(sb + (uint32_t)(c * 528 + q * 16),
              x + (((size_t)(bb * 96 + c)) << 14) + ss0 + q * 4);
    }
    cp_commit(); cp_wait0();
    __syncthreads();

    // ---- LN1: two threads per pixel ----
    {
        const int px = tid >> 1, half = tid & 1;
        float sum = 0.f, sq = 0.f;
#pragma unroll
        for (int i = 0; i < 48; i++) {
            float v = sXp[(half * 48 + i) * 132 + px];
            sum += v;
            sq = fmaf(v, v, sq);
        }
        sum += __shfl_xor_sync(0xffffffffu, sum, 1);
        sq  += __shfl_xor_sync(0xffffffffu, sq, 1);
        float mu = sum * (1.f / 96.f);
        float rs = rsqrtf(sq * (1.f / 96.f) - mu * mu + 1e-5f);
#pragma unroll
        for (int i = 0; i < 24; i++) {
            int c = half * 48 + 2 * i;
            float a0 = (sXp[c * 132 + px] - mu) * rs * __ldg(lnw + c)
                     + __ldg(lnb + c);
            float a1 = (sXp[(c + 1) * 132 + px] - mu) * rs * __ldg(lnw + c + 1)
                     + __ldg(lnb + c + 1);
            sAw[px * 52 + half * 24 + i] = packbf(a0, a1);
        }
    }
    __syncthreads();                                // sXp dead; sW region live

    // ---- GEMM over 3 N-blocks, double-buffered weights ----
    const int lane = tid & 31;
    const int wid = tid >> 5;
    const int wr = wid >> 2, wc = wid & 3;
    const int g = lane >> 2, tig = lane & 3;

    uint32_t aAddr[4];
#pragma unroll
    for (int i = 0; i < 4; i++)
        aAddr[i] = sAa + (uint32_t)((wr * 64 + i * 16 + (lane & 15)) * 208
                                    + (lane >> 4) * 16);
    uint32_t bA01, bA2;
    bfrag_addrs<208>(wc, lane, bA01, bA2);

    // preload nb0 weights into buf0
    for (int u = tid; u < 1152; u += 256) {
        int rr = u / 12, cc = u - rr * 12;
        cpa16(sb + (uint32_t)(rr * 208 + cc * 16), wq + rr * 96 + cc * 8);
    }
    cp_commit();

#pragma unroll 1
    for (int nb = 0; nb < 3; nb++) {
        cp_wait0();
        __syncthreads();
        if (nb < 2) {                                // prefetch nb+1
            const __nv_bfloat16* Wn = wq + (size_t)(nb + 1) * 9216;
            uint32_t dst = sb + (uint32_t)(((nb + 1) & 1) * 19968);
            for (int u = tid; u < 1152; u += 256) {
                int rr = u / 12, cc = u - rr * 12;
                cpa16(dst + (uint32_t)(rr * 208 + cc * 16), Wn + rr * 96 + cc * 8);
            }
            cp_commit();
        }
        const uint32_t wb = sb + (uint32_t)((nb & 1) * 19968);

        float acc[4][3][4];
#pragma unroll
        for (int i = 0; i < 4; i++)
#pragma unroll
            for (int j = 0; j < 3; j++)
#pragma unroll
                for (int q = 0; q < 4; q++) acc[i][j][q] = 0.f;

#pragma unroll
        for (int ks = 0; ks < 6; ks++) {
            uint32_t a[4][4], b01[4], b2x[2];
            LDSM4(b01[0], b01[1], b01[2], b01[3], wb + bA01 + (uint32_t)(ks * 32));
            LDSM2(b2x[0], b2x[1], wb + bA2 + (uint32_t)(ks * 32));
#pragma unroll
            for (int i = 0; i < 4; i++)
                LDSM4(a[i][0], a[i][1], a[i][2], a[i][3],
                      aAddr[i] + (uint32_t)(ks * 32));
#pragma unroll
            for (int i = 0; i < 4; i++) {
                mma16(acc[i][0], a[i], b01);
                mma16(acc[i][1], a[i], b01 + 2);
                mma16(acc[i][2], a[i], b2x);
            }
        }

        // stage D bf16 [col][132]
#pragma unroll
        for (int i = 0; i < 4; i++)
#pragma unroll
            for (int j = 0; j < 3; j++) {
                int row = wr * 64 + i * 16 + g;
                int col = wc * 24 + j * 8 + 2 * tig;
                sDb[col * 132 + row]           = __float2bfloat16_rn(acc[i][j][0]);
                sDb[(col + 1) * 132 + row]     = __float2bfloat16_rn(acc[i][j][1]);
                sDb[col * 132 + row + 8]       = __float2bfloat16_rn(acc[i][j][2]);
                sDb[(col + 1) * 132 + row + 8] = __float2bfloat16_rn(acc[i][j][3]);
            }
        __syncthreads();
        const uint32_t* sDu = (const uint32_t*)sDb;
#pragma unroll
        for (int u = tid; u < 6144; u += 256) {
            int col = u >> 6, q = u & 63;
            ((uint32_t*)(qkv + (((size_t)(nb * 96 + col)) << 17) + m0))[q]
                = sDu[col * 66 + q];
        }
        __syncthreads();
    }
}

// ================= dilated attention (packed ch-pairs) =================
__global__ __launch_bounds__(256)
void attn_kernel(const __nv_bfloat16* __restrict__ qkvp,
                 __nv_bfloat16* __restrict__ attn) {
    extern __shared__ __align__(16) uint32_t sm32[];
    const int tid = threadIdx.x;
    const int b = blockIdx.x >> 6;
    const int h0 = (blockIdx.x & 63) << 1;
    const int hd = blockIdx.y;
    const int grp = hd >> 1;
    const int dil = grp + 1;
    const int cb = grp * 32 + (hd & 1) * 16;
    const int nr = 2 + 2 * dil;

    {
        float4 z = make_float4(0.f, 0.f, 0.f, 0.f);
        float4* smv = (float4*)sm32;
#pragma unroll
        for (int i = 0; i < 18; i++) smv[i * 256 + tid] = z;
    }
    __syncthreads();

    const int baseh = h0 - dil;
    for (int u = tid; u < (nr << 7); u += 256) {
        int q8 = u & 15, seg = u >> 4;
        int cp = seg / nr, row = seg - cp * nr;
        int hr = baseh + row;
        if ((unsigned)hr < 128u) {
            size_t gofs = ((size_t)b << 14) + (hr << 7) + q8 * 8;
            uint4 k0 = *(const uint4*)(qkvp + (((size_t)(96 + cb + 2 * cp)) << 17) + gofs);
            uint4 k1 = *(const uint4*)(qkvp + (((size_t)(97 + cb + 2 * cp)) << 17) + gofs);
            uint4 v0 = *(const uint4*)(qkvp + (((size_t)(192 + cb + 2 * cp)) << 17) + gofs);
            uint4 v1 = *(const uint4*)(qkvp + (((size_t)(193 + cb + 2 * cp)) << 17) + gofs);
            int di = cp * 1152 + row * 144 + 8 + q8 * 8;
            uint4 o;
            o.x = __byte_perm(k0.x, k1.x, 0x5410); o.y = __byte_perm(k0.x, k1.x, 0x7632);
            o.z = __byte_perm(k0.y, k1.y, 0x5410); o.w = __byte_perm(k0.y, k1.y, 0x7632);
            *(uint4*)(sm32 + di) = o;
            o.x = __byte_perm(k0.z, k1.z, 0x5410); o.y = __byte_perm(k0.z, k1.z, 0x7632);
            o.z = __byte_perm(k0.w, k1.w, 0x5410); o.w = __byte_perm(k0.w, k1.w, 0x7632);
            *(uint4*)(sm32 + di + 4) = o;
            o.x = __byte_perm(v0.x, v1.x, 0x5410); o.y = __byte_perm(v0.x, v1.x, 0x7632);
            o.z = __byte_perm(v0.y, v1.y, 0x5410); o.w = __byte_perm(v0.y, v1.y, 0x7632);
            *(uint4*)(sm32 + di + 9216) = o;
            o.x = __byte_perm(v0.z, v1.z, 0x5410); o.y = __byte_perm(v0.z, v1.z, 0x7632);
            o.z = __byte_perm(v0.w, v1.w, 0x5410); o.w = __byte_perm(v0.w, v1.w, 0x7632);
            *(uint4*)(sm32 + di + 9220) = o;
        }
    }
    __syncthreads();

    const int r = tid >> 7, w = tid & 127;
    const size_t p = ((size_t)b << 14) + ((size_t)(h0 + r) << 7) + w;

    float ql[8], qh[8];
#pragma unroll
    for (int cp = 0; cp < 8; cp++) {
        ql[cp] = __bfloat162float(qkvp[(((size_t)(cb + 2 * cp)) << 17) + p]);
        qh[cp] = __bfloat162float(qkvp[(((size_t)(cb + 2 * cp + 1)) << 17) + p]);
    }

    float sc[9];
#pragma unroll
    for (int i = 0; i < 3; i++)
#pragma unroll
        for (int j = 0; j < 3; j++) {
            int base = (r + i * dil) * 144 + (8 + w + (j - 1) * dil);
            float d = 0.f;
#pragma unroll
            for (int cp = 0; cp < 8; cp++) {
                uint32_t u = sm32[cp * 1152 + base];
                d = fmaf(ql[cp], bflo(u), d);
                d = fmaf(qh[cp], bfhi(u), d);
            }
            sc[i * 3 + j] = d * 0.25f;
        }

    float mx = sc[0];
#pragma unroll
    for (int k = 1; k < 9; k++) mx = fmaxf(mx, sc[k]);
    float ssum = 0.f;
#pragma unroll
    for (int k = 0; k < 9; k++) { sc[k] = __expf(sc[k] - mx); ssum += sc[k]; }
    float inv = 1.f / ssum;

    float ol[8], oh[8];
#pragma unroll
    for (int cp = 0; cp < 8; cp++) { ol[cp] = 0.f; oh[cp] = 0.f; }
#pragma unroll
    for (int i = 0; i < 3; i++)
#pragma unroll
        for (int j = 0; j < 3; j++) {
            float wgt = sc[i * 3 + j] * inv;
            int base = 9216 + (r + i * dil) * 144 + (8 + w + (j - 1) * dil);
#pragma unroll
            for (int cp = 0; cp < 8; cp++) {
                uint32_t u = sm32[cp * 1152 + base];
                ol[cp] = fmaf(wgt, bflo(u), ol[cp]);
                oh[cp] = fmaf(wgt, bfhi(u), oh[cp]);
            }
        }

    __syncthreads();
#pragma unroll
    for (int cp = 0; cp < 8; cp++)
        sm32[tid * 17 + cp] = packbf(ol[cp], oh[cp]);
    __syncthreads();
    const size_t p0 = ((size_t)b << 14) + ((size_t)h0 << 7);
#pragma unroll
    for (int u = tid; u < 2048; u += 256) {
        int row = u >> 3, wq = u & 7;
        ((uint32_t*)(attn + (p0 + row) * 96 + cb))[wq] = sm32[row * 17 + wq];
    }
}

// ================= mega-fused proj+res+LN2+MLP, interleaved fc1->fc2 ========
// 9 full-chunk phases, single-sync-per-phase double-buffered weights.
// SMEM map (91392 B -> 2 CTAs/SM):
//   sX  fp32 [64][97]   @0      24832  (x1; final residual)
//   sA  bf16 [64][104]  @24832  13312  (attn A-tile, then LN2 out)
//   sHs bf16 [64][104]  @38144  13312  (per-nb h1 block, fc2 A operand)
//   W0  bf16 [96][104]  @51456  19968  (proj / fc2 weights)
//   W1  bf16 [96][104]  @71424  19968  (fc1 weights)
//   epilogue staging fp32 [64][97] reuses W0+W1 region.
#define M_SZ 91392

__global__ __launch_bounds__(256, 2)
void k_pm(const __nv_bfloat16* __restrict__ attn,
          const __nv_bfloat16* __restrict__ wp, const float* __restrict__ pb,
          const float* __restrict__ x,
          const __nv_bfloat16* __restrict__ w1, const float* __restrict__ b1,
          const __nv_bfloat16* __restrict__ w2, const float* __restrict__ b2,
          const float* __restrict__ lnw, const float* __restrict__ lnb,
          float* __restrict__ out) {
    extern __shared__ __align__(16) char dsm[];
    const uint32_t sb = smem_u32(dsm);
    float* sX = (float*)dsm;
    uint32_t* sAw = (uint32_t*)(dsm + 24832);
    uint32_t* sHsU = (uint32_t*)(dsm + 38144);
    float* sEp = (float*)(dsm + 51456);              // epilogue staging
    const uint32_t sAa = sb + 24832;
    const uint32_t sHa = sb + 38144;
    const uint32_t W0 = sb + 51456;
    const uint32_t W1 = sb + 71424;

    const int tid = threadIdx.x;
    const int lane = tid & 31;
    const int wid = tid >> 5;                        // 0..7
    const int wr = wid >> 2, wc = wid & 3;           // 2x4 warps
    const int g = lane >> 2, tig = lane & 3;
    const int m0 = blockIdx.x * 64;
    const int bb = m0 >> 14, ss0 = m0 & 16383;

    uint32_t aAddr[2], hAddr[2];
#pragma unroll
    for (int i = 0; i < 2; i++) {
        int row = wr * 32 + i * 16 + (lane & 15);
        aAddr[i] = sAa + (uint32_t)(row * 208 + (lane >> 4) * 16);
        hAddr[i] = sHa + (uint32_t)(row * 208 + (lane >> 4) * 16);
    }
    uint32_t bA01, bA2;
    bfrag_addrs<208>(wc, lane, bA01, bA2);

    // issue one full weight chunk: [96 rows][96 k-cols] from W(ld, col0) -> buf
    auto issue_chunk = [&](const __nv_bfloat16* W, int ld, int col0,
                           uint32_t buf) {
        for (int u = tid; u < 1152; u += 256) {
            int rr = u / 12, cc = u - rr * 12;
            cpa16(buf + (uint32_t)(rr * 208 + cc * 16),
                  W + (size_t)rr * ld + col0 + cc * 8);
        }
        cp_commit();
    };

    // ---- L0: attn A-tile + proj weights (one group) ----
    const __nv_bfloat16* Ab = attn + (size_t)m0 * 96;
#pragma unroll
    for (int it = 0; it < 3; it++) {                 // 768 x 16B
        int u = it * 256 + tid;
        int rr = u / 12, cc = u - rr * 12;
        cpa16(sAa + (uint32_t)(rr * 208 + cc * 16), Ab + (size_t)rr * 96 + cc * 8);
    }
    issue_chunk(wp, 96, 0, W0);                      // commits A-tile too

    // full-chunk mma: 6 ks over one 96-K weight buffer
#define CHUNK_MMA(ACC, A0, A1, WBUF)                                          \
    do {                                                                      \
        _Pragma("unroll")                                                     \
        for (int ks = 0; ks < 6; ks++) {                                      \
            uint32_t a[2][4], b01[4], b2x[2];                                 \
            LDSM4(b01[0], b01[1], b01[2], b01[3],                             \
                  (WBUF) + bA01 + (uint32_t)(ks * 32));                       \
            LDSM2(b2x[0], b2x[1], (WBUF) + bA2 + (uint32_t)(ks * 32));        \
            LDSM4(a[0][0], a[0][1], a[0][2], a[0][3],                         \
                  (A0) + (uint32_t)(ks * 32));                                \
            LDSM4(a[1][0], a[1][1], a[1][2], a[1][3],                         \
                  (A1) + (uint32_t)(ks * 32));                                \
            _Pragma("unroll")                                                 \
            for (int i = 0; i < 2; i++) {                                     \
                mma16((ACC)[i][0], a[i], b01);                                \
                mma16((ACC)[i][1], a[i], b01 + 2);                            \
                mma16((ACC)[i][2], a[i], b2x);                                \
            }                                                                 \
        }                                                                     \
    } while (0)

    // ---- phase 0: proj (W0) ----
    float acc[2][3][4];
#pragma unroll
    for (int i = 0; i < 2; i++)
#pragma unroll
        for (int j = 0; j < 3; j++)
#pragma unroll
            for (int q = 0; q < 4; q++) acc[i][j][q] = 0.f;

    cp_wait0(); __syncthreads();
    issue_chunk(w1, 96, 0, W1);                      // L1: fc1 nb0
    CHUNK_MMA(acc, aAddr[0], aAddr[1], W0);

    // ---- x1 = projD + bias into sX ----
#pragma unroll
    for (int i = 0; i < 2; i++)
#pragma unroll
        for (int j = 0; j < 3; j++) {
            int row = wr * 32 + i * 16 + g;
            int col = wc * 24 + j * 8 + 2 * tig;
            float bi0 = __ldg(pb + col), bi1 = __ldg(pb + col + 1);
            sX[row * 97 + col]           = acc[i][j][0] + bi0;
            sX[row * 97 + col + 1]       = acc[i][j][1] + bi1;
            sX[(row + 8) * 97 + col]     = acc[i][j][2] + bi0;
            sX[(row + 8) * 97 + col + 1] = acc[i][j][3] + bi1;
        }
    __syncthreads();

    // ---- += x (planar, coalesced) ----
#pragma unroll
    for (int u = tid; u < 6144; u += 256) {
        int col = u >> 6, px = u & 63;
        sX[px * 97 + col] += __ldg(x + (((size_t)(bb * 96 + col)) << 14) + ss0 + px);
    }
    __syncthreads();

    // ---- LN2: 4 threads per pixel -> sA region (proj reads done) ----
    {
        const int px = tid >> 2, q = tid & 3;
        const float* xr = sX + px * 97 + q * 24;
        float sum = 0.f, sq = 0.f;
#pragma unroll
        for (int i = 0; i < 24; i++) {
            float v = xr[i];
            sum += v;
            sq = fmaf(v, v, sq);
        }
        sum += __shfl_xor_sync(0xffffffffu, sum, 1);
        sq  += __shfl_xor_sync(0xffffffffu, sq, 1);
        sum += __shfl_xor_sync(0xffffffffu, sum, 2);
        sq  += __shfl_xor_sync(0xffffffffu, sq, 2);
        float mu = sum * (1.f / 96.f);
        float rs = rsqrtf(sq * (1.f / 96.f) - mu * mu + 1e-5f);
#pragma unroll
        for (int i = 0; i < 12; i++) {
            int c = q * 24 + 2 * i;
            float a0 = (xr[2 * i] - mu) * rs * __ldg(lnw + c) + __ldg(lnb + c);
            float a1 = (xr[2 * i + 1] - mu) * rs * __ldg(lnw + c + 1)
                     + __ldg(lnb + c + 1);
            sAw[px * 52 + q * 12 + i] = packbf(a0, a1);
        }
    }
    // no sync here: next phase's sync publishes LN2 output

    // ---- interleaved fc1 -> fc2 per 96-col block ----
    float acc2[2][3][4];
#pragma unroll
    for (int i = 0; i < 2; i++)
#pragma unroll
        for (int j = 0; j < 3; j++)
#pragma unroll
            for (int q = 0; q < 4; q++) acc2[i][j][q] = 0.f;

#pragma unroll 1
    for (int nb = 0; nb < 4; nb++) {
        // -- fc1 phase (W1) --
        cp_wait0(); __syncthreads();
        issue_chunk(w2, 384, nb * 96, W0);           // fc2 weights for this nb
        float a1c[2][3][4];
#pragma unroll
        for (int i = 0; i < 2; i++)
#pragma unroll
            for (int j = 0; j < 3; j++)
#pragma unroll
                for (int q = 0; q < 4; q++) a1c[i][j][q] = 0.f;
        CHUNK_MMA(a1c, aAddr[0], aAddr[1], W1);

        // GELU + bias -> sHs (local cols 0..95)
#pragma unroll
        for (int i = 0; i < 2; i++)
#pragma unroll
            for (int j = 0; j < 3; j++) {
                int row = wr * 32 + i * 16 + g;
                int col = wc * 24 + j * 8 + 2 * tig;
                float bi0 = __ldg(b1 + nb * 96 + col);
                float bi1 = __ldg(b1 + nb * 96 + col + 1);
                float t0 = gelu_f(a1c[i][j][0] + bi0);
                float t1 = gelu_f(a1c[i][j][1] + bi1);
                float t2 = gelu_f(a1c[i][j][2] + bi0);
                float t3 = gelu_f(a1c[i][j][3] + bi1);
                sHsU[(row * 104 + col) >> 1]       = packbf(t0, t1);
                sHsU[((row + 8) * 104 + col) >> 1] = packbf(t2, t3);
            }

        // -- fc2 phase (W0) --
        cp_wait0(); __syncthreads();                 // publishes sHs + W0
        if (nb < 3)
            issue_chunk(w1 + (size_t)(nb + 1) * 9216, 96, 0, W1);
        CHUNK_MMA(acc2, hAddr[0], hAddr[1], W0);
    }
    __syncthreads();                                 // all W/sHs reads done

    // ---- epilogue: stage 96 cols fp32 into W region, single pass ----
#pragma unroll
    for (int i = 0; i < 2; i++)
#pragma unroll
        for (int j = 0; j < 3; j++) {
            int row = wr * 32 + i * 16 + g;
            int col = wc * 24 + j * 8 + 2 * tig;
            sEp[row * 97 + col]           = acc2[i][j][0];
            sEp[row * 97 + col + 1]       = acc2[i][j][1];
            sEp[(row + 8) * 97 + col]     = acc2[i][j][2];
            sEp[(row + 8) * 97 + col + 1] = acc2[i][j][3];
        }
    __syncthreads();
#pragma unroll
    for (int u = tid; u < 6144; u += 256) {
        int col = u >> 6, px = u & 63;
        float val = sEp[px * 97 + col] + __ldg(b2 + col) + sX[px * 97 + col];
        out[(((size_t)(bb * 96 + col)) << 14) + ss0 + px] = val;
    }
#undef CHUNK_MMA
}

// ---------------- launch ----------------
extern "C" void kernel_launch(void* const* d_in, const int* in_sizes, int n_in,
                              void* d_out, int out_size) {
    (void)in_sizes; (void)n_in; (void)out_size;
    const float* x      = (const float*)d_in[0];
    const float* qkv_w  = (const float*)d_in[1];
    const float* proj_w = (const float*)d_in[2];
    const float* proj_b = (const float*)d_in[3];
    const float* ln1w   = (const float*)d_in[4];
    const float* ln1b   = (const float*)d_in[5];
    const float* ln2w   = (const float*)d_in[6];
    const float* ln2b   = (const float*)d_in[7];
    const float* fc1w   = (const float*)d_in[8];
    const float* fc1b   = (const float*)d_in[9];
    const float* fc2w   = (const float*)d_in[10];
    const float* fc2b   = (const float*)d_in[11];
    float* out = (float*)d_out;

    cudaFuncSetAttribute(k_ln1_qkv,
                         cudaFuncAttributeMaxDynamicSharedMemorySize, A_SZ);
    cudaFuncSetAttribute(attn_kernel,
                         cudaFuncAttributeMaxDynamicSharedMemorySize, 73728);
    cudaFuncSetAttribute(k_pm,
                         cudaFuncAttributeMaxDynamicSharedMemorySize, M_SZ);

    __nv_bfloat16 *pqkv, *pattn, *pwb;
    cudaGetSymbolAddress((void**)&pqkv, g_qkv);
    cudaGetSymbolAddress((void**)&pattn, g_attn);
    cudaGetSymbolAddress((void**)&pwb, g_wb);

    round_w<<<432, 256>>>(qkv_w, proj_w, fc1w, fc2w);
    k_ln1_qkv<<<PTOT / 128, 256, A_SZ>>>(x, pwb, ln1w, ln1b, pqkv);
    attn_kernel<<<dim3(512, 6), 256, 73728>>>(pqkv, pattn);
    k_pm<<<PTOT / 64, 256, M_SZ>>>(pattn, pwb + 27648, proj_b, x,
                                   pwb + 36864, fc1b, pwb + 73728, fc2b,
                                   ln2w, ln2b, out);
}

// round 12
// speedup vs baseline: 5.3106x; 1.0245x over previous
#include <cuda_runtime.h>
#include <cuda_bf16.h>
#include <cstdint>
#include <cstddef>

// ---------------- problem constants ----------------
#define HW    16384            // 128*128
#define PTOT  131072           // 8*128*128 = 1<<17

// ---------------- scratch (device globals; no allocation) ----------------
__device__ __align__(16) __nv_bfloat16 g_qkv [(size_t)PTOT * 288];  // PLANAR [288][P]
__device__ __align__(16) __nv_bfloat16 g_attn[(size_t)PTOT * 96];   // row-major P x 96
__device__ __align__(16) __nv_bfloat16 g_wb  [110592];              // bf16 weights

// ---------------- helpers ----------------
__device__ __forceinline__ uint32_t smem_u32(const void* p) {
    uint32_t a;
    asm("{ .reg .u64 t; cvta.to.shared.u64 t, %1; cvt.u32.u64 %0, t; }"
        : "=r"(a) : "l"(p));
    return a;
}
__device__ __forceinline__ void cpa16(uint32_t dst, const void* src) {
    asm volatile("cp.async.cg.shared.global [%0], [%1], 16;"
                 :: "r"(dst), "l"(src));
}
__device__ __forceinline__ void cp_commit() {
    asm volatile("cp.async.commit_group;" ::: "memory");
}
__device__ __forceinline__ void cp_wait0() {
    asm volatile("cp.async.wait_group 0;" ::: "memory");
}
#define LDSM4(r0, r1, r2, r3, addr) \
    asm volatile("ldmatrix.sync.aligned.m8n8.x4.shared.b16 {%0,%1,%2,%3}, [%4];" \
                 : "=r"(r0), "=r"(r1), "=r"(r2), "=r"(r3) : "r"(addr))
#define LDSM2(r0, r1, addr) \
    asm volatile("ldmatrix.sync.aligned.m8n8.x2.shared.b16 {%0,%1}, [%2];" \
                 : "=r"(r0), "=r"(r1) : "r"(addr))
__device__ __forceinline__ void mma16(float* d, const uint32_t* a,
                                      const uint32_t* b) {
    asm volatile(
        "mma.sync.aligned.m16n8k16.row.col.f32.bf16.bf16.f32 "
        "{%0,%1,%2,%3}, {%4,%5,%6,%7}, {%8,%9}, {%0,%1,%2,%3};"
        : "+f"(d[0]), "+f"(d[1]), "+f"(d[2]), "+f"(d[3])
        : "r"(a[0]), "r"(a[1]), "r"(a[2]), "r"(a[3]), "r"(b[0]), "r"(b[1]));
}
__device__ __forceinline__ uint32_t packbf(float a, float b) {
    __nv_bfloat162 p = __floats2bfloat162_rn(a, b);
    return *(uint32_t*)&p;
}
__device__ __forceinline__ float bflo(uint32_t u) {
    return __uint_as_float(u << 16);
}
__device__ __forceinline__ float bfhi(uint32_t u) {
    return __uint_as_float(u & 0xffff0000u);
}
// tanh-form GELU via hardware MUFU.TANH.
__device__ __forceinline__ float gelu_f(float t) {
    float u = 0.7978845608f * t * fmaf(t * t, 0.044715f, 1.0f);
    float th;
    asm("tanh.approx.f32 %0, %1;" : "=f"(th) : "f"(u));
    return 0.5f * t * (1.f + th);
}

// B-fragment ldmatrix relative addresses, row stride SB bytes.
template <int SB>
__device__ __forceinline__ void bfrag_addrs(int wc, int lane,
                                            uint32_t& bA01, uint32_t& bA2) {
    int rw = lane & 7;
    int hi16 = (lane >> 3) & 1;                // byte +16 = k 8..15
    bA01 = (uint32_t)((wc * 24 + ((lane >> 4) << 3) + rw) * SB + (hi16 << 4));
    bA2  = (uint32_t)((wc * 24 + 16 + rw) * SB + (hi16 << 4));
}

// ---------------- weight conversion fp32 -> bf16 ----------------
__global__ __launch_bounds__(256)
void round_w(const float* __restrict__ qkv, const float* __restrict__ proj,
             const float* __restrict__ fc1, const float* __restrict__ fc2) {
    int i = blockIdx.x * 256 + threadIdx.x;
    float v;
    if (i < 27648)        v = qkv[i];
    else if (i < 36864)   v = proj[i - 27648];
    else if (i < 73728)   v = fc1[i - 36864];
    else                  v = fc2[i - 73728];
    g_wb[i] = __float2bfloat16_rn(v);
}

// ================= fused LN1 + qkv GEMM (256 thr, 2 CTAs/SM) =================
#define A_SZ 91904

__global__ __launch_bounds__(256, 2)
void k_ln1_qkv(const float* __restrict__ x, const __nv_bfloat16* __restrict__ wq,
               const float* __restrict__ lnw, const float* __restrict__ lnb,
               __nv_bfloat16* __restrict__ qkv) {
    extern __shared__ __align__(16) char dsm[];
    const uint32_t sb = smem_u32(dsm);
    float* sXp = (float*)dsm;                       // stride 132
    __nv_bfloat16* sDb = (__nv_bfloat16*)(dsm + 39936);
    uint32_t* sAw = (uint32_t*)(dsm + 65280);
    const uint32_t sAa = sb + 65280;

    const int tid = threadIdx.x;
    const int m0 = blockIdx.x * 128;
    const int bb = m0 >> 14, ss0 = m0 & 16383;

    // ---- stage x (planar) channel-major into sXp ----
#pragma unroll
    for (int it = 0; it < 12; it++) {               // 3072 x 16B
        int u = it * 256 + tid;
        int c = u >> 5, q = u & 31;
        cpa16(sb + (uint32_t)(c * 528 + q * 16),
              x + (((size_t)(bb * 96 + c)) << 14) + ss0 + q * 4);
    }
    cp_commit(); cp_wait0();
    __syncthreads();

    // ---- LN1: two threads per pixel ----
    {
        const int px = tid >> 1, half = tid & 1;
        float sum = 0.f, sq = 0.f;
#pragma unroll
        for (int i = 0; i < 48; i++) {
            float v = sXp[(half * 48 + i) * 132 + px];
            sum += v;
            sq = fmaf(v, v, sq);
        }
        sum += __shfl_xor_sync(0xffffffffu, sum, 1);
        sq  += __shfl_xor_sync(0xffffffffu, sq, 1);
        float mu = sum * (1.f / 96.f);
        float rs = rsqrtf(sq * (1.f / 96.f) - mu * mu + 1e-5f);
#pragma unroll
        for (int i = 0; i < 24; i++) {
            int c = half * 48 + 2 * i;
            float a0 = (sXp[c * 132 + px] - mu) * rs * __ldg(lnw + c)
                     + __ldg(lnb + c);
            float a1 = (sXp[(c + 1) * 132 + px] - mu) * rs * __ldg(lnw + c + 1)
                     + __ldg(lnb + c + 1);
            sAw[px * 52 + half * 24 + i] = packbf(a0, a1);
        }
    }
    __syncthreads();                                // sXp dead; sW region live

    // ---- GEMM over 3 N-blocks, double-buffered weights ----
    const int lane = tid & 31;
    const int wid = tid >> 5;
    const int wr = wid >> 2, wc = wid & 3;
    const int g = lane >> 2, tig = lane & 3;

    uint32_t aAddr[4];
#pragma unroll
    for (int i = 0; i < 4; i++)
        aAddr[i] = sAa + (uint32_t)((wr * 64 + i * 16 + (lane & 15)) * 208
                                    + (lane >> 4) * 16);
    uint32_t bA01, bA2;
    bfrag_addrs<208>(wc, lane, bA01, bA2);

    // preload nb0 weights into buf0
    for (int u = tid; u < 1152; u += 256) {
        int rr = u / 12, cc = u - rr * 12;
        cpa16(sb + (uint32_t)(rr * 208 + cc * 16), wq + rr * 96 + cc * 8);
    }
    cp_commit();

#pragma unroll 1
    for (int nb = 0; nb < 3; nb++) {
        cp_wait0();
        __syncthreads();
        if (nb < 2) {                                // prefetch nb+1
            const __nv_bfloat16* Wn = wq + (size_t)(nb + 1) * 9216;
            uint32_t dst = sb + (uint32_t)(((nb + 1) & 1) * 19968);
            for (int u = tid; u < 1152; u += 256) {
                int rr = u / 12, cc = u - rr * 12;
                cpa16(dst + (uint32_t)(rr * 208 + cc * 16), Wn + rr * 96 + cc * 8);
            }
            cp_commit();
        }
        const uint32_t wb = sb + (uint32_t)((nb & 1) * 19968);

        float acc[4][3][4];
#pragma unroll
        for (int i = 0; i < 4; i++)
#pragma unroll
            for (int j = 0; j < 3; j++)
#pragma unroll
                for (int q = 0; q < 4; q++) acc[i][j][q] = 0.f;

#pragma unroll
        for (int ks = 0; ks < 6; ks++) {
            uint32_t a[4][4], b01[4], b2x[2];
            LDSM4(b01[0], b01[1], b01[2], b01[3], wb + bA01 + (uint32_t)(ks * 32));
            LDSM2(b2x[0], b2x[1], wb + bA2 + (uint32_t)(ks * 32));
#pragma unroll
            for (int i = 0; i < 4; i++)
                LDSM4(a[i][0], a[i][1], a[i][2], a[i][3],
                      aAddr[i] + (uint32_t)(ks * 32));
#pragma unroll
            for (int i = 0; i < 4; i++) {
                mma16(acc[i][0], a[i], b01);
                mma16(acc[i][1], a[i], b01 + 2);
                mma16(acc[i][2], a[i], b2x);
            }
        }

        // stage D bf16 [col][132]
#pragma unroll
        for (int i = 0; i < 4; i++)
#pragma unroll
            for (int j = 0; j < 3; j++) {
                int row = wr * 64 + i * 16 + g;
                int col = wc * 24 + j * 8 + 2 * tig;
                sDb[col * 132 + row]           = __float2bfloat16_rn(acc[i][j][0]);
                sDb[(col + 1) * 132 + row]     = __float2bfloat16_rn(acc[i][j][1]);
                sDb[col * 132 + row + 8]       = __float2bfloat16_rn(acc[i][j][2]);
                sDb[(col + 1) * 132 + row + 8] = __float2bfloat16_rn(acc[i][j][3]);
            }
        __syncthreads();
        const uint32_t* sDu = (const uint32_t*)sDb;
#pragma unroll
        for (int u = tid; u < 6144; u += 256) {
            int col = u >> 6, q = u & 63;
            ((uint32_t*)(qkv + (((size_t)(nb * 96 + col)) << 17) + m0))[q]
                = sDu[col * 66 + q];
        }
        __syncthreads();
    }
}

// ================= dilated attention (packed ch-pairs, pad-only zero) =======
__global__ __launch_bounds__(256)
void attn_kernel(const __nv_bfloat16* __restrict__ qkvp,
                 __nv_bfloat16* __restrict__ attn) {
    extern __shared__ __align__(16) uint32_t sm32[];
    const int tid = threadIdx.x;
    const int b = blockIdx.x >> 6;
    const int h0 = (blockIdx.x & 63) << 1;
    const int hd = blockIdx.y;
    const int grp = hd >> 1;
    const int dil = grp + 1;
    const int cb = grp * 32 + (hd & 1) * 16;
    const int nr = 2 + 2 * dil;

    // zero ONLY the w-pad columns (u32 0..7 and 136..143 of each row),
    // all 8 rows x 8 cp x both tensors: 512 float4
    {
        uint4 z = make_uint4(0u, 0u, 0u, 0u);
#pragma unroll
        for (int it = 0; it < 2; it++) {
            int idx = it * 256 + tid;
            int t = idx >> 8, rem = idx & 255;
            int cp = rem >> 5, row = (rem >> 2) & 7, f = rem & 3;
            int off = t * 9216 + cp * 1152 + row * 144
                    + (f < 2 ? f * 4 : 128 + f * 4);
            *(uint4*)(sm32 + off) = z;
        }
    }

    // stage k/v rows; OOB rows zeroed inline (pads already zero, disjoint)
    const int baseh = h0 - dil;
    for (int u = tid; u < (nr << 7); u += 256) {
        int q8 = u & 15, seg = u >> 4;
        int cp = seg / nr, row = seg - cp * nr;
        int hr = baseh + row;
        int di = cp * 1152 + row * 144 + 8 + q8 * 8;
        if ((unsigned)hr < 128u) {
            size_t gofs = ((size_t)b << 14) + (hr << 7) + q8 * 8;
            uint4 k0 = *(const uint4*)(qkvp + (((size_t)(96 + cb + 2 * cp)) << 17) + gofs);
            uint4 k1 = *(const uint4*)(qkvp + (((size_t)(97 + cb + 2 * cp)) << 17) + gofs);
            uint4 v0 = *(const uint4*)(qkvp + (((size_t)(192 + cb + 2 * cp)) << 17) + gofs);
            uint4 v1 = *(const uint4*)(qkvp + (((size_t)(193 + cb + 2 * cp)) << 17) + gofs);
            uint4 o;
            o.x = __byte_perm(k0.x, k1.x, 0x5410); o.y = __byte_perm(k0.x, k1.x, 0x7632);
            o.z = __byte_perm(k0.y, k1.y, 0x5410); o.w = __byte_perm(k0.y, k1.y, 0x7632);
            *(uint4*)(sm32 + di) = o;
            o.x = __byte_perm(k0.z, k1.z, 0x5410); o.y = __byte_perm(k0.z, k1.z, 0x7632);
            o.z = __byte_perm(k0.w, k1.w, 0x5410); o.w = __byte_perm(k0.w, k1.w, 0x7632);
            *(uint4*)(sm32 + di + 4) = o;
            o.x = __byte_perm(v0.x, v1.x, 0x5410); o.y = __byte_perm(v0.x, v1.x, 0x7632);
            o.z = __byte_perm(v0.y, v1.y, 0x5410); o.w = __byte_perm(v0.y, v1.y, 0x7632);
            *(uint4*)(sm32 + di + 9216) = o;
            o.x = __byte_perm(v0.z, v1.z, 0x5410); o.y = __byte_perm(v0.z, v1.z, 0x7632);
            o.z = __byte_perm(v0.w, v1.w, 0x5410); o.w = __byte_perm(v0.w, v1.w, 0x7632);
            *(uint4*)(sm32 + di + 9220) = o;
        } else {
            uint4 z = make_uint4(0u, 0u, 0u, 0u);
            *(uint4*)(sm32 + di) = z;        *(uint4*)(sm32 + di + 4) = z;
            *(uint4*)(sm32 + di + 9216) = z; *(uint4*)(sm32 + di + 9220) = z;
        }
    }
    __syncthreads();

    const int r = tid >> 7, w = tid & 127;
    const size_t p = ((size_t)b << 14) + ((size_t)(h0 + r) << 7) + w;

    float ql[8], qh[8];
#pragma unroll
    for (int cp = 0; cp < 8; cp++) {
        ql[cp] = __bfloat162float(qkvp[(((size_t)(cb + 2 * cp)) << 17) + p]);
        qh[cp] = __bfloat162float(qkvp[(((size_t)(cb + 2 * cp + 1)) << 17) + p]);
    }

    float sc[9];
#pragma unroll
    for (int i = 0; i < 3; i++)
#pragma unroll
        for (int j = 0; j < 3; j++) {
            int base = (r + i * dil) * 144 + (8 + w + (j - 1) * dil);
            float d = 0.f;
#pragma unroll
            for (int cp = 0; cp < 8; cp++) {
                uint32_t u = sm32[cp * 1152 + base];
                d = fmaf(ql[cp], bflo(u), d);
                d = fmaf(qh[cp], bfhi(u), d);
            }
            sc[i * 3 + j] = d * 0.25f;
        }

    float mx = sc[0];
#pragma unroll
    for (int k = 1; k < 9; k++) mx = fmaxf(mx, sc[k]);
    float ssum = 0.f;
#pragma unroll
    for (int k = 0; k < 9; k++) { sc[k] = __expf(sc[k] - mx); ssum += sc[k]; }
    float inv = 1.f / ssum;

    float ol[8], oh[8];
#pragma unroll
    for (int cp = 0; cp < 8; cp++) { ol[cp] = 0.f; oh[cp] = 0.f; }
#pragma unroll
    for (int i = 0; i < 3; i++)
#pragma unroll
        for (int j = 0; j < 3; j++) {
            float wgt = sc[i * 3 + j] * inv;
            int base = 9216 + (r + i * dil) * 144 + (8 + w + (j - 1) * dil);
#pragma unroll
            for (int cp = 0; cp < 8; cp++) {
                uint32_t u = sm32[cp * 1152 + base];
                ol[cp] = fmaf(wgt, bflo(u), ol[cp]);
                oh[cp] = fmaf(wgt, bfhi(u), oh[cp]);
            }
        }

    __syncthreads();
#pragma unroll
    for (int cp = 0; cp < 8; cp++)
        sm32[tid * 17 + cp] = packbf(ol[cp], oh[cp]);
    __syncthreads();
    const size_t p0 = ((size_t)b << 14) + ((size_t)h0 << 7);
#pragma unroll
    for (int u = tid; u < 2048; u += 256) {
        int row = u >> 3, wq = u & 7;
        ((uint32_t*)(attn + (p0 + row) * 96 + cb))[wq] = sm32[row * 17 + wq];
    }
}

// ================= mega-fused proj+res+LN2+MLP, interleaved fc1->fc2 ========
// Half-resident A fragments for fc1 (ks 0-2 in regs, read once, reused 4x).
#define M_SZ 91392

__global__ __launch_bounds__(256, 2)
void k_pm(const __nv_bfloat16* __restrict__ attn,
          const __nv_bfloat16* __restrict__ wp, const float* __restrict__ pb,
          const float* __restrict__ x,
          const __nv_bfloat16* __restrict__ w1, const float* __restrict__ b1,
          const __nv_bfloat16* __restrict__ w2, const float* __restrict__ b2,
          const float* __restrict__ lnw, const float* __restrict__ lnb,
          float* __restrict__ out) {
    extern __shared__ __align__(16) char dsm[];
    const uint32_t sb = smem_u32(dsm);
    float* sX = (float*)dsm;
    uint32_t* sAw = (uint32_t*)(dsm + 24832);
    uint32_t* sHsU = (uint32_t*)(dsm + 38144);
    float* sEp = (float*)(dsm + 51456);              // epilogue staging
    const uint32_t sAa = sb + 24832;
    const uint32_t sHa = sb + 38144;
    const uint32_t W0 = sb + 51456;
    const uint32_t W1 = sb + 71424;

    const int tid = threadIdx.x;
    const int lane = tid & 31;
    const int wid = tid >> 5;                        // 0..7
    const int wr = wid >> 2, wc = wid & 3;           // 2x4 warps
    const int g = lane >> 2, tig = lane & 3;
    const int m0 = blockIdx.x * 64;
    const int bb = m0 >> 14, ss0 = m0 & 16383;

    uint32_t aAddr[2], hAddr[2];
#pragma unroll
    for (int i = 0; i < 2; i++) {
        int row = wr * 32 + i * 16 + (lane & 15);
        aAddr[i] = sAa + (uint32_t)(row * 208 + (lane >> 4) * 16);
        hAddr[i] = sHa + (uint32_t)(row * 208 + (lane >> 4) * 16);
    }
    uint32_t bA01, bA2;
    bfrag_addrs<208>(wc, lane, bA01, bA2);

    auto issue_chunk = [&](const __nv_bfloat16* W, int ld, int col0,
                           uint32_t buf) {
        for (int u = tid; u < 1152; u += 256) {
            int rr = u / 12, cc = u - rr * 12;
            cpa16(buf + (uint32_t)(rr * 208 + cc * 16),
                  W + (size_t)rr * ld + col0 + cc * 8);
        }
        cp_commit();
    };

    // ---- L0: attn A-tile + proj weights ----
    const __nv_bfloat16* Ab = attn + (size_t)m0 * 96;
#pragma unroll
    for (int it = 0; it < 3; it++) {
        int u = it * 256 + tid;
        int rr = u / 12, cc = u - rr * 12;
        cpa16(sAa + (uint32_t)(rr * 208 + cc * 16), Ab + (size_t)rr * 96 + cc * 8);
    }
    issue_chunk(wp, 96, 0, W0);

#define CHUNK_MMA(ACC, A0, A1, WBUF)                                          \
    do {                                                                      \
        _Pragma("unroll")                                                     \
        for (int ks = 0; ks < 6; ks++) {                                      \
            uint32_t a[2][4], b01[4], b2x[2];                                 \
            LDSM4(b01[0], b01[1], b01[2], b01[3],                             \
                  (WBUF) + bA01 + (uint32_t)(ks * 32));                       \
            LDSM2(b2x[0], b2x[1], (WBUF) + bA2 + (uint32_t)(ks * 32));        \
            LDSM4(a[0][0], a[0][1], a[0][2], a[0][3],                         \
                  (A0) + (uint32_t)(ks * 32));                                \
            LDSM4(a[1][0], a[1][1], a[1][2], a[1][3],                         \
                  (A1) + (uint32_t)(ks * 32));                                \
            _Pragma("unroll")                                                 \
            for (int i = 0; i < 2; i++) {                                     \
                mma16((ACC)[i][0], a[i], b01);                                \
                mma16((ACC)[i][1], a[i], b01 + 2);                            \
                mma16((ACC)[i][2], a[i], b2x);                                \
            }                                                                 \
        }                                                                     \
    } while (0)

    // ---- phase 0: proj (W0) ----
    float acc[2][3][4];
#pragma unroll
    for (int i = 0; i < 2; i++)
#pragma unroll
        for (int j = 0; j < 3; j++)
#pragma unroll
            for (int q = 0; q < 4; q++) acc[i][j][q] = 0.f;

    cp_wait0(); __syncthreads();
    issue_chunk(w1, 96, 0, W1);                      // fc1 nb0
    CHUNK_MMA(acc, aAddr[0], aAddr[1], W0);

    // ---- x1 = projD + bias into sX ----
#pragma unroll
    for (int i = 0; i < 2; i++)
#pragma unroll
        for (int j = 0; j < 3; j++) {
            int row = wr * 32 + i * 16 + g;
            int col = wc * 24 + j * 8 + 2 * tig;
            float bi0 = __ldg(pb + col), bi1 = __ldg(pb + col + 1);
            sX[row * 97 + col]           = acc[i][j][0] + bi0;
            sX[row * 97 + col + 1]       = acc[i][j][1] + bi1;
            sX[(row + 8) * 97 + col]     = acc[i][j][2] + bi0;
            sX[(row + 8) * 97 + col + 1] = acc[i][j][3] + bi1;
        }
    __syncthreads();

    // ---- += x (planar, coalesced) ----
#pragma unroll
    for (int u = tid; u < 6144; u += 256) {
        int col = u >> 6, px = u & 63;
        sX[px * 97 + col] += __ldg(x + (((size_t)(bb * 96 + col)) << 14) + ss0 + px);
    }
    __syncthreads();

    // ---- LN2: 4 threads per pixel -> sA region ----
    {
        const int px = tid >> 2, q = tid & 3;
        const float* xr = sX + px * 97 + q * 24;
        float sum = 0.f, sq = 0.f;
#pragma unroll
        for (int i = 0; i < 24; i++) {
            float v = xr[i];
            sum += v;
            sq = fmaf(v, v, sq);
        }
        sum += __shfl_xor_sync(0xffffffffu, sum, 1);
        sq  += __shfl_xor_sync(0xffffffffu, sq, 1);
        sum += __shfl_xor_sync(0xffffffffu, sum, 2);
        sq  += __shfl_xor_sync(0xffffffffu, sq, 2);
        float mu = sum * (1.f / 96.f);
        float rs = rsqrtf(sq * (1.f / 96.f) - mu * mu + 1e-5f);
#pragma unroll
        for (int i = 0; i < 12; i++) {
            int c = q * 24 + 2 * i;
            float a0 = (xr[2 * i] - mu) * rs * __ldg(lnw + c) + __ldg(lnb + c);
            float a1 = (xr[2 * i + 1] - mu) * rs * __ldg(lnw + c + 1)
                     + __ldg(lnb + c + 1);
            sAw[px * 52 + q * 12 + i] = packbf(a0, a1);
        }
    }
    // next phase's sync publishes LN2 output

    // ---- interleaved fc1 -> fc2, half-resident A frags for fc1 ----
    float acc2[2][3][4];
#pragma unroll
    for (int i = 0; i < 2; i++)
#pragma unroll
        for (int j = 0; j < 3; j++)
#pragma unroll
            for (int q = 0; q < 4; q++) acc2[i][j][q] = 0.f;

    uint32_t aF[3][2][4];                            // ks 0..2 resident

#pragma unroll 1
    for (int nb = 0; nb < 4; nb++) {
        // -- fc1 phase (W1) --
        cp_wait0(); __syncthreads();
        issue_chunk(w2, 384, nb * 96, W0);
        if (nb == 0) {                               // read resident A frags once
#pragma unroll
            for (int ks = 0; ks < 3; ks++) {
                LDSM4(aF[ks][0][0], aF[ks][0][1], aF[ks][0][2], aF[ks][0][3],
                      aAddr[0] + (uint32_t)(ks * 32));
                LDSM4(aF[ks][1][0], aF[ks][1][1], aF[ks][1][2], aF[ks][1][3],
                      aAddr[1] + (uint32_t)(ks * 32));
            }
        }
        float a1c[2][3][4];
#pragma unroll
        for (int i = 0; i < 2; i++)
#pragma unroll
            for (int j = 0; j < 3; j++)
#pragma unroll
                for (int q = 0; q < 4; q++) a1c[i][j][q] = 0.f;
        // ks 0..2 from registers
#pragma unroll
        for (int ks = 0; ks < 3; ks++) {
            uint32_t b01[4], b2x[2];
            LDSM4(b01[0], b01[1], b01[2], b01[3],
                  W1 + bA01 + (uint32_t)(ks * 32));
            LDSM2(b2x[0], b2x[1], W1 + bA2 + (uint32_t)(ks * 32));
#pragma unroll
            for (int i = 0; i < 2; i++) {
                mma16(a1c[i][0], aF[ks][i], b01);
                mma16(a1c[i][1], aF[ks][i], b01 + 2);
                mma16(a1c[i][2], aF[ks][i], b2x);
            }
        }
        // ks 3..5 from SMEM
#pragma unroll
        for (int ks = 3; ks < 6; ks++) {
            uint32_t a[2][4], b01[4], b2x[2];
            LDSM4(b01[0], b01[1], b01[2], b01[3],
                  W1 + bA01 + (uint32_t)(ks * 32));
            LDSM2(b2x[0], b2x[1], W1 + bA2 + (uint32_t)(ks * 32));
            LDSM4(a[0][0], a[0][1], a[0][2], a[0][3],
                  aAddr[0] + (uint32_t)(ks * 32));
            LDSM4(a[1][0], a[1][1], a[1][2], a[1][3],
                  aAddr[1] + (uint32_t)(ks * 32));
#pragma unroll
            for (int i = 0; i < 2; i++) {
                mma16(a1c[i][0], a[i], b01);
                mma16(a1c[i][1], a[i], b01 + 2);
                mma16(a1c[i][2], a[i], b2x);
            }
        }

        // GELU + bias -> sHs
#pragma unroll
        for (int i = 0; i < 2; i++)
#pragma unroll
            for (int j = 0; j < 3; j++) {
                int row = wr * 32 + i * 16 + g;
                int col = wc * 24 + j * 8 + 2 * tig;
                float bi0 = __ldg(b1 + nb * 96 + col);
                float bi1 = __ldg(b1 + nb * 96 + col + 1);
                float t0 = gelu_f(a1c[i][j][0] + bi0);
                float t1 = gelu_f(a1c[i][j][1] + bi1);
                float t2 = gelu_f(a1c[i][j][2] + bi0);
                float t3 = gelu_f(a1c[i][j][3] + bi1);
                sHsU[(row * 104 + col) >> 1]       = packbf(t0, t1);
                sHsU[((row + 8) * 104 + col) >> 1] = packbf(t2, t3);
            }

        // -- fc2 phase (W0) --
        cp_wait0(); __syncthreads();                 // publishes sHs + W0
        if (nb < 3)
            issue_chunk(w1 + (size_t)(nb + 1) * 9216, 96, 0, W1);
        CHUNK_MMA(acc2, hAddr[0], hAddr[1], W0);
    }
    __syncthreads();                                 // all W/sHs reads done

    // ---- epilogue: stage 96 cols fp32 into W region, single pass ----
#pragma unroll
    for (int i = 0; i < 2; i++)
#pragma unroll
        for (int j = 0; j < 3; j++) {
            int row = wr * 32 + i * 16 + g;
            int col = wc * 24 + j * 8 + 2 * tig;
            sEp[row * 97 + col]           = acc2[i][j][0];
            sEp[row * 97 + col + 1]       = acc2[i][j][1];
            sEp[(row + 8) * 97 + col]     = acc2[i][j][2];
            sEp[(row + 8) * 97 + col + 1] = acc2[i][j][3];
        }
    __syncthreads();
#pragma unroll
    for (int u = tid; u < 6144; u += 256) {
        int col = u >> 6, px = u & 63;
        float val = sEp[px * 97 + col] + __ldg(b2 + col) + sX[px * 97 + col];
        out[(((size_t)(bb * 96 + col)) << 14) + ss0 + px] = val;
    }
#undef CHUNK_MMA
}

// ---------------- launch ----------------
extern "C" void kernel_launch(void* const* d_in, const int* in_sizes, int n_in,
                              void* d_out, int out_size) {
    (void)in_sizes; (void)n_in; (void)out_size;
    const float* x      = (const float*)d_in[0];
    const float* qkv_w  = (const float*)d_in[1];
    const float* proj_w = (const float*)d_in[2];
    const float* proj_b = (const float*)d_in[3];
    const float* ln1w   = (const float*)d_in[4];
    const float* ln1b   = (const float*)d_in[5];
    const float* ln2w   = (const float*)d_in[6];
    const float* ln2b   = (const float*)d_in[7];
    const float* fc1w   = (const float*)d_in[8];
    const float* fc1b   = (const float*)d_in[9];
    const float* fc2w   = (const float*)d_in[10];
    const float* fc2b   = (const float*)d_in[11];
    float* out = (float*)d_out;

    cudaFuncSetAttribute(k_ln1_qkv,
                         cudaFuncAttributeMaxDynamicSharedMemorySize, A_SZ);
    cudaFuncSetAttribute(attn_kernel,
                         cudaFuncAttributeMaxDynamicSharedMemorySize, 73728);
    cudaFuncSetAttribute(k_pm,
                         cudaFuncAttributeMaxDynamicSharedMemorySize, M_SZ);

    __nv_bfloat16 *pqkv, *pattn, *pwb;
    cudaGetSymbolAddress((void**)&pqkv, g_qkv);
    cudaGetSymbolAddress((void**)&pattn, g_attn);
    cudaGetSymbolAddress((void**)&pwb, g_wb);

    round_w<<<432, 256>>>(qkv_w, proj_w, fc1w, fc2w);
    k_ln1_qkv<<<PTOT / 128, 256, A_SZ>>>(x, pwb, ln1w, ln1b, pqkv);
    attn_kernel<<<dim3(512, 6), 256, 73728>>>(pqkv, pattn);
    k_pm<<<PTOT / 64, 256, M_SZ>>>(pattn, pwb + 27648, proj_b, x,
                                   pwb + 36864, fc1b, pwb + 73728, fc2b,
                                   ln2w, ln2b, out);
}